// round 1
// baseline (speedup 1.0000x reference)
#include <cuda_runtime.h>
#include <math.h>
#include <stdint.h>

#define T_SEQ 2048
#define C_DIM 256
#define H_NUM 16
#define NOPE 32
#define ROPE 64
#define HD 96
#define VD 32
#define KEEP 512
#define WIN 128
#define BMAX 2
#define EPSF 1e-6f

// ---------------- device scratch (static: no allocations allowed) ----------------
__device__ float g_costab[T_SEQ * 32];
__device__ float g_sintab[T_SEQ * 32];
__device__ float g_cq[BMAX * T_SEQ * 96];
__device__ float g_ckv[BMAX * T_SEQ * 32];
__device__ float g_kr[BMAX * T_SEQ * 64];
__device__ float g_imp[BMAX * T_SEQ];
__device__ int   g_idx[BMAX * KEEP];
__device__ float g_xmean[BMAX * C_DIM];
__device__ float g_gate[BMAX * 3];
__device__ float g_q [BMAX * H_NUM * T_SEQ * HD];
__device__ float g_k1[BMAX * H_NUM * T_SEQ * HD];
__device__ float g_v1[BMAX * H_NUM * T_SEQ * VD];
__device__ float g_ks[BMAX * H_NUM * KEEP * HD];
__device__ float g_vs[BMAX * H_NUM * KEEP * VD];
__device__ float g_kw[BMAX * H_NUM * T_SEQ * HD];
__device__ float g_vw[BMAX * H_NUM * T_SEQ * VD];
__device__ float g_O [BMAX * T_SEQ * H_NUM * VD];

// ---------------- rope table ----------------
__global__ void rope_tab_kernel() {
    int id = blockIdx.x * 256 + threadIdx.x;
    if (id >= T_SEQ * 32) return;
    int t = id >> 5, i = id & 31;
    float f = (float)pow(10000.0, -(double)i / 32.0);
    float ang = (float)t * f;
    g_costab[id] = cosf(ang);
    g_sintab[id] = sinf(ang);
}

// ---------------- per-row features: cq (rms), ckv (rms), kr (roped), imp ----------------
__global__ void row_feat_kernel(const float* __restrict__ x,
                                const float* __restrict__ Wcq, const float* __restrict__ qnw,
                                const float* __restrict__ Wckv, const float* __restrict__ kvnw,
                                const float* __restrict__ Wkr, const float* __restrict__ Wimp) {
    int row = blockIdx.x;
    int tid = threadIdx.x; // 256
    int t = row % T_SEQ;
    __shared__ float xs[C_DIM];
    __shared__ float ybuf[192]; // [0,96) cq raw, [96,128) ckv raw, [128,192) kr raw
    __shared__ float red[256];
    xs[tid] = x[(size_t)row * C_DIM + tid];
    __syncthreads();
    if (tid < 96) {
        float a = 0.f;
        for (int c = 0; c < C_DIM; ++c) a += xs[c] * Wcq[c * 96 + tid];
        ybuf[tid] = a;
    } else if (tid < 128) {
        int j = tid - 96; float a = 0.f;
        for (int c = 0; c < C_DIM; ++c) a += xs[c] * Wckv[c * 32 + j];
        ybuf[96 + j] = a;
    } else if (tid < 192) {
        int j = tid - 128; float a = 0.f;
        for (int c = 0; c < C_DIM; ++c) a += xs[c] * Wkr[c * 64 + j];
        ybuf[128 + j] = a * (1.f / (float)H_NUM);
    } else if (tid == 192) {
        float a = 0.f;
        for (int c = 0; c < C_DIM; ++c) a += xs[c] * Wimp[c];
        g_imp[row] = a;
    }
    __syncthreads();
    red[tid] = (tid < 96) ? ybuf[tid] * ybuf[tid] : 0.f;
    __syncthreads();
    for (int s = 128; s > 0; s >>= 1) { if (tid < s) red[tid] += red[tid + s]; __syncthreads(); }
    float rms_cq = rsqrtf(red[0] / 96.f + EPSF);
    __syncthreads();
    red[tid] = (tid < 32) ? ybuf[96 + tid] * ybuf[96 + tid] : 0.f;
    __syncthreads();
    for (int s = 128; s > 0; s >>= 1) { if (tid < s) red[tid] += red[tid + s]; __syncthreads(); }
    float rms_kv = rsqrtf(red[0] / 32.f + EPSF);
    if (tid < 96) g_cq[(size_t)row * 96 + tid] = ybuf[tid] * rms_cq * qnw[tid];
    if (tid < 32) g_ckv[(size_t)row * 32 + tid] = ybuf[96 + tid] * rms_kv * kvnw[tid];
    if (tid < 32) {
        float xr = ybuf[128 + tid], xi = ybuf[160 + tid];
        float co = g_costab[t * 32 + tid], si = g_sintab[t * 32 + tid];
        g_kr[(size_t)row * 64 + tid]      = xr * co - xi * si;
        g_kr[(size_t)row * 64 + 32 + tid] = xr * si + xi * co;
    }
}

// ---------------- column mean over T (for gate) ----------------
__global__ void colmean_kernel(const float* __restrict__ x) {
    int b = blockIdx.x, c = threadIdx.x;
    float s = 0.f;
    for (int t = 0; t < T_SEQ; ++t) s += x[((size_t)b * T_SEQ + t) * C_DIM + c];
    g_xmean[b * C_DIM + c] = s / (float)T_SEQ;
}

__global__ void gate_kernel(const float* __restrict__ Wgate, int B) {
    int tid = threadIdx.x;
    __shared__ float lg[BMAX * 3];
    if (tid < B * 3) {
        int b = tid / 3, j = tid % 3;
        float s = 0.f;
        for (int c = 0; c < C_DIM; ++c) s += g_xmean[b * C_DIM + c] * Wgate[c * 3 + j];
        lg[tid] = s;
    }
    __syncthreads();
    if (tid < B) {
        float a = lg[tid * 3], b2 = lg[tid * 3 + 1], c2 = lg[tid * 3 + 2];
        float mx = fmaxf(a, fmaxf(b2, c2));
        float ea = expf(a - mx), eb = expf(b2 - mx), ec = expf(c2 - mx);
        float s = ea + eb + ec;
        g_gate[tid * 3 + 0] = ea / s;
        g_gate[tid * 3 + 1] = eb / s;
        g_gate[tid * 3 + 2] = ec / s;
    }
}

// ---------------- q / k1 / v1 projection (8-row tiles) ----------------
__global__ void qkv_kernel(const float* __restrict__ Wqn, const float* __restrict__ Wqr,
                           const float* __restrict__ Wkn, const float* __restrict__ Wv) {
    const int RT = 8;
    int row0 = blockIdx.x * RT;
    int tid = threadIdx.x; // 256
    __shared__ float cqs[RT][96];
    __shared__ float ckvs[RT][32];
    __shared__ float krs[RT][64];
    for (int i = tid; i < RT * 96; i += 256) cqs[i / 96][i % 96] = g_cq[(size_t)(row0 + i / 96) * 96 + (i % 96)];
    for (int i = tid; i < RT * 32; i += 256) ckvs[i / 32][i % 32] = g_ckv[(size_t)(row0 + i / 32) * 32 + (i % 32)];
    for (int i = tid; i < RT * 64; i += 256) krs[i / 64][i % 64] = g_kr[(size_t)(row0 + i / 64) * 64 + (i % 64)];
    __syncthreads();
    // q nope
    for (int o = tid; o < 512; o += 256) {
        int h = o >> 5, d = o & 31;
        float acc[RT]; 
        #pragma unroll
        for (int r = 0; r < RT; ++r) acc[r] = 0.f;
        for (int c = 0; c < 96; ++c) {
            float w = Wqn[c * 512 + o];
            #pragma unroll
            for (int r = 0; r < RT; ++r) acc[r] += cqs[r][c] * w;
        }
        #pragma unroll
        for (int r = 0; r < RT; ++r) {
            int row = row0 + r; int b = row / T_SEQ, t = row % T_SEQ;
            g_q[((size_t)(b * H_NUM + h) * T_SEQ + t) * HD + d] = acc[r];
        }
    }
    // q rope pairs
    for (int p = tid; p < 512; p += 256) {
        int h = p >> 5, i = p & 31;
        float ar[RT], ai[RT];
        #pragma unroll
        for (int r = 0; r < RT; ++r) { ar[r] = 0.f; ai[r] = 0.f; }
        for (int c = 0; c < 96; ++c) {
            float wr = Wqr[c * 1024 + h * 64 + i];
            float wi = Wqr[c * 1024 + h * 64 + 32 + i];
            #pragma unroll
            for (int r = 0; r < RT; ++r) { ar[r] += cqs[r][c] * wr; ai[r] += cqs[r][c] * wi; }
        }
        #pragma unroll
        for (int r = 0; r < RT; ++r) {
            int row = row0 + r; int b = row / T_SEQ, t = row % T_SEQ;
            float co = g_costab[t * 32 + i], si = g_sintab[t * 32 + i];
            size_t base = ((size_t)(b * H_NUM + h) * T_SEQ + t) * HD;
            g_q[base + 32 + i] = ar[r] * co - ai[r] * si;
            g_q[base + 64 + i] = ar[r] * si + ai[r] * co;
        }
    }
    // k nope
    for (int o = tid; o < 512; o += 256) {
        int h = o >> 5, d = o & 31;
        float acc[RT];
        #pragma unroll
        for (int r = 0; r < RT; ++r) acc[r] = 0.f;
        for (int c = 0; c < 32; ++c) {
            float w = Wkn[c * 512 + o];
            #pragma unroll
            for (int r = 0; r < RT; ++r) acc[r] += ckvs[r][c] * w;
        }
        #pragma unroll
        for (int r = 0; r < RT; ++r) {
            int row = row0 + r; int b = row / T_SEQ, t = row % T_SEQ;
            g_k1[((size_t)(b * H_NUM + h) * T_SEQ + t) * HD + d] = acc[r];
        }
    }
    // v1
    for (int o = tid; o < 512; o += 256) {
        int h = o >> 5, d = o & 31;
        float acc[RT];
        #pragma unroll
        for (int r = 0; r < RT; ++r) acc[r] = 0.f;
        for (int c = 0; c < 32; ++c) {
            float w = Wv[c * 512 + o];
            #pragma unroll
            for (int r = 0; r < RT; ++r) acc[r] += ckvs[r][c] * w;
        }
        #pragma unroll
        for (int r = 0; r < RT; ++r) {
            int row = row0 + r; int b = row / T_SEQ, t = row % T_SEQ;
            g_v1[((size_t)(b * H_NUM + h) * T_SEQ + t) * VD + d] = acc[r];
        }
    }
    // k1 rope part: broadcast kr to all heads
    for (int i = tid; i < RT * H_NUM * 64; i += 256) {
        int r = i / (H_NUM * 64); int rem = i % (H_NUM * 64); int h = rem / 64; int d = rem % 64;
        int row = row0 + r; int b = row / T_SEQ, t = row % T_SEQ;
        g_k1[((size_t)(b * H_NUM + h) * T_SEQ + t) * HD + 32 + d] = krs[r][d];
    }
}

// ---------------- top-k (1 block per batch): bitonic sort 2048 desc, then sort 512 idx asc ----------------
__global__ void topk_kernel() {
    __shared__ float v[T_SEQ];
    __shared__ int   ix[T_SEQ];
    int b = blockIdx.x, tid = threadIdx.x; // 1024
    for (int i = tid; i < T_SEQ; i += 1024) { v[i] = g_imp[b * T_SEQ + i]; ix[i] = i; }
    __syncthreads();
    for (int k = 2; k <= T_SEQ; k <<= 1)
        for (int j = k >> 1; j > 0; j >>= 1) {
            for (int i = tid; i < T_SEQ; i += 1024) {
                int p = i ^ j;
                if (p > i) {
                    bool up = ((i & k) == 0);
                    bool sw = up ? (v[i] < v[p]) : (v[i] > v[p]); // descending overall
                    if (sw) {
                        float tv = v[i]; v[i] = v[p]; v[p] = tv;
                        int ti = ix[i]; ix[i] = ix[p]; ix[p] = ti;
                    }
                }
            }
            __syncthreads();
        }
    // sort first KEEP indices ascending
    for (int k = 2; k <= KEEP; k <<= 1)
        for (int j = k >> 1; j > 0; j >>= 1) {
            if (tid < KEEP) {
                int i = tid, p = i ^ j;
                if (p > i) {
                    bool up = ((i & k) == 0);
                    bool sw = up ? (ix[i] > ix[p]) : (ix[i] < ix[p]); // ascending overall
                    if (sw) { int ti = ix[i]; ix[i] = ix[p]; ix[p] = ti; }
                }
            }
            __syncthreads();
        }
    for (int i = tid; i < KEEP; i += 1024) g_idx[b * KEEP + i] = ix[i];
}

// ---------------- sel / window K,V projection (16-row tiles, roped) ----------------
template <bool SEL>
__global__ void kvproj_kernel(const float* __restrict__ x,
                              const float* __restrict__ Wk, const float* __restrict__ Wv) {
    const int RT = 16;
    const int Tk = SEL ? KEEP : T_SEQ;
    int row0 = blockIdx.x * RT;
    int tid = threadIdx.x; // 256
    __shared__ float xs[RT][C_DIM];
    for (int r = 0; r < RT; ++r) {
        int row = row0 + r; int b = row / Tk; int s = row % Tk;
        int src = SEL ? (b * T_SEQ + g_idx[b * KEEP + s]) : (b * T_SEQ + s);
        xs[r][tid] = x[(size_t)src * C_DIM + tid];
    }
    __syncthreads();
    float* Ko = SEL ? g_ks : g_kw;
    float* Vo = SEL ? g_vs : g_vw;
    // K nope
    for (int o = tid; o < 512; o += 256) {
        int h = o >> 5, d = o & 31; int col = h * HD + d;
        float acc[RT];
        #pragma unroll
        for (int r = 0; r < RT; ++r) acc[r] = 0.f;
        for (int c = 0; c < C_DIM; ++c) {
            float w = Wk[c * (H_NUM * HD) + col];
            #pragma unroll
            for (int r = 0; r < RT; ++r) acc[r] += xs[r][c] * w;
        }
        #pragma unroll
        for (int r = 0; r < RT; ++r) {
            int row = row0 + r; int b = row / Tk; int s = row % Tk;
            Ko[((size_t)(b * H_NUM + h) * Tk + s) * HD + d] = acc[r];
        }
    }
    // K rope pairs
    for (int p = tid; p < 512; p += 256) {
        int h = p >> 5, i = p & 31;
        float ar[RT], ai[RT];
        #pragma unroll
        for (int r = 0; r < RT; ++r) { ar[r] = 0.f; ai[r] = 0.f; }
        for (int c = 0; c < C_DIM; ++c) {
            float wr = Wk[c * (H_NUM * HD) + h * HD + 32 + i];
            float wi = Wk[c * (H_NUM * HD) + h * HD + 64 + i];
            #pragma unroll
            for (int r = 0; r < RT; ++r) { ar[r] += xs[r][c] * wr; ai[r] += xs[r][c] * wi; }
        }
        #pragma unroll
        for (int r = 0; r < RT; ++r) {
            int row = row0 + r; int b = row / Tk; int s = row % Tk;
            float co = g_costab[s * 32 + i], si = g_sintab[s * 32 + i];
            size_t base = ((size_t)(b * H_NUM + h) * Tk + s) * HD;
            Ko[base + 32 + i] = ar[r] * co - ai[r] * si;
            Ko[base + 64 + i] = ar[r] * si + ai[r] * co;
        }
    }
    // V
    for (int o = tid; o < 512; o += 256) {
        int h = o >> 5, d = o & 31;
        float acc[RT];
        #pragma unroll
        for (int r = 0; r < RT; ++r) acc[r] = 0.f;
        for (int c = 0; c < C_DIM; ++c) {
            float w = Wv[c * 512 + o];
            #pragma unroll
            for (int r = 0; r < RT; ++r) acc[r] += xs[r][c] * w;
        }
        #pragma unroll
        for (int r = 0; r < RT; ++r) {
            int row = row0 + r; int b = row / Tk; int s = row % Tk;
            Vo[((size_t)(b * H_NUM + h) * Tk + s) * VD + d] = acc[r];
        }
    }
}

// ---------------- attention (thread = query, 32-key shared tiles, online softmax) ----------------
// MODE 0: full causal (k1,v1)  MODE 1: sel, no mask (ks,vs)  MODE 2: window causal (kw,vw)
template <int MODE, bool ACCUM>
__global__ void __launch_bounds__(128) attn_kernel(int branch) {
    const int QT = 128, KT = 32;
    const int Tk = (MODE == 1) ? KEEP : T_SEQ;
    int b = blockIdx.z, h = blockIdx.y;
    int qt0 = blockIdx.x * QT;
    int tid = threadIdx.x;
    int t = qt0 + tid;
    __shared__ float4 Ksh4[KT * HD / 4];
    __shared__ float4 Vsh4[KT * VD / 4];
    const float* Ksh = (const float*)Ksh4;
    const float* Vsh = (const float*)Vsh4;
    const float* K = (MODE == 1) ? g_ks : (MODE == 2) ? g_kw : g_k1;
    const float* V = (MODE == 1) ? g_vs : (MODE == 2) ? g_vw : g_v1;

    float4 q4[24];
    const float4* qp = (const float4*)(g_q + ((size_t)(b * H_NUM + h) * T_SEQ + t) * HD);
    #pragma unroll
    for (int i = 0; i < 24; ++i) q4[i] = qp[i];

    float4 acc[8];
    #pragma unroll
    for (int i = 0; i < 8; ++i) acc[i] = make_float4(0.f, 0.f, 0.f, 0.f);
    float m = -1e30f, l = 0.f;

    int kend = (MODE == 1) ? Tk : min(Tk, qt0 + QT);
    int k0 = (MODE == 2) ? max(0, qt0 - QT) : 0;
    int myLo = (MODE == 2) ? (t - (WIN - 1)) : 0;
    int myHi = (MODE == 1) ? (Tk - 1) : t;
    const float scale = 0.10206207262f; // 1/sqrt(96)
    const float* Kbase = K + (size_t)(b * H_NUM + h) * Tk * HD;
    const float* Vbase = V + (size_t)(b * H_NUM + h) * Tk * VD;

    for (int kt = k0; kt < kend; kt += KT) {
        __syncthreads();
        const float4* Ksrc = (const float4*)(Kbase + (size_t)kt * HD);
        #pragma unroll
        for (int i = 0; i < 6; ++i) ((float4*)Ksh4)[tid + i * 128] = Ksrc[tid + i * 128];
        const float4* Vsrc = (const float4*)(Vbase + (size_t)kt * VD);
        #pragma unroll
        for (int i = 0; i < 2; ++i) ((float4*)Vsh4)[tid + i * 128] = Vsrc[tid + i * 128];
        __syncthreads();
        int jlo = max(0, myLo - kt);
        int jhi = min(KT, myHi - kt + 1);
        for (int j = jlo; j < jhi; ++j) {
            const float4* kr = (const float4*)(Ksh + j * HD);
            float s0 = 0.f, s1 = 0.f, s2 = 0.f, s3 = 0.f;
            #pragma unroll
            for (int d = 0; d < 24; ++d) {
                float4 kv = kr[d];
                s0 += q4[d].x * kv.x; s1 += q4[d].y * kv.y;
                s2 += q4[d].z * kv.z; s3 += q4[d].w * kv.w;
            }
            float s = ((s0 + s1) + (s2 + s3)) * scale;
            if (s > m) {
                float corr = __expf(m - s);
                l *= corr;
                #pragma unroll
                for (int d = 0; d < 8; ++d) {
                    acc[d].x *= corr; acc[d].y *= corr; acc[d].z *= corr; acc[d].w *= corr;
                }
                m = s;
            }
            float p = __expf(s - m);
            l += p;
            const float4* vv = (const float4*)(Vsh + j * VD);
            #pragma unroll
            for (int d = 0; d < 8; ++d) {
                float4 xv = vv[d];
                acc[d].x += p * xv.x; acc[d].y += p * xv.y;
                acc[d].z += p * xv.z; acc[d].w += p * xv.w;
            }
        }
    }
    float g = g_gate[b * 3 + branch];
    float inv = g / l;
    float4* op = (float4*)(g_O + ((size_t)(b * T_SEQ + t) * H_NUM + h) * VD);
    #pragma unroll
    for (int d = 0; d < 8; ++d) {
        float4 o4 = make_float4(acc[d].x * inv, acc[d].y * inv, acc[d].z * inv, acc[d].w * inv);
        if (ACCUM) {
            float4 cur = op[d];
            o4.x += cur.x; o4.y += cur.y; o4.z += cur.z; o4.w += cur.w;
        }
        op[d] = o4;
    }
}

// ---------------- final projection: (B,T,512) @ (512,256) ----------------
__global__ void proj_kernel(const float* __restrict__ Wproj, float* __restrict__ out) {
    const int RT = 16;
    int row0 = blockIdx.x * RT;
    int tid = threadIdx.x; // 256
    __shared__ float Os[RT][512];
    for (int i = tid; i < RT * 512; i += 256) Os[i >> 9][i & 511] = g_O[((size_t)row0 << 9) + i];
    __syncthreads();
    float acc[RT];
    #pragma unroll
    for (int r = 0; r < RT; ++r) acc[r] = 0.f;
    for (int c = 0; c < 512; ++c) {
        float w = Wproj[c * 256 + tid];
        #pragma unroll
        for (int r = 0; r < RT; ++r) acc[r] += Os[r][c] * w;
    }
    #pragma unroll
    for (int r = 0; r < RT; ++r) out[(size_t)(row0 + r) * 256 + tid] = acc[r];
}

// ---------------- launch ----------------
extern "C" void kernel_launch(void* const* d_in, const int* in_sizes, int n_in,
                              void* d_out, int out_size) {
    const float* x     = (const float*)d_in[0];
    const float* Wcq   = (const float*)d_in[1];
    const float* qnw   = (const float*)d_in[2];
    const float* Wqn   = (const float*)d_in[3];
    const float* Wqr   = (const float*)d_in[4];
    const float* Wckv  = (const float*)d_in[5];
    const float* kvnw  = (const float*)d_in[6];
    const float* Wkn   = (const float*)d_in[7];
    const float* Wv    = (const float*)d_in[8];
    const float* Wkr   = (const float*)d_in[9];
    const float* Wimp  = (const float*)d_in[10];
    const float* Wselk = (const float*)d_in[11];
    const float* Wselv = (const float*)d_in[12];
    const float* Wwink = (const float*)d_in[13];
    const float* Wwinv = (const float*)d_in[14];
    const float* Wgate = (const float*)d_in[15];
    const float* Wproj = (const float*)d_in[16];
    float* out = (float*)d_out;
    int B = in_sizes[0] / (T_SEQ * C_DIM);
    if (B < 1) B = 1; if (B > BMAX) B = BMAX;

    rope_tab_kernel<<<(T_SEQ * 32 + 255) / 256, 256>>>();
    row_feat_kernel<<<B * T_SEQ, 256>>>(x, Wcq, qnw, Wckv, kvnw, Wkr, Wimp);
    colmean_kernel<<<B, 256>>>(x);
    gate_kernel<<<1, 32>>>(Wgate, B);
    qkv_kernel<<<B * T_SEQ / 8, 256>>>(Wqn, Wqr, Wkn, Wv);
    topk_kernel<<<B, 1024>>>();
    kvproj_kernel<true><<<B * KEEP / 16, 256>>>(x, Wselk, Wselv);
    kvproj_kernel<false><<<B * T_SEQ / 16, 256>>>(x, Wwink, Wwinv);

    dim3 agrid(T_SEQ / 128, H_NUM, B);
    attn_kernel<0, false><<<agrid, 128>>>(0);
    attn_kernel<1, true ><<<agrid, 128>>>(1);
    attn_kernel<2, true ><<<agrid, 128>>>(2);

    proj_kernel<<<B * T_SEQ / 16, 256>>>(Wproj, out);
}

// round 2
// speedup vs baseline: 1.1128x; 1.1128x over previous
#include <cuda_runtime.h>
#include <math.h>
#include <stdint.h>
#include <mma.h>
using namespace nvcuda;

#define T_SEQ 2048
#define C_DIM 256
#define H_NUM 16
#define NOPE 32
#define ROPE 64
#define HD 96
#define VD 32
#define KEEP 512
#define WIN 128
#define BMAX 2
#define EPSF 1e-6f

// ---------------- device scratch (static: no allocations allowed) ----------------
__device__ float g_costab[T_SEQ * 32];
__device__ float g_sintab[T_SEQ * 32];
__device__ float g_cq[BMAX * T_SEQ * 96];
__device__ float g_ckv[BMAX * T_SEQ * 32];
__device__ float g_kr[BMAX * T_SEQ * 64];
__device__ float g_imp[BMAX * T_SEQ];
__device__ int   g_idx[BMAX * KEEP];
__device__ float g_gate[BMAX * 3];
__device__ float g_q [BMAX * H_NUM * T_SEQ * HD];
__device__ float g_k1[BMAX * H_NUM * T_SEQ * HD];
__device__ float g_v1[BMAX * H_NUM * T_SEQ * VD];
__device__ float g_ks[BMAX * H_NUM * KEEP * HD];
__device__ float g_vs[BMAX * H_NUM * KEEP * VD];
__device__ float g_kw[BMAX * H_NUM * T_SEQ * HD];
__device__ float g_vw[BMAX * H_NUM * T_SEQ * VD];
__device__ float g_O [BMAX * T_SEQ * H_NUM * VD];

// ---------------- rope table ----------------
__global__ void rope_tab_kernel() {
    int id = blockIdx.x * 256 + threadIdx.x;
    if (id >= T_SEQ * 32) return;
    int t = id >> 5, i = id & 31;
    float f = (float)pow(10000.0, -(double)i / 32.0);
    float ang = (float)t * f;
    g_costab[id] = cosf(ang);
    g_sintab[id] = sinf(ang);
}

// ---------------- per-row features: cq (rms), ckv (rms), kr (roped), imp ----------------
__global__ void row_feat_kernel(const float* __restrict__ x,
                                const float* __restrict__ Wcq, const float* __restrict__ qnw,
                                const float* __restrict__ Wckv, const float* __restrict__ kvnw,
                                const float* __restrict__ Wkr, const float* __restrict__ Wimp) {
    int row = blockIdx.x;
    int tid = threadIdx.x; // 256
    int t = row % T_SEQ;
    __shared__ float xs[C_DIM];
    __shared__ float ybuf[192];
    __shared__ float red[256];
    xs[tid] = x[(size_t)row * C_DIM + tid];
    __syncthreads();
    if (tid < 96) {
        float a = 0.f;
        for (int c = 0; c < C_DIM; ++c) a += xs[c] * Wcq[c * 96 + tid];
        ybuf[tid] = a;
    } else if (tid < 128) {
        int j = tid - 96; float a = 0.f;
        for (int c = 0; c < C_DIM; ++c) a += xs[c] * Wckv[c * 32 + j];
        ybuf[96 + j] = a;
    } else if (tid < 192) {
        int j = tid - 128; float a = 0.f;
        for (int c = 0; c < C_DIM; ++c) a += xs[c] * Wkr[c * 64 + j];
        ybuf[128 + j] = a * (1.f / (float)H_NUM);
    } else if (tid == 192) {
        float a = 0.f;
        for (int c = 0; c < C_DIM; ++c) a += xs[c] * Wimp[c];
        g_imp[row] = a;
    }
    __syncthreads();
    red[tid] = (tid < 96) ? ybuf[tid] * ybuf[tid] : 0.f;
    __syncthreads();
    for (int s = 128; s > 0; s >>= 1) { if (tid < s) red[tid] += red[tid + s]; __syncthreads(); }
    float rms_cq = rsqrtf(red[0] / 96.f + EPSF);
    __syncthreads();
    red[tid] = (tid < 32) ? ybuf[96 + tid] * ybuf[96 + tid] : 0.f;
    __syncthreads();
    for (int s = 128; s > 0; s >>= 1) { if (tid < s) red[tid] += red[tid + s]; __syncthreads(); }
    float rms_kv = rsqrtf(red[0] / 32.f + EPSF);
    if (tid < 96) g_cq[(size_t)row * 96 + tid] = ybuf[tid] * rms_cq * qnw[tid];
    if (tid < 32) g_ckv[(size_t)row * 32 + tid] = ybuf[96 + tid] * rms_kv * kvnw[tid];
    if (tid < 32) {
        float xr = ybuf[128 + tid], xi = ybuf[160 + tid];
        float co = g_costab[t * 32 + tid], si = g_sintab[t * 32 + tid];
        g_kr[(size_t)row * 64 + tid]      = xr * co - xi * si;
        g_kr[(size_t)row * 64 + 32 + tid] = xr * si + xi * co;
    }
}

// ---------------- gate: colmean + softmax fused (one block) ----------------
__global__ void gate_kernel(const float* __restrict__ x, const float* __restrict__ Wgate, int B) {
    // 192 threads = 6 warps; warp w handles (b = w/3, j = w%3)
    __shared__ float lg[6];
    int tid = threadIdx.x;
    int w = tid >> 5, lane = tid & 31;
    if (w < B * 3) {
        int b = w / 3, j = w % 3;
        float s = 0.f;
        for (int c = lane; c < C_DIM; c += 32) {
            float colsum = 0.f;
            const float* xp = x + (size_t)b * T_SEQ * C_DIM + c;
            for (int t = 0; t < T_SEQ; ++t) colsum += xp[(size_t)t * C_DIM];
            s += (colsum / (float)T_SEQ) * Wgate[c * 3 + j];
        }
        #pragma unroll
        for (int o = 16; o > 0; o >>= 1) s += __shfl_xor_sync(0xffffffffu, s, o);
        if (lane == 0) lg[w] = s;
    }
    __syncthreads();
    if (tid < B) {
        float a = lg[tid * 3], b2 = lg[tid * 3 + 1], c2 = lg[tid * 3 + 2];
        float mx = fmaxf(a, fmaxf(b2, c2));
        float ea = expf(a - mx), eb = expf(b2 - mx), ec = expf(c2 - mx);
        float s = ea + eb + ec;
        g_gate[tid * 3 + 0] = ea / s;
        g_gate[tid * 3 + 1] = eb / s;
        g_gate[tid * 3 + 2] = ec / s;
    }
}

// ---------------- q / k1 / v1 projection (8-row tiles) ----------------
__global__ void qkv_kernel(const float* __restrict__ Wqn, const float* __restrict__ Wqr,
                           const float* __restrict__ Wkn, const float* __restrict__ Wv) {
    const int RT = 8;
    int row0 = blockIdx.x * RT;
    int tid = threadIdx.x; // 256
    __shared__ float cqs[RT][96];
    __shared__ float ckvs[RT][32];
    __shared__ float krs[RT][64];
    for (int i = tid; i < RT * 96; i += 256) cqs[i / 96][i % 96] = g_cq[(size_t)(row0 + i / 96) * 96 + (i % 96)];
    for (int i = tid; i < RT * 32; i += 256) ckvs[i / 32][i % 32] = g_ckv[(size_t)(row0 + i / 32) * 32 + (i % 32)];
    for (int i = tid; i < RT * 64; i += 256) krs[i / 64][i % 64] = g_kr[(size_t)(row0 + i / 64) * 64 + (i % 64)];
    __syncthreads();
    for (int o = tid; o < 512; o += 256) {
        int h = o >> 5, d = o & 31;
        float acc[RT];
        #pragma unroll
        for (int r = 0; r < RT; ++r) acc[r] = 0.f;
        for (int c = 0; c < 96; ++c) {
            float w = Wqn[c * 512 + o];
            #pragma unroll
            for (int r = 0; r < RT; ++r) acc[r] += cqs[r][c] * w;
        }
        #pragma unroll
        for (int r = 0; r < RT; ++r) {
            int row = row0 + r; int b = row / T_SEQ, t = row % T_SEQ;
            g_q[((size_t)(b * H_NUM + h) * T_SEQ + t) * HD + d] = acc[r];
        }
    }
    for (int p = tid; p < 512; p += 256) {
        int h = p >> 5, i = p & 31;
        float ar[RT], ai[RT];
        #pragma unroll
        for (int r = 0; r < RT; ++r) { ar[r] = 0.f; ai[r] = 0.f; }
        for (int c = 0; c < 96; ++c) {
            float wr = Wqr[c * 1024 + h * 64 + i];
            float wi = Wqr[c * 1024 + h * 64 + 32 + i];
            #pragma unroll
            for (int r = 0; r < RT; ++r) { ar[r] += cqs[r][c] * wr; ai[r] += cqs[r][c] * wi; }
        }
        #pragma unroll
        for (int r = 0; r < RT; ++r) {
            int row = row0 + r; int b = row / T_SEQ, t = row % T_SEQ;
            float co = g_costab[t * 32 + i], si = g_sintab[t * 32 + i];
            size_t base = ((size_t)(b * H_NUM + h) * T_SEQ + t) * HD;
            g_q[base + 32 + i] = ar[r] * co - ai[r] * si;
            g_q[base + 64 + i] = ar[r] * si + ai[r] * co;
        }
    }
    for (int o = tid; o < 512; o += 256) {
        int h = o >> 5, d = o & 31;
        float acc[RT];
        #pragma unroll
        for (int r = 0; r < RT; ++r) acc[r] = 0.f;
        for (int c = 0; c < 32; ++c) {
            float w = Wkn[c * 512 + o];
            #pragma unroll
            for (int r = 0; r < RT; ++r) acc[r] += ckvs[r][c] * w;
        }
        #pragma unroll
        for (int r = 0; r < RT; ++r) {
            int row = row0 + r; int b = row / T_SEQ, t = row % T_SEQ;
            g_k1[((size_t)(b * H_NUM + h) * T_SEQ + t) * HD + d] = acc[r];
        }
    }
    for (int o = tid; o < 512; o += 256) {
        int h = o >> 5, d = o & 31;
        float acc[RT];
        #pragma unroll
        for (int r = 0; r < RT; ++r) acc[r] = 0.f;
        for (int c = 0; c < 32; ++c) {
            float w = Wv[c * 512 + o];
            #pragma unroll
            for (int r = 0; r < RT; ++r) acc[r] += ckvs[r][c] * w;
        }
        #pragma unroll
        for (int r = 0; r < RT; ++r) {
            int row = row0 + r; int b = row / T_SEQ, t = row % T_SEQ;
            g_v1[((size_t)(b * H_NUM + h) * T_SEQ + t) * VD + d] = acc[r];
        }
    }
    for (int i = tid; i < RT * H_NUM * 64; i += 256) {
        int r = i / (H_NUM * 64); int rem = i % (H_NUM * 64); int h = rem / 64; int d = rem % 64;
        int row = row0 + r; int b = row / T_SEQ, t = row % T_SEQ;
        g_k1[((size_t)(b * H_NUM + h) * T_SEQ + t) * HD + 32 + d] = krs[r][d];
    }
}

// ---------------- top-k ----------------
__global__ void topk_kernel() {
    __shared__ float v[T_SEQ];
    __shared__ int   ix[T_SEQ];
    int b = blockIdx.x, tid = threadIdx.x; // 1024
    for (int i = tid; i < T_SEQ; i += 1024) { v[i] = g_imp[b * T_SEQ + i]; ix[i] = i; }
    __syncthreads();
    for (int k = 2; k <= T_SEQ; k <<= 1)
        for (int j = k >> 1; j > 0; j >>= 1) {
            for (int i = tid; i < T_SEQ; i += 1024) {
                int p = i ^ j;
                if (p > i) {
                    bool up = ((i & k) == 0);
                    bool sw = up ? (v[i] < v[p]) : (v[i] > v[p]);
                    if (sw) {
                        float tv = v[i]; v[i] = v[p]; v[p] = tv;
                        int ti = ix[i]; ix[i] = ix[p]; ix[p] = ti;
                    }
                }
            }
            __syncthreads();
        }
    for (int k = 2; k <= KEEP; k <<= 1)
        for (int j = k >> 1; j > 0; j >>= 1) {
            if (tid < KEEP) {
                int i = tid, p = i ^ j;
                if (p > i) {
                    bool up = ((i & k) == 0);
                    bool sw = up ? (ix[i] > ix[p]) : (ix[i] < ix[p]);
                    if (sw) { int ti = ix[i]; ix[i] = ix[p]; ix[p] = ti; }
                }
            }
            __syncthreads();
        }
    for (int i = tid; i < KEEP; i += 1024) g_idx[b * KEEP + i] = ix[i];
}

// ---------------- sel / window K,V projection (16-row tiles, roped) ----------------
template <bool SEL>
__global__ void kvproj_kernel(const float* __restrict__ x,
                              const float* __restrict__ Wk, const float* __restrict__ Wv) {
    const int RT = 16;
    const int Tk = SEL ? KEEP : T_SEQ;
    int row0 = blockIdx.x * RT;
    int tid = threadIdx.x; // 256
    __shared__ float xs[RT][C_DIM];
    for (int r = 0; r < RT; ++r) {
        int row = row0 + r; int b = row / Tk; int s = row % Tk;
        int src = SEL ? (b * T_SEQ + g_idx[b * KEEP + s]) : (b * T_SEQ + s);
        xs[r][tid] = x[(size_t)src * C_DIM + tid];
    }
    __syncthreads();
    float* Ko = SEL ? g_ks : g_kw;
    float* Vo = SEL ? g_vs : g_vw;
    for (int o = tid; o < 512; o += 256) {
        int h = o >> 5, d = o & 31; int col = h * HD + d;
        float acc[RT];
        #pragma unroll
        for (int r = 0; r < RT; ++r) acc[r] = 0.f;
        for (int c = 0; c < C_DIM; ++c) {
            float w = Wk[c * (H_NUM * HD) + col];
            #pragma unroll
            for (int r = 0; r < RT; ++r) acc[r] += xs[r][c] * w;
        }
        #pragma unroll
        for (int r = 0; r < RT; ++r) {
            int row = row0 + r; int b = row / Tk; int s = row % Tk;
            Ko[((size_t)(b * H_NUM + h) * Tk + s) * HD + d] = acc[r];
        }
    }
    for (int p = tid; p < 512; p += 256) {
        int h = p >> 5, i = p & 31;
        float ar[RT], ai[RT];
        #pragma unroll
        for (int r = 0; r < RT; ++r) { ar[r] = 0.f; ai[r] = 0.f; }
        for (int c = 0; c < C_DIM; ++c) {
            float wr = Wk[c * (H_NUM * HD) + h * HD + 32 + i];
            float wi = Wk[c * (H_NUM * HD) + h * HD + 64 + i];
            #pragma unroll
            for (int r = 0; r < RT; ++r) { ar[r] += xs[r][c] * wr; ai[r] += xs[r][c] * wi; }
        }
        #pragma unroll
        for (int r = 0; r < RT; ++r) {
            int row = row0 + r; int b = row / Tk; int s = row % Tk;
            float co = g_costab[s * 32 + i], si = g_sintab[s * 32 + i];
            size_t base = ((size_t)(b * H_NUM + h) * Tk + s) * HD;
            Ko[base + 32 + i] = ar[r] * co - ai[r] * si;
            Ko[base + 64 + i] = ar[r] * si + ai[r] * co;
        }
    }
    for (int o = tid; o < 512; o += 256) {
        int h = o >> 5, d = o & 31;
        float acc[RT];
        #pragma unroll
        for (int r = 0; r < RT; ++r) acc[r] = 0.f;
        for (int c = 0; c < C_DIM; ++c) {
            float w = Wv[c * 512 + o];
            #pragma unroll
            for (int r = 0; r < RT; ++r) acc[r] += xs[r][c] * w;
        }
        #pragma unroll
        for (int r = 0; r < RT; ++r) {
            int row = row0 + r; int b = row / Tk; int s = row % Tk;
            Vo[((size_t)(b * H_NUM + h) * Tk + s) * VD + d] = acc[r];
        }
    }
}

// ---------------- tensor-core flash attention (tf32 wmma) ----------------
// Block: 32 queries, 64-key tiles, 8 warps (256 thr).
// MODE 0: full causal (k1,v1)  MODE 1: sel, no mask (ks,vs)  MODE 2: window causal (kw,vw)
#define QB 32
#define KB 64
#define LDK 100
#define LDQ 100
#define LDV 36
#define LDS_ 68
#define LDO 36
#define ATTN_SMEM ((KB*LDK + KB*LDV + QB*LDQ + QB*LDS_ + QB*LDO + 64) * 4)

template <int MODE, bool ACCUM>
__global__ void __launch_bounds__(256) attn_mma(int branch) {
    extern __shared__ float sm[];
    float* Ks   = sm;                  // KB x LDK
    float* Vs   = Ks + KB * LDK;       // KB x LDV
    float* Qs   = Vs + KB * LDV;       // QB x LDQ
    float* Ss   = Qs + QB * LDQ;       // QB x LDS_
    float* Os   = Ss + QB * LDS_;      // QB x LDO
    float* m_sm = Os + QB * LDO;       // QB
    float* l_sm = m_sm + QB;           // QB

    const int Tk = (MODE == 1) ? KEEP : T_SEQ;
    int b = blockIdx.z, h = blockIdx.y;
    int qt0 = blockIdx.x * QB;
    int tid = threadIdx.x;
    int w = tid >> 5;
    const float* K = (MODE == 1) ? g_ks : (MODE == 2) ? g_kw : g_k1;
    const float* V = (MODE == 1) ? g_vs : (MODE == 2) ? g_vw : g_v1;
    const float* Kbase = K + (size_t)(b * H_NUM + h) * Tk * HD;
    const float* Vbase = V + (size_t)(b * H_NUM + h) * Tk * VD;
    const float* Qbase = g_q + ((size_t)(b * H_NUM + h) * T_SEQ + qt0) * HD;
    const float scale = 0.10206207262f; // 1/sqrt(96)

    for (int i = tid; i < QB * HD; i += 256) {
        int r = i / HD, c = i % HD;
        Qs[r * LDQ + c] = Qbase[(size_t)r * HD + c] * scale;
    }
    for (int i = tid; i < QB * VD; i += 256) Os[(i / VD) * LDO + (i % VD)] = 0.f;
    if (tid < QB) { m_sm[tid] = -1e30f; l_sm[tid] = 0.f; }
    __syncthreads();

    int wr = w >> 2, wc = w & 3;
    wmma::fragment<wmma::matrix_a, 16, 16, 8, wmma::precision::tf32, wmma::row_major> afrag[12];
    #pragma unroll
    for (int kk = 0; kk < 12; ++kk)
        wmma::load_matrix_sync(afrag[kk], Qs + wr * 16 * LDQ + kk * 8, LDQ);

    int kend = (MODE == 1) ? Tk : (qt0 + QB);
    int k0 = 0;
    if (MODE == 2) { int a0 = qt0 - (WIN - 1); k0 = (a0 > 0) ? (a0 & ~(KB - 1)) : 0; }

    int row = tid >> 3, sub = tid & 7;
    int trow = qt0 + row;

    for (int kt = k0; kt < kend; kt += KB) {
        __syncthreads();
        // load K tile (64x96) / V tile (64x32) as float4
        const float4* Ksrc = (const float4*)(Kbase + (size_t)kt * HD);
        float4* Kd = (float4*)Ks;
        #pragma unroll
        for (int i = 0; i < 6; ++i) {
            int idx = tid + i * 256;
            int r = idx / 24, c = idx % 24;
            Kd[r * 25 + c] = Ksrc[idx];
        }
        const float4* Vsrc = (const float4*)(Vbase + (size_t)kt * VD);
        float4* Vd = (float4*)Vs;
        #pragma unroll
        for (int i = 0; i < 2; ++i) {
            int idx = tid + i * 256;
            int r = idx / 8, c = idx % 8;
            Vd[r * 9 + c] = Vsrc[idx];
        }
        __syncthreads();
        // S = Q K^T : each warp one 16x16 tile
        {
            wmma::fragment<wmma::accumulator, 16, 16, 8, float> cf;
            wmma::fill_fragment(cf, 0.f);
            #pragma unroll
            for (int kk = 0; kk < 12; ++kk) {
                wmma::fragment<wmma::matrix_b, 16, 16, 8, wmma::precision::tf32, wmma::col_major> bf;
                wmma::load_matrix_sync(bf, Ks + wc * 16 * LDK + kk * 8, LDK);
                wmma::mma_sync(cf, afrag[kk], bf, cf);
            }
            wmma::store_matrix_sync(Ss + wr * 16 * LDS_ + wc * 16, cf, LDS_, wmma::mem_row_major);
        }
        __syncthreads();
        // online softmax: 8 threads per row
        {
            float mx = -1e30f;
            #pragma unroll
            for (int j = 0; j < 8; ++j) {
                int col = sub * 8 + j;
                int key = kt + col;
                bool ok = (MODE == 1) ? true : (key <= trow);
                if (MODE == 2) ok = ok && (trow - key < WIN);
                float s = ok ? Ss[row * LDS_ + col] : -1e30f;
                Ss[row * LDS_ + col] = s;
                mx = fmaxf(mx, s);
            }
            mx = fmaxf(mx, __shfl_xor_sync(0xffffffffu, mx, 1));
            mx = fmaxf(mx, __shfl_xor_sync(0xffffffffu, mx, 2));
            mx = fmaxf(mx, __shfl_xor_sync(0xffffffffu, mx, 4));
            float m_old = m_sm[row];
            float m_new = fmaxf(m_old, mx);
            float corr = __expf(m_old - m_new);
            float lsum = 0.f;
            #pragma unroll
            for (int j = 0; j < 8; ++j) {
                int col = sub * 8 + j;
                float s = Ss[row * LDS_ + col];
                float p = __expf(s - m_new);
                p = (s > -1e29f) ? p : 0.f;   // fully-masked guard (m_new may be -1e30)
                Ss[row * LDS_ + col] = p;
                lsum += p;
            }
            lsum += __shfl_xor_sync(0xffffffffu, lsum, 1);
            lsum += __shfl_xor_sync(0xffffffffu, lsum, 2);
            lsum += __shfl_xor_sync(0xffffffffu, lsum, 4);
            if (sub == 0) { m_sm[row] = m_new; l_sm[row] = l_sm[row] * corr + lsum; }
            #pragma unroll
            for (int j = 0; j < 4; ++j) Os[row * LDO + sub * 4 + j] *= corr;
        }
        __syncthreads();
        // O += P V : warps 0..3 each a 16x16 tile
        if (w < 4) {
            int r0 = (w >> 1) * 16, c0 = (w & 1) * 16;
            wmma::fragment<wmma::accumulator, 16, 16, 8, float> of;
            wmma::load_matrix_sync(of, Os + r0 * LDO + c0, LDO, wmma::mem_row_major);
            #pragma unroll
            for (int kk = 0; kk < 8; ++kk) {
                wmma::fragment<wmma::matrix_a, 16, 16, 8, wmma::precision::tf32, wmma::row_major> pa;
                wmma::fragment<wmma::matrix_b, 16, 16, 8, wmma::precision::tf32, wmma::row_major> vb;
                wmma::load_matrix_sync(pa, Ss + r0 * LDS_ + kk * 8, LDS_);
                wmma::load_matrix_sync(vb, Vs + kk * 8 * LDV + c0, LDV);
                wmma::mma_sync(of, pa, vb, of);
            }
            wmma::store_matrix_sync(Os + r0 * LDO + c0, of, LDO, wmma::mem_row_major);
        }
    }
    __syncthreads();
    // epilogue: out = Os * gate / l  (accumulate across branches)
    float g = g_gate[b * 3 + branch];
    float inv = g / l_sm[row];
    int d0 = sub * 4;
    float* op = g_O + ((size_t)(b * T_SEQ + trow) * H_NUM + h) * VD + d0;
    #pragma unroll
    for (int j = 0; j < 4; ++j) {
        float v = Os[row * LDO + d0 + j] * inv;
        if (ACCUM) v += op[j];
        op[j] = v;
    }
}

// ---------------- final projection: (B,T,512) @ (512,256) ----------------
__global__ void proj_kernel(const float* __restrict__ Wproj, float* __restrict__ out) {
    const int RT = 16;
    int row0 = blockIdx.x * RT;
    int tid = threadIdx.x; // 256
    __shared__ float Os[RT][512];
    for (int i = tid; i < RT * 512; i += 256) Os[i >> 9][i & 511] = g_O[((size_t)row0 << 9) + i];
    __syncthreads();
    float acc[RT];
    #pragma unroll
    for (int r = 0; r < RT; ++r) acc[r] = 0.f;
    for (int c = 0; c < 512; ++c) {
        float w = Wproj[c * 256 + tid];
        #pragma unroll
        for (int r = 0; r < RT; ++r) acc[r] += Os[r][c] * w;
    }
    #pragma unroll
    for (int r = 0; r < RT; ++r) out[(size_t)(row0 + r) * 256 + tid] = acc[r];
}

// ---------------- launch ----------------
extern "C" void kernel_launch(void* const* d_in, const int* in_sizes, int n_in,
                              void* d_out, int out_size) {
    const float* x     = (const float*)d_in[0];
    const float* Wcq   = (const float*)d_in[1];
    const float* qnw   = (const float*)d_in[2];
    const float* Wqn   = (const float*)d_in[3];
    const float* Wqr   = (const float*)d_in[4];
    const float* Wckv  = (const float*)d_in[5];
    const float* kvnw  = (const float*)d_in[6];
    const float* Wkn   = (const float*)d_in[7];
    const float* Wv    = (const float*)d_in[8];
    const float* Wkr   = (const float*)d_in[9];
    const float* Wimp  = (const float*)d_in[10];
    const float* Wselk = (const float*)d_in[11];
    const float* Wselv = (const float*)d_in[12];
    const float* Wwink = (const float*)d_in[13];
    const float* Wwinv = (const float*)d_in[14];
    const float* Wgate = (const float*)d_in[15];
    const float* Wproj = (const float*)d_in[16];
    float* out = (float*)d_out;
    int B = in_sizes[0] / (T_SEQ * C_DIM);
    if (B < 1) B = 1; if (B > BMAX) B = BMAX;

    cudaFuncSetAttribute(attn_mma<0, false>, cudaFuncAttributeMaxDynamicSharedMemorySize, ATTN_SMEM);
    cudaFuncSetAttribute(attn_mma<1, true >, cudaFuncAttributeMaxDynamicSharedMemorySize, ATTN_SMEM);
    cudaFuncSetAttribute(attn_mma<2, true >, cudaFuncAttributeMaxDynamicSharedMemorySize, ATTN_SMEM);

    rope_tab_kernel<<<(T_SEQ * 32 + 255) / 256, 256>>>();
    row_feat_kernel<<<B * T_SEQ, 256>>>(x, Wcq, qnw, Wckv, kvnw, Wkr, Wimp);
    gate_kernel<<<1, 192>>>(x, Wgate, B);
    qkv_kernel<<<B * T_SEQ / 8, 256>>>(Wqn, Wqr, Wkn, Wv);
    topk_kernel<<<B, 1024>>>();
    kvproj_kernel<true><<<B * KEEP / 16, 256>>>(x, Wselk, Wselv);
    kvproj_kernel<false><<<B * T_SEQ / 16, 256>>>(x, Wwink, Wwinv);

    dim3 agrid(T_SEQ / QB, H_NUM, B);
    attn_mma<0, false><<<agrid, 256, ATTN_SMEM>>>(0);
    attn_mma<1, true ><<<agrid, 256, ATTN_SMEM>>>(1);
    attn_mma<2, true ><<<agrid, 256, ATTN_SMEM>>>(2);

    proj_kernel<<<B * T_SEQ / 16, 256>>>(Wproj, out);
}

// round 3
// speedup vs baseline: 1.2319x; 1.1070x over previous
#include <cuda_runtime.h>
#include <math.h>
#include <stdint.h>

#define T_SEQ 2048
#define C_DIM 256
#define H_NUM 16
#define NOPE 32
#define ROPE 64
#define HD 96
#define VD 32
#define KEEP 512
#define WIN 128
#define BMAX 2
#define EPSF 1e-6f

// ---------------- device scratch ----------------
__device__ float g_costab[T_SEQ * 32];
__device__ float g_sintab[T_SEQ * 32];
__device__ float g_cq[BMAX * T_SEQ * 96];
__device__ float g_ckv[BMAX * T_SEQ * 32];
__device__ float g_kr[BMAX * T_SEQ * 64];
__device__ float g_imp[BMAX * T_SEQ];
__device__ int   g_idx[BMAX * KEEP];
__device__ float g_gate[BMAX * 3];
__device__ float g_q [BMAX * H_NUM * T_SEQ * HD];
__device__ float g_k1[BMAX * H_NUM * T_SEQ * HD];
__device__ float g_v1[BMAX * H_NUM * T_SEQ * VD];
__device__ float g_ks[BMAX * H_NUM * KEEP * HD];
__device__ float g_vs[BMAX * H_NUM * KEEP * VD];
__device__ float g_kw[BMAX * H_NUM * T_SEQ * HD];
__device__ float g_vw[BMAX * H_NUM * T_SEQ * VD];
__device__ float g_O [BMAX * T_SEQ * H_NUM * VD];

__device__ __forceinline__ uint32_t f2tf32(float f) {
    uint32_t r;
    asm("cvt.rna.tf32.f32 %0, %1;" : "=r"(r) : "f"(f));
    return r;
}
__device__ __forceinline__ float tf32v(float f) { return __uint_as_float(f2tf32(f)); }

__device__ __forceinline__ void mma8(float* c, const uint32_t* a, uint32_t b0, uint32_t b1) {
    asm volatile("mma.sync.aligned.m16n8k8.row.col.f32.tf32.tf32.f32 "
        "{%0,%1,%2,%3}, {%4,%5,%6,%7}, {%8,%9}, {%0,%1,%2,%3};"
        : "+f"(c[0]), "+f"(c[1]), "+f"(c[2]), "+f"(c[3])
        : "r"(a[0]), "r"(a[1]), "r"(a[2]), "r"(a[3]), "r"(b0), "r"(b1));
}

// ---------------- rope table ----------------
__global__ void rope_tab_kernel() {
    int id = blockIdx.x * 256 + threadIdx.x;
    if (id >= T_SEQ * 32) return;
    int t = id >> 5, i = id & 31;
    float f = (float)pow(10000.0, -(double)i / 32.0);
    float ang = (float)t * f;
    g_costab[id] = cosf(ang);
    g_sintab[id] = sinf(ang);
}

// ---------------- per-row features ----------------
__global__ void row_feat_kernel(const float* __restrict__ x,
                                const float* __restrict__ Wcq, const float* __restrict__ qnw,
                                const float* __restrict__ Wckv, const float* __restrict__ kvnw,
                                const float* __restrict__ Wkr, const float* __restrict__ Wimp) {
    int row = blockIdx.x;
    int tid = threadIdx.x; // 256
    int t = row % T_SEQ;
    __shared__ float xs[C_DIM];
    __shared__ float ybuf[192];
    __shared__ float red[256];
    xs[tid] = x[(size_t)row * C_DIM + tid];
    __syncthreads();
    if (tid < 96) {
        float a = 0.f;
        for (int c = 0; c < C_DIM; ++c) a += xs[c] * Wcq[c * 96 + tid];
        ybuf[tid] = a;
    } else if (tid < 128) {
        int j = tid - 96; float a = 0.f;
        for (int c = 0; c < C_DIM; ++c) a += xs[c] * Wckv[c * 32 + j];
        ybuf[96 + j] = a;
    } else if (tid < 192) {
        int j = tid - 128; float a = 0.f;
        for (int c = 0; c < C_DIM; ++c) a += xs[c] * Wkr[c * 64 + j];
        ybuf[128 + j] = a * (1.f / (float)H_NUM);
    } else if (tid == 192) {
        float a = 0.f;
        for (int c = 0; c < C_DIM; ++c) a += xs[c] * Wimp[c];
        g_imp[row] = a;
    }
    __syncthreads();
    red[tid] = (tid < 96) ? ybuf[tid] * ybuf[tid] : 0.f;
    __syncthreads();
    for (int s = 128; s > 0; s >>= 1) { if (tid < s) red[tid] += red[tid + s]; __syncthreads(); }
    float rms_cq = rsqrtf(red[0] / 96.f + EPSF);
    __syncthreads();
    red[tid] = (tid < 32) ? ybuf[96 + tid] * ybuf[96 + tid] : 0.f;
    __syncthreads();
    for (int s = 128; s > 0; s >>= 1) { if (tid < s) red[tid] += red[tid + s]; __syncthreads(); }
    float rms_kv = rsqrtf(red[0] / 32.f + EPSF);
    if (tid < 96) g_cq[(size_t)row * 96 + tid] = ybuf[tid] * rms_cq * qnw[tid];
    if (tid < 32) g_ckv[(size_t)row * 32 + tid] = ybuf[96 + tid] * rms_kv * kvnw[tid];
    if (tid < 32) {
        float xr = ybuf[128 + tid], xi = ybuf[160 + tid];
        float co = g_costab[t * 32 + tid], si = g_sintab[t * 32 + tid];
        g_kr[(size_t)row * 64 + tid]      = xr * co - xi * si;
        g_kr[(size_t)row * 64 + 32 + tid] = xr * si + xi * co;
    }
}

// ---------------- gate ----------------
__global__ void gate_kernel(const float* __restrict__ x, const float* __restrict__ Wgate, int B) {
    __shared__ float lg[6];
    int tid = threadIdx.x;
    int w = tid >> 5, lane = tid & 31;
    if (w < B * 3) {
        int b = w / 3, j = w % 3;
        float s = 0.f;
        for (int c = lane; c < C_DIM; c += 32) {
            float colsum = 0.f;
            const float* xp = x + (size_t)b * T_SEQ * C_DIM + c;
            for (int t = 0; t < T_SEQ; ++t) colsum += xp[(size_t)t * C_DIM];
            s += (colsum / (float)T_SEQ) * Wgate[c * 3 + j];
        }
        #pragma unroll
        for (int o = 16; o > 0; o >>= 1) s += __shfl_xor_sync(0xffffffffu, s, o);
        if (lane == 0) lg[w] = s;
    }
    __syncthreads();
    if (tid < B) {
        float a = lg[tid * 3], b2 = lg[tid * 3 + 1], c2 = lg[tid * 3 + 2];
        float mx = fmaxf(a, fmaxf(b2, c2));
        float ea = expf(a - mx), eb = expf(b2 - mx), ec = expf(c2 - mx);
        float s = ea + eb + ec;
        g_gate[tid * 3 + 0] = ea / s;
        g_gate[tid * 3 + 1] = eb / s;
        g_gate[tid * 3 + 2] = ec / s;
    }
}

// ---------------- q / k1 / v1 projection ----------------
__global__ void qkv_kernel(const float* __restrict__ Wqn, const float* __restrict__ Wqr,
                           const float* __restrict__ Wkn, const float* __restrict__ Wv) {
    const int RT = 8;
    int row0 = blockIdx.x * RT;
    int tid = threadIdx.x; // 256
    __shared__ float cqs[RT][96];
    __shared__ float ckvs[RT][32];
    __shared__ float krs[RT][64];
    for (int i = tid; i < RT * 96; i += 256) cqs[i / 96][i % 96] = g_cq[(size_t)(row0 + i / 96) * 96 + (i % 96)];
    for (int i = tid; i < RT * 32; i += 256) ckvs[i / 32][i % 32] = g_ckv[(size_t)(row0 + i / 32) * 32 + (i % 32)];
    for (int i = tid; i < RT * 64; i += 256) krs[i / 64][i % 64] = g_kr[(size_t)(row0 + i / 64) * 64 + (i % 64)];
    __syncthreads();
    for (int o = tid; o < 512; o += 256) {
        int h = o >> 5, d = o & 31;
        float acc[RT];
        #pragma unroll
        for (int r = 0; r < RT; ++r) acc[r] = 0.f;
        for (int c = 0; c < 96; ++c) {
            float w = Wqn[c * 512 + o];
            #pragma unroll
            for (int r = 0; r < RT; ++r) acc[r] += cqs[r][c] * w;
        }
        #pragma unroll
        for (int r = 0; r < RT; ++r) {
            int row = row0 + r; int b = row / T_SEQ, t = row % T_SEQ;
            g_q[((size_t)(b * H_NUM + h) * T_SEQ + t) * HD + d] = acc[r];
        }
    }
    for (int p = tid; p < 512; p += 256) {
        int h = p >> 5, i = p & 31;
        float ar[RT], ai[RT];
        #pragma unroll
        for (int r = 0; r < RT; ++r) { ar[r] = 0.f; ai[r] = 0.f; }
        for (int c = 0; c < 96; ++c) {
            float wr = Wqr[c * 1024 + h * 64 + i];
            float wi = Wqr[c * 1024 + h * 64 + 32 + i];
            #pragma unroll
            for (int r = 0; r < RT; ++r) { ar[r] += cqs[r][c] * wr; ai[r] += cqs[r][c] * wi; }
        }
        #pragma unroll
        for (int r = 0; r < RT; ++r) {
            int row = row0 + r; int b = row / T_SEQ, t = row % T_SEQ;
            float co = g_costab[t * 32 + i], si = g_sintab[t * 32 + i];
            size_t base = ((size_t)(b * H_NUM + h) * T_SEQ + t) * HD;
            g_q[base + 32 + i] = ar[r] * co - ai[r] * si;
            g_q[base + 64 + i] = ar[r] * si + ai[r] * co;
        }
    }
    for (int o = tid; o < 512; o += 256) {
        int h = o >> 5, d = o & 31;
        float acc[RT];
        #pragma unroll
        for (int r = 0; r < RT; ++r) acc[r] = 0.f;
        for (int c = 0; c < 32; ++c) {
            float w = Wkn[c * 512 + o];
            #pragma unroll
            for (int r = 0; r < RT; ++r) acc[r] += ckvs[r][c] * w;
        }
        #pragma unroll
        for (int r = 0; r < RT; ++r) {
            int row = row0 + r; int b = row / T_SEQ, t = row % T_SEQ;
            g_k1[((size_t)(b * H_NUM + h) * T_SEQ + t) * HD + d] = acc[r];
        }
    }
    for (int o = tid; o < 512; o += 256) {
        int h = o >> 5, d = o & 31;
        float acc[RT];
        #pragma unroll
        for (int r = 0; r < RT; ++r) acc[r] = 0.f;
        for (int c = 0; c < 32; ++c) {
            float w = Wv[c * 512 + o];
            #pragma unroll
            for (int r = 0; r < RT; ++r) acc[r] += ckvs[r][c] * w;
        }
        #pragma unroll
        for (int r = 0; r < RT; ++r) {
            int row = row0 + r; int b = row / T_SEQ, t = row % T_SEQ;
            g_v1[((size_t)(b * H_NUM + h) * T_SEQ + t) * VD + d] = acc[r];
        }
    }
    for (int i = tid; i < RT * H_NUM * 64; i += 256) {
        int r = i / (H_NUM * 64); int rem = i % (H_NUM * 64); int h = rem / 64; int d = rem % 64;
        int row = row0 + r; int b = row / T_SEQ, t = row % T_SEQ;
        g_k1[((size_t)(b * H_NUM + h) * T_SEQ + t) * HD + 32 + d] = krs[r][d];
    }
}

// ---------------- top-k ----------------
__global__ void topk_kernel() {
    __shared__ float v[T_SEQ];
    __shared__ int   ix[T_SEQ];
    int b = blockIdx.x, tid = threadIdx.x; // 1024
    for (int i = tid; i < T_SEQ; i += 1024) { v[i] = g_imp[b * T_SEQ + i]; ix[i] = i; }
    __syncthreads();
    for (int k = 2; k <= T_SEQ; k <<= 1)
        for (int j = k >> 1; j > 0; j >>= 1) {
            for (int i = tid; i < T_SEQ; i += 1024) {
                int p = i ^ j;
                if (p > i) {
                    bool up = ((i & k) == 0);
                    bool sw = up ? (v[i] < v[p]) : (v[i] > v[p]);
                    if (sw) {
                        float tv = v[i]; v[i] = v[p]; v[p] = tv;
                        int ti = ix[i]; ix[i] = ix[p]; ix[p] = ti;
                    }
                }
            }
            __syncthreads();
        }
    for (int k = 2; k <= KEEP; k <<= 1)
        for (int j = k >> 1; j > 0; j >>= 1) {
            if (tid < KEEP) {
                int i = tid, p = i ^ j;
                if (p > i) {
                    bool up = ((i & k) == 0);
                    bool sw = up ? (ix[i] > ix[p]) : (ix[i] < ix[p]);
                    if (sw) { int ti = ix[i]; ix[i] = ix[p]; ix[p] = ti; }
                }
            }
            __syncthreads();
        }
    for (int i = tid; i < KEEP; i += 1024) g_idx[b * KEEP + i] = ix[i];
}

// ---------------- sel / window K,V projection ----------------
template <bool SEL>
__global__ void kvproj_kernel(const float* __restrict__ x,
                              const float* __restrict__ Wk, const float* __restrict__ Wv) {
    const int RT = 16;
    const int Tk = SEL ? KEEP : T_SEQ;
    int row0 = blockIdx.x * RT;
    int tid = threadIdx.x; // 256
    __shared__ float xs[RT][C_DIM];
    for (int r = 0; r < RT; ++r) {
        int row = row0 + r; int b = row / Tk; int s = row % Tk;
        int src = SEL ? (b * T_SEQ + g_idx[b * KEEP + s]) : (b * T_SEQ + s);
        xs[r][tid] = x[(size_t)src * C_DIM + tid];
    }
    __syncthreads();
    float* Ko = SEL ? g_ks : g_kw;
    float* Vo = SEL ? g_vs : g_vw;
    for (int o = tid; o < 512; o += 256) {
        int h = o >> 5, d = o & 31; int col = h * HD + d;
        float acc[RT];
        #pragma unroll
        for (int r = 0; r < RT; ++r) acc[r] = 0.f;
        for (int c = 0; c < C_DIM; ++c) {
            float w = Wk[c * (H_NUM * HD) + col];
            #pragma unroll
            for (int r = 0; r < RT; ++r) acc[r] += xs[r][c] * w;
        }
        #pragma unroll
        for (int r = 0; r < RT; ++r) {
            int row = row0 + r; int b = row / Tk; int s = row % Tk;
            Ko[((size_t)(b * H_NUM + h) * Tk + s) * HD + d] = acc[r];
        }
    }
    for (int p = tid; p < 512; p += 256) {
        int h = p >> 5, i = p & 31;
        float ar[RT], ai[RT];
        #pragma unroll
        for (int r = 0; r < RT; ++r) { ar[r] = 0.f; ai[r] = 0.f; }
        for (int c = 0; c < C_DIM; ++c) {
            float wr = Wk[c * (H_NUM * HD) + h * HD + 32 + i];
            float wi = Wk[c * (H_NUM * HD) + h * HD + 64 + i];
            #pragma unroll
            for (int r = 0; r < RT; ++r) { ar[r] += xs[r][c] * wr; ai[r] += xs[r][c] * wi; }
        }
        #pragma unroll
        for (int r = 0; r < RT; ++r) {
            int row = row0 + r; int b = row / Tk; int s = row % Tk;
            float co = g_costab[s * 32 + i], si = g_sintab[s * 32 + i];
            size_t base = ((size_t)(b * H_NUM + h) * Tk + s) * HD;
            Ko[base + 32 + i] = ar[r] * co - ai[r] * si;
            Ko[base + 64 + i] = ar[r] * si + ai[r] * co;
        }
    }
    for (int o = tid; o < 512; o += 256) {
        int h = o >> 5, d = o & 31;
        float acc[RT];
        #pragma unroll
        for (int r = 0; r < RT; ++r) acc[r] = 0.f;
        for (int c = 0; c < C_DIM; ++c) {
            float w = Wv[c * 512 + o];
            #pragma unroll
            for (int r = 0; r < RT; ++r) acc[r] += xs[r][c] * w;
        }
        #pragma unroll
        for (int r = 0; r < RT; ++r) {
            int row = row0 + r; int b = row / Tk; int s = row % Tk;
            Vo[((size_t)(b * H_NUM + h) * Tk + s) * VD + d] = acc[r];
        }
    }
}

// ---------------- flash-attention v2 (raw mma m16n8k8 tf32, 3-term QK) ----------------
#define AQB 64
#define AKB 64
#define LDK 100
#define LDV 40
#define LDP 68
#define FA_SMEM ((2 * AKB * LDK + AKB * LDV + 4 * 16 * LDP) * 4)

template <int MODE, bool ACCUM>
__global__ void __launch_bounds__(128) attn_fa(int branch) {
    extern __shared__ float sm[];
    float* Khi = sm;                       // AKB x LDK
    float* Klo = Khi + AKB * LDK;          // AKB x LDK
    float* Vs  = Klo + AKB * LDK;          // AKB x LDV
    float* Pb  = Vs + AKB * LDV;           // 4 warps x 16 x LDP

    const int Tk = (MODE == 1) ? KEEP : T_SEQ;
    int b = blockIdx.z, h = blockIdx.y;
    int qt0 = blockIdx.x * AQB;
    int tid = threadIdx.x;
    int w = tid >> 5, lane = tid & 31;
    int g = lane >> 2, tg = lane & 3;
    int r0 = w * 16;
    float* Pw = Pb + w * 16 * LDP;

    const float* K = (MODE == 1) ? g_ks : (MODE == 2) ? g_kw : g_k1;
    const float* V = (MODE == 1) ? g_vs : (MODE == 2) ? g_vw : g_v1;
    const float* Kbase = K + (size_t)(b * H_NUM + h) * Tk * HD;
    const float* Vbase = V + (size_t)(b * H_NUM + h) * Tk * VD;
    const float* Qbase = g_q + ((size_t)(b * H_NUM + h) * T_SEQ + qt0) * HD;
    const float scale = 0.10206207262f; // 1/sqrt(96)

    // Q in registers, hi/lo tf32 split, scale folded in
    uint32_t qhi[12][4], qlo[12][4];
    #pragma unroll
    for (int kc = 0; kc < 12; ++kc) {
        #pragma unroll
        for (int e = 0; e < 4; ++e) {
            int row = r0 + g + (e & 1) * 8;
            int col = kc * 8 + tg + (e & 2) * 2;
            float q = Qbase[(size_t)row * HD + col] * scale;
            uint32_t hi = f2tf32(q);
            qhi[kc][e] = hi;
            qlo[kc][e] = f2tf32(q - __uint_as_float(hi));
        }
    }

    float oacc[4][4];
    #pragma unroll
    for (int nt = 0; nt < 4; ++nt)
        #pragma unroll
        for (int e = 0; e < 4; ++e) oacc[nt][e] = 0.f;
    float m0 = -1e30f, m1 = -1e30f, l0 = 0.f, l1 = 0.f;

    int kend = (MODE == 1) ? Tk : (qt0 + AQB);
    int k0 = 0;
    if (MODE == 2) { int a0 = qt0 - (WIN - 1); k0 = (a0 > 0) ? (a0 & ~(AKB - 1)) : 0; }

    for (int kt = k0; kt < kend; kt += AKB) {
        __syncthreads();
        // cooperative load: K hi/lo, V (all tf32-rounded)
        const float4* Ksrc = (const float4*)(Kbase + (size_t)kt * HD);
        #pragma unroll
        for (int it = 0; it < 12; ++it) {
            int i = tid + it * 128;
            int r = i / 24, c = i % 24;
            float4 v = Ksrc[i];
            float4 hi4, lo4;
            hi4.x = tf32v(v.x); lo4.x = tf32v(v.x - hi4.x);
            hi4.y = tf32v(v.y); lo4.y = tf32v(v.y - hi4.y);
            hi4.z = tf32v(v.z); lo4.z = tf32v(v.z - hi4.z);
            hi4.w = tf32v(v.w); lo4.w = tf32v(v.w - hi4.w);
            ((float4*)Khi)[r * 25 + c] = hi4;
            ((float4*)Klo)[r * 25 + c] = lo4;
        }
        const float4* Vsrc = (const float4*)(Vbase + (size_t)kt * VD);
        #pragma unroll
        for (int it = 0; it < 4; ++it) {
            int i = tid + it * 128;
            int r = i / 8, c = i % 8;
            float4 v = Vsrc[i];
            v.x = tf32v(v.x); v.y = tf32v(v.y); v.z = tf32v(v.z); v.w = tf32v(v.w);
            ((float4*)Vs)[r * 10 + c] = v;
        }
        __syncthreads();

        // S = Q K^T (3-term tf32)
        float sacc[8][4];
        #pragma unroll
        for (int nt = 0; nt < 8; ++nt)
            #pragma unroll
            for (int e = 0; e < 4; ++e) sacc[nt][e] = 0.f;
        #pragma unroll
        for (int nt = 0; nt < 8; ++nt) {
            #pragma unroll
            for (int kc = 0; kc < 12; ++kc) {
                const float* kp = Khi + (nt * 8 + g) * LDK + kc * 8 + tg;
                const float* lp = Klo + (nt * 8 + g) * LDK + kc * 8 + tg;
                uint32_t bh0 = __float_as_uint(kp[0]);
                uint32_t bh1 = __float_as_uint(kp[4]);
                uint32_t bl0 = __float_as_uint(lp[0]);
                uint32_t bl1 = __float_as_uint(lp[4]);
                mma8(sacc[nt], qhi[kc], bh0, bh1);
                mma8(sacc[nt], qhi[kc], bl0, bl1);
                mma8(sacc[nt], qlo[kc], bh0, bh1);
            }
        }

        // mask
        bool need_mask = (MODE == 2) || (MODE == 0 && kt + AKB > qt0);
        if (need_mask) {
            #pragma unroll
            for (int nt = 0; nt < 8; ++nt) {
                #pragma unroll
                for (int e = 0; e < 4; ++e) {
                    int key = kt + nt * 8 + 2 * tg + (e & 1);
                    int row = qt0 + r0 + g + ((e & 2) ? 8 : 0);
                    bool ok = key <= row;
                    if (MODE == 2) ok = ok && (row - key < WIN);
                    if (!ok) sacc[nt][e] = -1e30f;
                }
            }
        }

        // online softmax (registers + shfl)
        float mx0 = -1e30f, mx1 = -1e30f;
        #pragma unroll
        for (int nt = 0; nt < 8; ++nt) {
            mx0 = fmaxf(mx0, fmaxf(sacc[nt][0], sacc[nt][1]));
            mx1 = fmaxf(mx1, fmaxf(sacc[nt][2], sacc[nt][3]));
        }
        mx0 = fmaxf(mx0, __shfl_xor_sync(0xffffffffu, mx0, 1));
        mx0 = fmaxf(mx0, __shfl_xor_sync(0xffffffffu, mx0, 2));
        mx1 = fmaxf(mx1, __shfl_xor_sync(0xffffffffu, mx1, 1));
        mx1 = fmaxf(mx1, __shfl_xor_sync(0xffffffffu, mx1, 2));
        float m0n = fmaxf(m0, mx0), m1n = fmaxf(m1, mx1);
        float c0 = __expf(m0 - m0n), c1 = __expf(m1 - m1n);
        float s0 = 0.f, s1 = 0.f;
        #pragma unroll
        for (int nt = 0; nt < 8; ++nt) {
            #pragma unroll
            for (int e = 0; e < 4; ++e) {
                float sv = sacc[nt][e];
                float p = __expf(sv - ((e & 2) ? m1n : m0n));
                p = (sv > -1e29f) ? p : 0.f;
                if (e & 2) s1 += p; else s0 += p;
                Pw[(g + ((e & 2) ? 8 : 0)) * LDP + nt * 8 + 2 * tg + (e & 1)] =
                    __uint_as_float(f2tf32(p));
            }
        }
        s0 += __shfl_xor_sync(0xffffffffu, s0, 1);
        s0 += __shfl_xor_sync(0xffffffffu, s0, 2);
        s1 += __shfl_xor_sync(0xffffffffu, s1, 1);
        s1 += __shfl_xor_sync(0xffffffffu, s1, 2);
        l0 = l0 * c0 + s0; l1 = l1 * c1 + s1;
        m0 = m0n; m1 = m1n;
        #pragma unroll
        for (int nt = 0; nt < 4; ++nt) {
            oacc[nt][0] *= c0; oacc[nt][1] *= c0;
            oacc[nt][2] *= c1; oacc[nt][3] *= c1;
        }
        __syncwarp();

        // O += P V
        #pragma unroll
        for (int kc2 = 0; kc2 < 8; ++kc2) {
            uint32_t pa[4];
            #pragma unroll
            for (int e = 0; e < 4; ++e)
                pa[e] = __float_as_uint(Pw[(g + (e & 1) * 8) * LDP + kc2 * 8 + tg + (e & 2) * 2]);
            #pragma unroll
            for (int nt = 0; nt < 4; ++nt) {
                uint32_t b0 = __float_as_uint(Vs[(kc2 * 8 + tg) * LDV + nt * 8 + g]);
                uint32_t b1 = __float_as_uint(Vs[(kc2 * 8 + tg + 4) * LDV + nt * 8 + g]);
                mma8(oacc[nt], pa, b0, b1);
            }
        }
    }

    // epilogue
    float gte = g_gate[b * 3 + branch];
    float inv0 = gte / l0, inv1 = gte / l1;
    #pragma unroll
    for (int nt = 0; nt < 4; ++nt) {
        #pragma unroll
        for (int e = 0; e < 4; ++e) {
            int row = qt0 + r0 + g + ((e & 2) ? 8 : 0);
            int col = nt * 8 + 2 * tg + (e & 1);
            float v = oacc[nt][e] * ((e & 2) ? inv1 : inv0);
            float* op = &g_O[((size_t)(b * T_SEQ + row) * H_NUM + h) * VD + col];
            if (ACCUM) v += *op;
            *op = v;
        }
    }
}

// ---------------- final projection ----------------
__global__ void proj_kernel(const float* __restrict__ Wproj, float* __restrict__ out) {
    const int RT = 16;
    int row0 = blockIdx.x * RT;
    int tid = threadIdx.x; // 256
    __shared__ float Os[RT][512];
    for (int i = tid; i < RT * 512; i += 256) Os[i >> 9][i & 511] = g_O[((size_t)row0 << 9) + i];
    __syncthreads();
    float acc[RT];
    #pragma unroll
    for (int r = 0; r < RT; ++r) acc[r] = 0.f;
    for (int c = 0; c < 512; ++c) {
        float w = Wproj[c * 256 + tid];
        #pragma unroll
        for (int r = 0; r < RT; ++r) acc[r] += Os[r][c] * w;
    }
    #pragma unroll
    for (int r = 0; r < RT; ++r) out[(size_t)(row0 + r) * 256 + tid] = acc[r];
}

// ---------------- launch ----------------
extern "C" void kernel_launch(void* const* d_in, const int* in_sizes, int n_in,
                              void* d_out, int out_size) {
    const float* x     = (const float*)d_in[0];
    const float* Wcq   = (const float*)d_in[1];
    const float* qnw   = (const float*)d_in[2];
    const float* Wqn   = (const float*)d_in[3];
    const float* Wqr   = (const float*)d_in[4];
    const float* Wckv  = (const float*)d_in[5];
    const float* kvnw  = (const float*)d_in[6];
    const float* Wkn   = (const float*)d_in[7];
    const float* Wv    = (const float*)d_in[8];
    const float* Wkr   = (const float*)d_in[9];
    const float* Wimp  = (const float*)d_in[10];
    const float* Wselk = (const float*)d_in[11];
    const float* Wselv = (const float*)d_in[12];
    const float* Wwink = (const float*)d_in[13];
    const float* Wwinv = (const float*)d_in[14];
    const float* Wgate = (const float*)d_in[15];
    const float* Wproj = (const float*)d_in[16];
    float* out = (float*)d_out;
    int B = in_sizes[0] / (T_SEQ * C_DIM);
    if (B < 1) B = 1; if (B > BMAX) B = BMAX;

    cudaFuncSetAttribute(attn_fa<0, false>, cudaFuncAttributeMaxDynamicSharedMemorySize, FA_SMEM);
    cudaFuncSetAttribute(attn_fa<1, true >, cudaFuncAttributeMaxDynamicSharedMemorySize, FA_SMEM);
    cudaFuncSetAttribute(attn_fa<2, true >, cudaFuncAttributeMaxDynamicSharedMemorySize, FA_SMEM);

    rope_tab_kernel<<<(T_SEQ * 32 + 255) / 256, 256>>>();
    row_feat_kernel<<<B * T_SEQ, 256>>>(x, Wcq, qnw, Wckv, kvnw, Wkr, Wimp);
    gate_kernel<<<1, 192>>>(x, Wgate, B);
    qkv_kernel<<<B * T_SEQ / 8, 256>>>(Wqn, Wqr, Wkn, Wv);
    topk_kernel<<<B, 1024>>>();
    kvproj_kernel<true><<<B * KEEP / 16, 256>>>(x, Wselk, Wselv);
    kvproj_kernel<false><<<B * T_SEQ / 16, 256>>>(x, Wwink, Wwinv);

    dim3 agrid(T_SEQ / AQB, H_NUM, B);
    attn_fa<0, false><<<agrid, 128, FA_SMEM>>>(0);
    attn_fa<1, true ><<<agrid, 128, FA_SMEM>>>(1);
    attn_fa<2, true ><<<agrid, 128, FA_SMEM>>>(2);

    proj_kernel<<<B * T_SEQ / 16, 256>>>(Wproj, out);
}

// round 4
// speedup vs baseline: 1.3694x; 1.1116x over previous
#include <cuda_runtime.h>
#include <cuda_bf16.h>
#include <math.h>
#include <stdint.h>

#define T_SEQ 2048
#define C_DIM 256
#define H_NUM 16
#define NOPE 32
#define ROPE 64
#define HD 96
#define VD 32
#define KEEP 512
#define WIN 128
#define BMAX 2
#define EPSF 1e-6f

// ---------------- device scratch ----------------
__device__ float g_costab[T_SEQ * 32];
__device__ float g_sintab[T_SEQ * 32];
__device__ float g_cq[BMAX * T_SEQ * 96];
__device__ float g_ckv[BMAX * T_SEQ * 32];
__device__ float g_kr[BMAX * T_SEQ * 64];
__device__ float g_imp[BMAX * T_SEQ];
__device__ int   g_idx[BMAX * KEEP];
__device__ float g_gate[BMAX * 3];
__device__ float g_q [BMAX * H_NUM * T_SEQ * HD];
// K tensors stored as bf16 hi/lo split (written directly by projection kernels)
__device__ __nv_bfloat16 g_k1hi[BMAX * H_NUM * T_SEQ * HD];
__device__ __nv_bfloat16 g_k1lo[BMAX * H_NUM * T_SEQ * HD];
__device__ __nv_bfloat16 g_kshi[BMAX * H_NUM * KEEP * HD];
__device__ __nv_bfloat16 g_kslo[BMAX * H_NUM * KEEP * HD];
__device__ __nv_bfloat16 g_kwhi[BMAX * H_NUM * T_SEQ * HD];
__device__ __nv_bfloat16 g_kwlo[BMAX * H_NUM * T_SEQ * HD];
__device__ float g_v1[BMAX * H_NUM * T_SEQ * VD];
__device__ float g_vs[BMAX * H_NUM * KEEP * VD];
__device__ float g_vw[BMAX * H_NUM * T_SEQ * VD];
__device__ float g_O [BMAX * T_SEQ * H_NUM * VD];

__device__ __forceinline__ uint32_t f2tf32(float f) {
    uint32_t r;
    asm("cvt.rna.tf32.f32 %0, %1;" : "=r"(r) : "f"(f));
    return r;
}
__device__ __forceinline__ float tf32v(float f) { return __uint_as_float(f2tf32(f)); }

__device__ __forceinline__ void mma8(float* c, const uint32_t* a, uint32_t b0, uint32_t b1) {
    asm volatile("mma.sync.aligned.m16n8k8.row.col.f32.tf32.tf32.f32 "
        "{%0,%1,%2,%3}, {%4,%5,%6,%7}, {%8,%9}, {%0,%1,%2,%3};"
        : "+f"(c[0]), "+f"(c[1]), "+f"(c[2]), "+f"(c[3])
        : "r"(a[0]), "r"(a[1]), "r"(a[2]), "r"(a[3]), "r"(b0), "r"(b1));
}
__device__ __forceinline__ void mma16bf(float* c, const uint32_t* a, uint32_t b0, uint32_t b1) {
    asm volatile("mma.sync.aligned.m16n8k16.row.col.f32.bf16.bf16.f32 "
        "{%0,%1,%2,%3}, {%4,%5,%6,%7}, {%8,%9}, {%0,%1,%2,%3};"
        : "+f"(c[0]), "+f"(c[1]), "+f"(c[2]), "+f"(c[3])
        : "r"(a[0]), "r"(a[1]), "r"(a[2]), "r"(a[3]), "r"(b0), "r"(b1));
}

__device__ __forceinline__ void split_store(float v, __nv_bfloat16* hi, __nv_bfloat16* lo) {
    __nv_bfloat16 h = __float2bfloat16(v);
    *hi = h;
    *lo = __float2bfloat16(v - __bfloat162float(h));
}

// ---------------- rope table ----------------
__global__ void rope_tab_kernel() {
    int id = blockIdx.x * 256 + threadIdx.x;
    if (id >= T_SEQ * 32) return;
    int t = id >> 5, i = id & 31;
    float f = (float)pow(10000.0, -(double)i / 32.0);
    float ang = (float)t * f;
    g_costab[id] = cosf(ang);
    g_sintab[id] = sinf(ang);
}

// ---------------- per-row features ----------------
__global__ void row_feat_kernel(const float* __restrict__ x,
                                const float* __restrict__ Wcq, const float* __restrict__ qnw,
                                const float* __restrict__ Wckv, const float* __restrict__ kvnw,
                                const float* __restrict__ Wkr, const float* __restrict__ Wimp) {
    int row = blockIdx.x;
    int tid = threadIdx.x; // 256
    int t = row % T_SEQ;
    __shared__ float xs[C_DIM];
    __shared__ float ybuf[192];
    __shared__ float red[256];
    xs[tid] = x[(size_t)row * C_DIM + tid];
    __syncthreads();
    if (tid < 96) {
        float a = 0.f;
        for (int c = 0; c < C_DIM; ++c) a += xs[c] * Wcq[c * 96 + tid];
        ybuf[tid] = a;
    } else if (tid < 128) {
        int j = tid - 96; float a = 0.f;
        for (int c = 0; c < C_DIM; ++c) a += xs[c] * Wckv[c * 32 + j];
        ybuf[96 + j] = a;
    } else if (tid < 192) {
        int j = tid - 128; float a = 0.f;
        for (int c = 0; c < C_DIM; ++c) a += xs[c] * Wkr[c * 64 + j];
        ybuf[128 + j] = a * (1.f / (float)H_NUM);
    } else if (tid == 192) {
        float a = 0.f;
        for (int c = 0; c < C_DIM; ++c) a += xs[c] * Wimp[c];
        g_imp[row] = a;
    }
    __syncthreads();
    red[tid] = (tid < 96) ? ybuf[tid] * ybuf[tid] : 0.f;
    __syncthreads();
    for (int s = 128; s > 0; s >>= 1) { if (tid < s) red[tid] += red[tid + s]; __syncthreads(); }
    float rms_cq = rsqrtf(red[0] / 96.f + EPSF);
    __syncthreads();
    red[tid] = (tid < 32) ? ybuf[96 + tid] * ybuf[96 + tid] : 0.f;
    __syncthreads();
    for (int s = 128; s > 0; s >>= 1) { if (tid < s) red[tid] += red[tid + s]; __syncthreads(); }
    float rms_kv = rsqrtf(red[0] / 32.f + EPSF);
    if (tid < 96) g_cq[(size_t)row * 96 + tid] = ybuf[tid] * rms_cq * qnw[tid];
    if (tid < 32) g_ckv[(size_t)row * 32 + tid] = ybuf[96 + tid] * rms_kv * kvnw[tid];
    if (tid < 32) {
        float xr = ybuf[128 + tid], xi = ybuf[160 + tid];
        float co = g_costab[t * 32 + tid], si = g_sintab[t * 32 + tid];
        g_kr[(size_t)row * 64 + tid]      = xr * co - xi * si;
        g_kr[(size_t)row * 64 + 32 + tid] = xr * si + xi * co;
    }
}

// ---------------- gate ----------------
__global__ void gate_kernel(const float* __restrict__ x, const float* __restrict__ Wgate, int B) {
    __shared__ float lg[6];
    int tid = threadIdx.x;
    int w = tid >> 5, lane = tid & 31;
    if (w < B * 3) {
        int b = w / 3, j = w % 3;
        float s = 0.f;
        for (int c = lane; c < C_DIM; c += 32) {
            float colsum = 0.f;
            const float* xp = x + (size_t)b * T_SEQ * C_DIM + c;
            for (int t = 0; t < T_SEQ; ++t) colsum += xp[(size_t)t * C_DIM];
            s += (colsum / (float)T_SEQ) * Wgate[c * 3 + j];
        }
        #pragma unroll
        for (int o = 16; o > 0; o >>= 1) s += __shfl_xor_sync(0xffffffffu, s, o);
        if (lane == 0) lg[w] = s;
    }
    __syncthreads();
    if (tid < B) {
        float a = lg[tid * 3], b2 = lg[tid * 3 + 1], c2 = lg[tid * 3 + 2];
        float mx = fmaxf(a, fmaxf(b2, c2));
        float ea = expf(a - mx), eb = expf(b2 - mx), ec = expf(c2 - mx);
        float s = ea + eb + ec;
        g_gate[tid * 3 + 0] = ea / s;
        g_gate[tid * 3 + 1] = eb / s;
        g_gate[tid * 3 + 2] = ec / s;
    }
}

// ---------------- q / k1 / v1 projection ----------------
__global__ void qkv_kernel(const float* __restrict__ Wqn, const float* __restrict__ Wqr,
                           const float* __restrict__ Wkn, const float* __restrict__ Wv) {
    const int RT = 8;
    int row0 = blockIdx.x * RT;
    int tid = threadIdx.x; // 256
    __shared__ float cqs[RT][96];
    __shared__ float ckvs[RT][32];
    __shared__ float krs[RT][64];
    for (int i = tid; i < RT * 96; i += 256) cqs[i / 96][i % 96] = g_cq[(size_t)(row0 + i / 96) * 96 + (i % 96)];
    for (int i = tid; i < RT * 32; i += 256) ckvs[i / 32][i % 32] = g_ckv[(size_t)(row0 + i / 32) * 32 + (i % 32)];
    for (int i = tid; i < RT * 64; i += 256) krs[i / 64][i % 64] = g_kr[(size_t)(row0 + i / 64) * 64 + (i % 64)];
    __syncthreads();
    for (int o = tid; o < 512; o += 256) {
        int h = o >> 5, d = o & 31;
        float acc[RT];
        #pragma unroll
        for (int r = 0; r < RT; ++r) acc[r] = 0.f;
        for (int c = 0; c < 96; ++c) {
            float w = Wqn[c * 512 + o];
            #pragma unroll
            for (int r = 0; r < RT; ++r) acc[r] += cqs[r][c] * w;
        }
        #pragma unroll
        for (int r = 0; r < RT; ++r) {
            int row = row0 + r; int b = row / T_SEQ, t = row % T_SEQ;
            g_q[((size_t)(b * H_NUM + h) * T_SEQ + t) * HD + d] = acc[r];
        }
    }
    for (int p = tid; p < 512; p += 256) {
        int h = p >> 5, i = p & 31;
        float ar[RT], ai[RT];
        #pragma unroll
        for (int r = 0; r < RT; ++r) { ar[r] = 0.f; ai[r] = 0.f; }
        for (int c = 0; c < 96; ++c) {
            float wr = Wqr[c * 1024 + h * 64 + i];
            float wi = Wqr[c * 1024 + h * 64 + 32 + i];
            #pragma unroll
            for (int r = 0; r < RT; ++r) { ar[r] += cqs[r][c] * wr; ai[r] += cqs[r][c] * wi; }
        }
        #pragma unroll
        for (int r = 0; r < RT; ++r) {
            int row = row0 + r; int b = row / T_SEQ, t = row % T_SEQ;
            float co = g_costab[t * 32 + i], si = g_sintab[t * 32 + i];
            size_t base = ((size_t)(b * H_NUM + h) * T_SEQ + t) * HD;
            g_q[base + 32 + i] = ar[r] * co - ai[r] * si;
            g_q[base + 64 + i] = ar[r] * si + ai[r] * co;
        }
    }
    for (int o = tid; o < 512; o += 256) {
        int h = o >> 5, d = o & 31;
        float acc[RT];
        #pragma unroll
        for (int r = 0; r < RT; ++r) acc[r] = 0.f;
        for (int c = 0; c < 32; ++c) {
            float w = Wkn[c * 512 + o];
            #pragma unroll
            for (int r = 0; r < RT; ++r) acc[r] += ckvs[r][c] * w;
        }
        #pragma unroll
        for (int r = 0; r < RT; ++r) {
            int row = row0 + r; int b = row / T_SEQ, t = row % T_SEQ;
            size_t o2 = ((size_t)(b * H_NUM + h) * T_SEQ + t) * HD + d;
            split_store(acc[r], &g_k1hi[o2], &g_k1lo[o2]);
        }
    }
    for (int o = tid; o < 512; o += 256) {
        int h = o >> 5, d = o & 31;
        float acc[RT];
        #pragma unroll
        for (int r = 0; r < RT; ++r) acc[r] = 0.f;
        for (int c = 0; c < 32; ++c) {
            float w = Wv[c * 512 + o];
            #pragma unroll
            for (int r = 0; r < RT; ++r) acc[r] += ckvs[r][c] * w;
        }
        #pragma unroll
        for (int r = 0; r < RT; ++r) {
            int row = row0 + r; int b = row / T_SEQ, t = row % T_SEQ;
            g_v1[((size_t)(b * H_NUM + h) * T_SEQ + t) * VD + d] = acc[r];
        }
    }
    for (int i = tid; i < RT * H_NUM * 64; i += 256) {
        int r = i / (H_NUM * 64); int rem = i % (H_NUM * 64); int h = rem / 64; int d = rem % 64;
        int row = row0 + r; int b = row / T_SEQ, t = row % T_SEQ;
        size_t o2 = ((size_t)(b * H_NUM + h) * T_SEQ + t) * HD + 32 + d;
        split_store(krs[r][d], &g_k1hi[o2], &g_k1lo[o2]);
    }
}

// ---------------- top-k ----------------
__global__ void topk_kernel() {
    __shared__ float v[T_SEQ];
    __shared__ int   ix[T_SEQ];
    int b = blockIdx.x, tid = threadIdx.x; // 1024
    for (int i = tid; i < T_SEQ; i += 1024) { v[i] = g_imp[b * T_SEQ + i]; ix[i] = i; }
    __syncthreads();
    for (int k = 2; k <= T_SEQ; k <<= 1)
        for (int j = k >> 1; j > 0; j >>= 1) {
            for (int i = tid; i < T_SEQ; i += 1024) {
                int p = i ^ j;
                if (p > i) {
                    bool up = ((i & k) == 0);
                    bool sw = up ? (v[i] < v[p]) : (v[i] > v[p]);
                    if (sw) {
                        float tv = v[i]; v[i] = v[p]; v[p] = tv;
                        int ti = ix[i]; ix[i] = ix[p]; ix[p] = ti;
                    }
                }
            }
            __syncthreads();
        }
    for (int k = 2; k <= KEEP; k <<= 1)
        for (int j = k >> 1; j > 0; j >>= 1) {
            if (tid < KEEP) {
                int i = tid, p = i ^ j;
                if (p > i) {
                    bool up = ((i & k) == 0);
                    bool sw = up ? (ix[i] > ix[p]) : (ix[i] < ix[p]);
                    if (sw) { int ti = ix[i]; ix[i] = ix[p]; ix[p] = ti; }
                }
            }
            __syncthreads();
        }
    for (int i = tid; i < KEEP; i += 1024) g_idx[b * KEEP + i] = ix[i];
}

// ---------------- sel / window K,V projection ----------------
template <bool SEL>
__global__ void kvproj_kernel(const float* __restrict__ x,
                              const float* __restrict__ Wk, const float* __restrict__ Wv) {
    const int RT = 16;
    const int Tk = SEL ? KEEP : T_SEQ;
    int row0 = blockIdx.x * RT;
    int tid = threadIdx.x; // 256
    __shared__ float xs[RT][C_DIM];
    for (int r = 0; r < RT; ++r) {
        int row = row0 + r; int b = row / Tk; int s = row % Tk;
        int src = SEL ? (b * T_SEQ + g_idx[b * KEEP + s]) : (b * T_SEQ + s);
        xs[r][tid] = x[(size_t)src * C_DIM + tid];
    }
    __syncthreads();
    __nv_bfloat16* Khi = SEL ? g_kshi : g_kwhi;
    __nv_bfloat16* Klo = SEL ? g_kslo : g_kwlo;
    float* Vo = SEL ? g_vs : g_vw;
    for (int o = tid; o < 512; o += 256) {
        int h = o >> 5, d = o & 31; int col = h * HD + d;
        float acc[RT];
        #pragma unroll
        for (int r = 0; r < RT; ++r) acc[r] = 0.f;
        for (int c = 0; c < C_DIM; ++c) {
            float w = Wk[c * (H_NUM * HD) + col];
            #pragma unroll
            for (int r = 0; r < RT; ++r) acc[r] += xs[r][c] * w;
        }
        #pragma unroll
        for (int r = 0; r < RT; ++r) {
            int row = row0 + r; int b = row / Tk; int s = row % Tk;
            size_t o2 = ((size_t)(b * H_NUM + h) * Tk + s) * HD + d;
            split_store(acc[r], &Khi[o2], &Klo[o2]);
        }
    }
    for (int p = tid; p < 512; p += 256) {
        int h = p >> 5, i = p & 31;
        float ar[RT], ai[RT];
        #pragma unroll
        for (int r = 0; r < RT; ++r) { ar[r] = 0.f; ai[r] = 0.f; }
        for (int c = 0; c < C_DIM; ++c) {
            float wr = Wk[c * (H_NUM * HD) + h * HD + 32 + i];
            float wi = Wk[c * (H_NUM * HD) + h * HD + 64 + i];
            #pragma unroll
            for (int r = 0; r < RT; ++r) { ar[r] += xs[r][c] * wr; ai[r] += xs[r][c] * wi; }
        }
        #pragma unroll
        for (int r = 0; r < RT; ++r) {
            int row = row0 + r; int b = row / Tk; int s = row % Tk;
            float co = g_costab[s * 32 + i], si = g_sintab[s * 32 + i];
            size_t base = ((size_t)(b * H_NUM + h) * Tk + s) * HD;
            split_store(ar[r] * co - ai[r] * si, &Khi[base + 32 + i], &Klo[base + 32 + i]);
            split_store(ar[r] * si + ai[r] * co, &Khi[base + 64 + i], &Klo[base + 64 + i]);
        }
    }
    for (int o = tid; o < 512; o += 256) {
        int h = o >> 5, d = o & 31;
        float acc[RT];
        #pragma unroll
        for (int r = 0; r < RT; ++r) acc[r] = 0.f;
        for (int c = 0; c < C_DIM; ++c) {
            float w = Wv[c * 512 + o];
            #pragma unroll
            for (int r = 0; r < RT; ++r) acc[r] += xs[r][c] * w;
        }
        #pragma unroll
        for (int r = 0; r < RT; ++r) {
            int row = row0 + r; int b = row / Tk; int s = row % Tk;
            Vo[((size_t)(b * H_NUM + h) * Tk + s) * VD + d] = acc[r];
        }
    }
}

// ---------------- flash-attention v2 (QK: bf16 hi/lo 3-term m16n8k16; PV: tf32) ----------------
#define AQB 64
#define AKB 64
#define KROW_U32 52         /* padded K row stride: 104 bf16 = 52 u32 (conflict-free) */
#define KROW_U4  13
#define LDV 40
#define LDP 68
#define FA_SMEM (2 * (AKB * KROW_U4 * 16) + AKB * LDV * 4 + 4 * 16 * LDP * 4)

template <int MODE, bool ACCUM>
__global__ void __launch_bounds__(128) attn_fa(int branch) {
    extern __shared__ char smc[];
    uint4* Khi4 = (uint4*)smc;                       // AKB x 13 uint4
    uint4* Klo4 = Khi4 + AKB * KROW_U4;
    float* Vs   = (float*)(Klo4 + AKB * KROW_U4);    // AKB x LDV
    float* Pb   = Vs + AKB * LDV;                    // 4 warps x 16 x LDP
    const uint32_t* KhiW = (const uint32_t*)Khi4;
    const uint32_t* KloW = (const uint32_t*)Klo4;

    const int Tk = (MODE == 1) ? KEEP : T_SEQ;
    int b = blockIdx.z, h = blockIdx.y;
    int qt0 = blockIdx.x * AQB;
    int tid = threadIdx.x;
    int w = tid >> 5, lane = tid & 31;
    int g = lane >> 2, tg = lane & 3;
    int r0 = w * 16;
    float* Pw = Pb + w * 16 * LDP;

    const __nv_bfloat16* KHI = (MODE == 1) ? g_kshi : (MODE == 2) ? g_kwhi : g_k1hi;
    const __nv_bfloat16* KLO = (MODE == 1) ? g_kslo : (MODE == 2) ? g_kwlo : g_k1lo;
    const float* V = (MODE == 1) ? g_vs : (MODE == 2) ? g_vw : g_v1;
    const __nv_bfloat16* KbaseH = KHI + (size_t)(b * H_NUM + h) * Tk * HD;
    const __nv_bfloat16* KbaseL = KLO + (size_t)(b * H_NUM + h) * Tk * HD;
    const float* Vbase = V + (size_t)(b * H_NUM + h) * Tk * VD;
    const float* Qbase = g_q + ((size_t)(b * H_NUM + h) * T_SEQ + qt0) * HD;
    const float scale = 0.10206207262f; // 1/sqrt(96)

    // Q in registers: bf16 hi/lo A-fragments (scale folded)
    uint32_t qhi[6][4], qlo[6][4];
    #pragma unroll
    for (int kc = 0; kc < 6; ++kc) {
        #pragma unroll
        for (int e = 0; e < 4; ++e) {
            int row = r0 + g + (e & 1) * 8;
            int col = kc * 16 + 2 * tg + (e & 2) * 4;
            float2 qv = *(const float2*)(Qbase + (size_t)row * HD + col);
            qv.x *= scale; qv.y *= scale;
            __nv_bfloat16 hx = __float2bfloat16(qv.x);
            __nv_bfloat16 hy = __float2bfloat16(qv.y);
            qhi[kc][e] = ((uint32_t)__bfloat16_as_ushort(hy) << 16) | __bfloat16_as_ushort(hx);
            __nv_bfloat16 lx = __float2bfloat16(qv.x - __bfloat162float(hx));
            __nv_bfloat16 ly = __float2bfloat16(qv.y - __bfloat162float(hy));
            qlo[kc][e] = ((uint32_t)__bfloat16_as_ushort(ly) << 16) | __bfloat16_as_ushort(lx);
        }
    }

    float oacc[4][4];
    #pragma unroll
    for (int nt = 0; nt < 4; ++nt)
        #pragma unroll
        for (int e = 0; e < 4; ++e) oacc[nt][e] = 0.f;
    float m0 = -1e30f, m1 = -1e30f, l0 = 0.f, l1 = 0.f;

    int kend = (MODE == 1) ? Tk : (qt0 + AQB);
    int k0 = 0;
    if (MODE == 2) { int a0 = qt0 - (WIN - 1); k0 = (a0 > 0) ? (a0 & ~(AKB - 1)) : 0; }

    for (int kt = k0; kt < kend; kt += AKB) {
        __syncthreads();
        // K tiles: pure uint4 copies of precomputed bf16 hi/lo
        const uint4* KsrcH = (const uint4*)(KbaseH + (size_t)kt * HD);
        const uint4* KsrcL = (const uint4*)(KbaseL + (size_t)kt * HD);
        #pragma unroll
        for (int it = 0; it < 6; ++it) {
            int i = tid + it * 128;
            int r = i / 12, c = i % 12;
            Khi4[r * KROW_U4 + c] = KsrcH[i];
            Klo4[r * KROW_U4 + c] = KsrcL[i];
        }
        const float4* Vsrc = (const float4*)(Vbase + (size_t)kt * VD);
        #pragma unroll
        for (int it = 0; it < 4; ++it) {
            int i = tid + it * 128;
            int r = i / 8, c = i % 8;
            float4 v = Vsrc[i];
            v.x = tf32v(v.x); v.y = tf32v(v.y); v.z = tf32v(v.z); v.w = tf32v(v.w);
            ((float4*)Vs)[r * 10 + c] = v;
        }
        __syncthreads();

        // S = Q K^T (bf16 3-term)
        float sacc[8][4];
        #pragma unroll
        for (int nt = 0; nt < 8; ++nt)
            #pragma unroll
            for (int e = 0; e < 4; ++e) sacc[nt][e] = 0.f;
        #pragma unroll
        for (int nt = 0; nt < 8; ++nt) {
            int key = nt * 8 + g;
            #pragma unroll
            for (int kc = 0; kc < 6; ++kc) {
                const uint32_t* kh = KhiW + key * KROW_U32 + kc * 8 + tg;
                const uint32_t* kl = KloW + key * KROW_U32 + kc * 8 + tg;
                uint32_t bh0 = kh[0], bh1 = kh[4];
                uint32_t bl0 = kl[0], bl1 = kl[4];
                mma16bf(sacc[nt], qhi[kc], bh0, bh1);
                mma16bf(sacc[nt], qhi[kc], bl0, bl1);
                mma16bf(sacc[nt], qlo[kc], bh0, bh1);
            }
        }

        // mask
        bool need_mask = (MODE == 2) || (MODE == 0 && kt + AKB > qt0);
        if (need_mask) {
            #pragma unroll
            for (int nt = 0; nt < 8; ++nt) {
                #pragma unroll
                for (int e = 0; e < 4; ++e) {
                    int key = kt + nt * 8 + 2 * tg + (e & 1);
                    int row = qt0 + r0 + g + ((e & 2) ? 8 : 0);
                    bool ok = key <= row;
                    if (MODE == 2) ok = ok && (row - key < WIN);
                    if (!ok) sacc[nt][e] = -1e30f;
                }
            }
        }

        // online softmax
        float mx0 = -1e30f, mx1 = -1e30f;
        #pragma unroll
        for (int nt = 0; nt < 8; ++nt) {
            mx0 = fmaxf(mx0, fmaxf(sacc[nt][0], sacc[nt][1]));
            mx1 = fmaxf(mx1, fmaxf(sacc[nt][2], sacc[nt][3]));
        }
        mx0 = fmaxf(mx0, __shfl_xor_sync(0xffffffffu, mx0, 1));
        mx0 = fmaxf(mx0, __shfl_xor_sync(0xffffffffu, mx0, 2));
        mx1 = fmaxf(mx1, __shfl_xor_sync(0xffffffffu, mx1, 1));
        mx1 = fmaxf(mx1, __shfl_xor_sync(0xffffffffu, mx1, 2));
        float m0n = fmaxf(m0, mx0), m1n = fmaxf(m1, mx1);
        float c0 = __expf(m0 - m0n), c1 = __expf(m1 - m1n);
        float s0 = 0.f, s1 = 0.f;
        #pragma unroll
        for (int nt = 0; nt < 8; ++nt) {
            #pragma unroll
            for (int e = 0; e < 4; ++e) {
                float sv = sacc[nt][e];
                float p = __expf(sv - ((e & 2) ? m1n : m0n));
                p = (sv > -1e29f) ? p : 0.f;
                if (e & 2) s1 += p; else s0 += p;
                Pw[(g + ((e & 2) ? 8 : 0)) * LDP + nt * 8 + 2 * tg + (e & 1)] =
                    __uint_as_float(f2tf32(p));
            }
        }
        s0 += __shfl_xor_sync(0xffffffffu, s0, 1);
        s0 += __shfl_xor_sync(0xffffffffu, s0, 2);
        s1 += __shfl_xor_sync(0xffffffffu, s1, 1);
        s1 += __shfl_xor_sync(0xffffffffu, s1, 2);
        l0 = l0 * c0 + s0; l1 = l1 * c1 + s1;
        m0 = m0n; m1 = m1n;
        #pragma unroll
        for (int nt = 0; nt < 4; ++nt) {
            oacc[nt][0] *= c0; oacc[nt][1] *= c0;
            oacc[nt][2] *= c1; oacc[nt][3] *= c1;
        }
        __syncwarp();

        // O += P V (tf32)
        #pragma unroll
        for (int kc2 = 0; kc2 < 8; ++kc2) {
            uint32_t pa[4];
            #pragma unroll
            for (int e = 0; e < 4; ++e)
                pa[e] = __float_as_uint(Pw[(g + (e & 1) * 8) * LDP + kc2 * 8 + tg + (e & 2) * 2]);
            #pragma unroll
            for (int nt = 0; nt < 4; ++nt) {
                uint32_t b0 = __float_as_uint(Vs[(kc2 * 8 + tg) * LDV + nt * 8 + g]);
                uint32_t b1 = __float_as_uint(Vs[(kc2 * 8 + tg + 4) * LDV + nt * 8 + g]);
                mma8(oacc[nt], pa, b0, b1);
            }
        }
    }

    // epilogue
    float gte = g_gate[b * 3 + branch];
    float inv0 = gte / l0, inv1 = gte / l1;
    #pragma unroll
    for (int nt = 0; nt < 4; ++nt) {
        #pragma unroll
        for (int e = 0; e < 4; ++e) {
            int row = qt0 + r0 + g + ((e & 2) ? 8 : 0);
            int col = nt * 8 + 2 * tg + (e & 1);
            float v = oacc[nt][e] * ((e & 2) ? inv1 : inv0);
            float* op = &g_O[((size_t)(b * T_SEQ + row) * H_NUM + h) * VD + col];
            if (ACCUM) v += *op;
            *op = v;
        }
    }
}

// ---------------- final projection ----------------
__global__ void proj_kernel(const float* __restrict__ Wproj, float* __restrict__ out) {
    const int RT = 16;
    int row0 = blockIdx.x * RT;
    int tid = threadIdx.x; // 256
    __shared__ float Os[RT][512];
    for (int i = tid; i < RT * 512; i += 256) Os[i >> 9][i & 511] = g_O[((size_t)row0 << 9) + i];
    __syncthreads();
    float acc[RT];
    #pragma unroll
    for (int r = 0; r < RT; ++r) acc[r] = 0.f;
    for (int c = 0; c < 512; ++c) {
        float w = Wproj[c * 256 + tid];
        #pragma unroll
        for (int r = 0; r < RT; ++r) acc[r] += Os[r][c] * w;
    }
    #pragma unroll
    for (int r = 0; r < RT; ++r) out[(size_t)(row0 + r) * 256 + tid] = acc[r];
}

// ---------------- launch ----------------
extern "C" void kernel_launch(void* const* d_in, const int* in_sizes, int n_in,
                              void* d_out, int out_size) {
    const float* x     = (const float*)d_in[0];
    const float* Wcq   = (const float*)d_in[1];
    const float* qnw   = (const float*)d_in[2];
    const float* Wqn   = (const float*)d_in[3];
    const float* Wqr   = (const float*)d_in[4];
    const float* Wckv  = (const float*)d_in[5];
    const float* kvnw  = (const float*)d_in[6];
    const float* Wkn   = (const float*)d_in[7];
    const float* Wv    = (const float*)d_in[8];
    const float* Wkr   = (const float*)d_in[9];
    const float* Wimp  = (const float*)d_in[10];
    const float* Wselk = (const float*)d_in[11];
    const float* Wselv = (const float*)d_in[12];
    const float* Wwink = (const float*)d_in[13];
    const float* Wwinv = (const float*)d_in[14];
    const float* Wgate = (const float*)d_in[15];
    const float* Wproj = (const float*)d_in[16];
    float* out = (float*)d_out;
    int B = in_sizes[0] / (T_SEQ * C_DIM);
    if (B < 1) B = 1; if (B > BMAX) B = BMAX;

    cudaFuncSetAttribute(attn_fa<0, false>, cudaFuncAttributeMaxDynamicSharedMemorySize, FA_SMEM);
    cudaFuncSetAttribute(attn_fa<1, true >, cudaFuncAttributeMaxDynamicSharedMemorySize, FA_SMEM);
    cudaFuncSetAttribute(attn_fa<2, true >, cudaFuncAttributeMaxDynamicSharedMemorySize, FA_SMEM);

    rope_tab_kernel<<<(T_SEQ * 32 + 255) / 256, 256>>>();
    row_feat_kernel<<<B * T_SEQ, 256>>>(x, Wcq, qnw, Wckv, kvnw, Wkr, Wimp);
    gate_kernel<<<1, 192>>>(x, Wgate, B);
    qkv_kernel<<<B * T_SEQ / 8, 256>>>(Wqn, Wqr, Wkn, Wv);
    topk_kernel<<<B, 1024>>>();
    kvproj_kernel<true><<<B * KEEP / 16, 256>>>(x, Wselk, Wselv);
    kvproj_kernel<false><<<B * T_SEQ / 16, 256>>>(x, Wwink, Wwinv);

    dim3 agrid(T_SEQ / AQB, H_NUM, B);
    attn_fa<0, false><<<agrid, 128, FA_SMEM>>>(0);
    attn_fa<1, true ><<<agrid, 128, FA_SMEM>>>(1);
    attn_fa<2, true ><<<agrid, 128, FA_SMEM>>>(2);

    proj_kernel<<<B * T_SEQ / 16, 256>>>(Wproj, out);
}

// round 5
// speedup vs baseline: 1.4190x; 1.0362x over previous
#include <cuda_runtime.h>
#include <cuda_bf16.h>
#include <cuda_fp16.h>
#include <math.h>
#include <stdint.h>

#define T_SEQ 2048
#define C_DIM 256
#define H_NUM 16
#define NOPE 32
#define ROPE 64
#define HD 96
#define VD 32
#define KEEP 512
#define WIN 128
#define BMAX 2
#define EPSF 1e-6f

// ---------------- device scratch ----------------
__device__ float g_costab[T_SEQ * 32];
__device__ float g_sintab[T_SEQ * 32];
__device__ float g_cq[BMAX * T_SEQ * 96];
__device__ float g_ckv[BMAX * T_SEQ * 32];
__device__ float g_kr[BMAX * T_SEQ * 64];
__device__ float g_imp[BMAX * T_SEQ];
__device__ int   g_idx[BMAX * KEEP];
__device__ float g_gate[BMAX * 3];
__device__ float g_q [BMAX * H_NUM * T_SEQ * HD];
// K tensors stored as bf16 hi/lo split (written directly by projection kernels)
__device__ __nv_bfloat16 g_k1hi[BMAX * H_NUM * T_SEQ * HD];
__device__ __nv_bfloat16 g_k1lo[BMAX * H_NUM * T_SEQ * HD];
__device__ __nv_bfloat16 g_kshi[BMAX * H_NUM * KEEP * HD];
__device__ __nv_bfloat16 g_kslo[BMAX * H_NUM * KEEP * HD];
__device__ __nv_bfloat16 g_kwhi[BMAX * H_NUM * T_SEQ * HD];
__device__ __nv_bfloat16 g_kwlo[BMAX * H_NUM * T_SEQ * HD];
__device__ float g_v1[BMAX * H_NUM * T_SEQ * VD];
__device__ float g_vs[BMAX * H_NUM * KEEP * VD];
__device__ float g_vw[BMAX * H_NUM * T_SEQ * VD];
__device__ float g_O [BMAX * T_SEQ * H_NUM * VD];

__device__ __forceinline__ void mma16bf(float* c, const uint32_t* a, uint32_t b0, uint32_t b1) {
    asm volatile("mma.sync.aligned.m16n8k16.row.col.f32.bf16.bf16.f32 "
        "{%0,%1,%2,%3}, {%4,%5,%6,%7}, {%8,%9}, {%0,%1,%2,%3};"
        : "+f"(c[0]), "+f"(c[1]), "+f"(c[2]), "+f"(c[3])
        : "r"(a[0]), "r"(a[1]), "r"(a[2]), "r"(a[3]), "r"(b0), "r"(b1));
}
__device__ __forceinline__ void mma16h(float* c, const uint32_t* a, uint32_t b0, uint32_t b1) {
    asm volatile("mma.sync.aligned.m16n8k16.row.col.f32.f16.f16.f32 "
        "{%0,%1,%2,%3}, {%4,%5,%6,%7}, {%8,%9}, {%0,%1,%2,%3};"
        : "+f"(c[0]), "+f"(c[1]), "+f"(c[2]), "+f"(c[3])
        : "r"(a[0]), "r"(a[1]), "r"(a[2]), "r"(a[3]), "r"(b0), "r"(b1));
}

__device__ __forceinline__ void split_store(float v, __nv_bfloat16* hi, __nv_bfloat16* lo) {
    __nv_bfloat16 h = __float2bfloat16(v);
    *hi = h;
    *lo = __float2bfloat16(v - __bfloat162float(h));
}

// ---------------- rope table ----------------
__global__ void rope_tab_kernel() {
    int id = blockIdx.x * 256 + threadIdx.x;
    if (id >= T_SEQ * 32) return;
    int t = id >> 5, i = id & 31;
    float f = (float)pow(10000.0, -(double)i / 32.0);
    float ang = (float)t * f;
    g_costab[id] = cosf(ang);
    g_sintab[id] = sinf(ang);
}

// ---------------- per-row features ----------------
__global__ void row_feat_kernel(const float* __restrict__ x,
                                const float* __restrict__ Wcq, const float* __restrict__ qnw,
                                const float* __restrict__ Wckv, const float* __restrict__ kvnw,
                                const float* __restrict__ Wkr, const float* __restrict__ Wimp) {
    int row = blockIdx.x;
    int tid = threadIdx.x; // 256
    int t = row % T_SEQ;
    __shared__ float xs[C_DIM];
    __shared__ float ybuf[192];
    __shared__ float red[256];
    xs[tid] = x[(size_t)row * C_DIM + tid];
    __syncthreads();
    if (tid < 96) {
        float a = 0.f;
        for (int c = 0; c < C_DIM; ++c) a += xs[c] * Wcq[c * 96 + tid];
        ybuf[tid] = a;
    } else if (tid < 128) {
        int j = tid - 96; float a = 0.f;
        for (int c = 0; c < C_DIM; ++c) a += xs[c] * Wckv[c * 32 + j];
        ybuf[96 + j] = a;
    } else if (tid < 192) {
        int j = tid - 128; float a = 0.f;
        for (int c = 0; c < C_DIM; ++c) a += xs[c] * Wkr[c * 64 + j];
        ybuf[128 + j] = a * (1.f / (float)H_NUM);
    } else if (tid == 192) {
        float a = 0.f;
        for (int c = 0; c < C_DIM; ++c) a += xs[c] * Wimp[c];
        g_imp[row] = a;
    }
    __syncthreads();
    red[tid] = (tid < 96) ? ybuf[tid] * ybuf[tid] : 0.f;
    __syncthreads();
    for (int s = 128; s > 0; s >>= 1) { if (tid < s) red[tid] += red[tid + s]; __syncthreads(); }
    float rms_cq = rsqrtf(red[0] / 96.f + EPSF);
    __syncthreads();
    red[tid] = (tid < 32) ? ybuf[96 + tid] * ybuf[96 + tid] : 0.f;
    __syncthreads();
    for (int s = 128; s > 0; s >>= 1) { if (tid < s) red[tid] += red[tid + s]; __syncthreads(); }
    float rms_kv = rsqrtf(red[0] / 32.f + EPSF);
    if (tid < 96) g_cq[(size_t)row * 96 + tid] = ybuf[tid] * rms_cq * qnw[tid];
    if (tid < 32) g_ckv[(size_t)row * 32 + tid] = ybuf[96 + tid] * rms_kv * kvnw[tid];
    if (tid < 32) {
        float xr = ybuf[128 + tid], xi = ybuf[160 + tid];
        float co = g_costab[t * 32 + tid], si = g_sintab[t * 32 + tid];
        g_kr[(size_t)row * 64 + tid]      = xr * co - xi * si;
        g_kr[(size_t)row * 64 + 32 + tid] = xr * si + xi * co;
    }
}

// ---------------- gate ----------------
__global__ void gate_kernel(const float* __restrict__ x, const float* __restrict__ Wgate, int B) {
    __shared__ float lg[6];
    int tid = threadIdx.x;
    int w = tid >> 5, lane = tid & 31;
    if (w < B * 3) {
        int b = w / 3, j = w % 3;
        float s = 0.f;
        for (int c = lane; c < C_DIM; c += 32) {
            float colsum = 0.f;
            const float* xp = x + (size_t)b * T_SEQ * C_DIM + c;
            for (int t = 0; t < T_SEQ; ++t) colsum += xp[(size_t)t * C_DIM];
            s += (colsum / (float)T_SEQ) * Wgate[c * 3 + j];
        }
        #pragma unroll
        for (int o = 16; o > 0; o >>= 1) s += __shfl_xor_sync(0xffffffffu, s, o);
        if (lane == 0) lg[w] = s;
    }
    __syncthreads();
    if (tid < B) {
        float a = lg[tid * 3], b2 = lg[tid * 3 + 1], c2 = lg[tid * 3 + 2];
        float mx = fmaxf(a, fmaxf(b2, c2));
        float ea = expf(a - mx), eb = expf(b2 - mx), ec = expf(c2 - mx);
        float s = ea + eb + ec;
        g_gate[tid * 3 + 0] = ea / s;
        g_gate[tid * 3 + 1] = eb / s;
        g_gate[tid * 3 + 2] = ec / s;
    }
}

// ---------------- q / k1 / v1 projection ----------------
__global__ void qkv_kernel(const float* __restrict__ Wqn, const float* __restrict__ Wqr,
                           const float* __restrict__ Wkn, const float* __restrict__ Wv) {
    const int RT = 8;
    int row0 = blockIdx.x * RT;
    int tid = threadIdx.x; // 256
    __shared__ float cqs[RT][96];
    __shared__ float ckvs[RT][32];
    __shared__ float krs[RT][64];
    for (int i = tid; i < RT * 96; i += 256) cqs[i / 96][i % 96] = g_cq[(size_t)(row0 + i / 96) * 96 + (i % 96)];
    for (int i = tid; i < RT * 32; i += 256) ckvs[i / 32][i % 32] = g_ckv[(size_t)(row0 + i / 32) * 32 + (i % 32)];
    for (int i = tid; i < RT * 64; i += 256) krs[i / 64][i % 64] = g_kr[(size_t)(row0 + i / 64) * 64 + (i % 64)];
    __syncthreads();
    for (int o = tid; o < 512; o += 256) {
        int h = o >> 5, d = o & 31;
        float acc[RT];
        #pragma unroll
        for (int r = 0; r < RT; ++r) acc[r] = 0.f;
        for (int c = 0; c < 96; ++c) {
            float w = Wqn[c * 512 + o];
            #pragma unroll
            for (int r = 0; r < RT; ++r) acc[r] += cqs[r][c] * w;
        }
        #pragma unroll
        for (int r = 0; r < RT; ++r) {
            int row = row0 + r; int b = row / T_SEQ, t = row % T_SEQ;
            g_q[((size_t)(b * H_NUM + h) * T_SEQ + t) * HD + d] = acc[r];
        }
    }
    for (int p = tid; p < 512; p += 256) {
        int h = p >> 5, i = p & 31;
        float ar[RT], ai[RT];
        #pragma unroll
        for (int r = 0; r < RT; ++r) { ar[r] = 0.f; ai[r] = 0.f; }
        for (int c = 0; c < 96; ++c) {
            float wr = Wqr[c * 1024 + h * 64 + i];
            float wi = Wqr[c * 1024 + h * 64 + 32 + i];
            #pragma unroll
            for (int r = 0; r < RT; ++r) { ar[r] += cqs[r][c] * wr; ai[r] += cqs[r][c] * wi; }
        }
        #pragma unroll
        for (int r = 0; r < RT; ++r) {
            int row = row0 + r; int b = row / T_SEQ, t = row % T_SEQ;
            float co = g_costab[t * 32 + i], si = g_sintab[t * 32 + i];
            size_t base = ((size_t)(b * H_NUM + h) * T_SEQ + t) * HD;
            g_q[base + 32 + i] = ar[r] * co - ai[r] * si;
            g_q[base + 64 + i] = ar[r] * si + ai[r] * co;
        }
    }
    for (int o = tid; o < 512; o += 256) {
        int h = o >> 5, d = o & 31;
        float acc[RT];
        #pragma unroll
        for (int r = 0; r < RT; ++r) acc[r] = 0.f;
        for (int c = 0; c < 32; ++c) {
            float w = Wkn[c * 512 + o];
            #pragma unroll
            for (int r = 0; r < RT; ++r) acc[r] += ckvs[r][c] * w;
        }
        #pragma unroll
        for (int r = 0; r < RT; ++r) {
            int row = row0 + r; int b = row / T_SEQ, t = row % T_SEQ;
            size_t o2 = ((size_t)(b * H_NUM + h) * T_SEQ + t) * HD + d;
            split_store(acc[r], &g_k1hi[o2], &g_k1lo[o2]);
        }
    }
    for (int o = tid; o < 512; o += 256) {
        int h = o >> 5, d = o & 31;
        float acc[RT];
        #pragma unroll
        for (int r = 0; r < RT; ++r) acc[r] = 0.f;
        for (int c = 0; c < 32; ++c) {
            float w = Wv[c * 512 + o];
            #pragma unroll
            for (int r = 0; r < RT; ++r) acc[r] += ckvs[r][c] * w;
        }
        #pragma unroll
        for (int r = 0; r < RT; ++r) {
            int row = row0 + r; int b = row / T_SEQ, t = row % T_SEQ;
            g_v1[((size_t)(b * H_NUM + h) * T_SEQ + t) * VD + d] = acc[r];
        }
    }
    for (int i = tid; i < RT * H_NUM * 64; i += 256) {
        int r = i / (H_NUM * 64); int rem = i % (H_NUM * 64); int h = rem / 64; int d = rem % 64;
        int row = row0 + r; int b = row / T_SEQ, t = row % T_SEQ;
        size_t o2 = ((size_t)(b * H_NUM + h) * T_SEQ + t) * HD + 32 + d;
        split_store(krs[r][d], &g_k1hi[o2], &g_k1lo[o2]);
    }
}

// ---------------- top-k ----------------
__global__ void topk_kernel() {
    __shared__ float v[T_SEQ];
    __shared__ int   ix[T_SEQ];
    int b = blockIdx.x, tid = threadIdx.x; // 1024
    for (int i = tid; i < T_SEQ; i += 1024) { v[i] = g_imp[b * T_SEQ + i]; ix[i] = i; }
    __syncthreads();
    for (int k = 2; k <= T_SEQ; k <<= 1)
        for (int j = k >> 1; j > 0; j >>= 1) {
            for (int i = tid; i < T_SEQ; i += 1024) {
                int p = i ^ j;
                if (p > i) {
                    bool up = ((i & k) == 0);
                    bool sw = up ? (v[i] < v[p]) : (v[i] > v[p]);
                    if (sw) {
                        float tv = v[i]; v[i] = v[p]; v[p] = tv;
                        int ti = ix[i]; ix[i] = ix[p]; ix[p] = ti;
                    }
                }
            }
            __syncthreads();
        }
    for (int k = 2; k <= KEEP; k <<= 1)
        for (int j = k >> 1; j > 0; j >>= 1) {
            if (tid < KEEP) {
                int i = tid, p = i ^ j;
                if (p > i) {
                    bool up = ((i & k) == 0);
                    bool sw = up ? (ix[i] > ix[p]) : (ix[i] < ix[p]);
                    if (sw) { int ti = ix[i]; ix[i] = ix[p]; ix[p] = ti; }
                }
            }
            __syncthreads();
        }
    for (int i = tid; i < KEEP; i += 1024) g_idx[b * KEEP + i] = ix[i];
}

// ---------------- sel / window K,V projection ----------------
template <bool SEL>
__global__ void kvproj_kernel(const float* __restrict__ x,
                              const float* __restrict__ Wk, const float* __restrict__ Wv) {
    const int RT = 16;
    const int Tk = SEL ? KEEP : T_SEQ;
    int row0 = blockIdx.x * RT;
    int tid = threadIdx.x; // 256
    __shared__ float xs[RT][C_DIM];
    for (int r = 0; r < RT; ++r) {
        int row = row0 + r; int b = row / Tk; int s = row % Tk;
        int src = SEL ? (b * T_SEQ + g_idx[b * KEEP + s]) : (b * T_SEQ + s);
        xs[r][tid] = x[(size_t)src * C_DIM + tid];
    }
    __syncthreads();
    __nv_bfloat16* Khi = SEL ? g_kshi : g_kwhi;
    __nv_bfloat16* Klo = SEL ? g_kslo : g_kwlo;
    float* Vo = SEL ? g_vs : g_vw;
    for (int o = tid; o < 512; o += 256) {
        int h = o >> 5, d = o & 31; int col = h * HD + d;
        float acc[RT];
        #pragma unroll
        for (int r = 0; r < RT; ++r) acc[r] = 0.f;
        for (int c = 0; c < C_DIM; ++c) {
            float w = Wk[c * (H_NUM * HD) + col];
            #pragma unroll
            for (int r = 0; r < RT; ++r) acc[r] += xs[r][c] * w;
        }
        #pragma unroll
        for (int r = 0; r < RT; ++r) {
            int row = row0 + r; int b = row / Tk; int s = row % Tk;
            size_t o2 = ((size_t)(b * H_NUM + h) * Tk + s) * HD + d;
            split_store(acc[r], &Khi[o2], &Klo[o2]);
        }
    }
    for (int p = tid; p < 512; p += 256) {
        int h = p >> 5, i = p & 31;
        float ar[RT], ai[RT];
        #pragma unroll
        for (int r = 0; r < RT; ++r) { ar[r] = 0.f; ai[r] = 0.f; }
        for (int c = 0; c < C_DIM; ++c) {
            float wr = Wk[c * (H_NUM * HD) + h * HD + 32 + i];
            float wi = Wk[c * (H_NUM * HD) + h * HD + 64 + i];
            #pragma unroll
            for (int r = 0; r < RT; ++r) { ar[r] += xs[r][c] * wr; ai[r] += xs[r][c] * wi; }
        }
        #pragma unroll
        for (int r = 0; r < RT; ++r) {
            int row = row0 + r; int b = row / Tk; int s = row % Tk;
            float co = g_costab[s * 32 + i], si = g_sintab[s * 32 + i];
            size_t base = ((size_t)(b * H_NUM + h) * Tk + s) * HD;
            split_store(ar[r] * co - ai[r] * si, &Khi[base + 32 + i], &Klo[base + 32 + i]);
            split_store(ar[r] * si + ai[r] * co, &Khi[base + 64 + i], &Klo[base + 64 + i]);
        }
    }
    for (int o = tid; o < 512; o += 256) {
        int h = o >> 5, d = o & 31;
        float acc[RT];
        #pragma unroll
        for (int r = 0; r < RT; ++r) acc[r] = 0.f;
        for (int c = 0; c < C_DIM; ++c) {
            float w = Wv[c * 512 + o];
            #pragma unroll
            for (int r = 0; r < RT; ++r) acc[r] += xs[r][c] * w;
        }
        #pragma unroll
        for (int r = 0; r < RT; ++r) {
            int row = row0 + r; int b = row / Tk; int s = row % Tk;
            Vo[((size_t)(b * H_NUM + h) * Tk + s) * VD + d] = acc[r];
        }
    }
}

// ---------------- flash attention: no-max softmax, fp16x2 exp, register P, fp16 PV ----------------
// S computed in log2 domain (log2e folded into Q scale). l accumulated by tensor core
// via a ones-column appended to V (n-tile 4, col 32).
#define AQB 64
#define AKB 64
#define KROW_U32 52         /* padded K row stride: 104 bf16 = 52 u32 (conflict-free) */
#define KROW_U4  13
#define LDVP 42             /* packed V stride in u32 (pair-rows x 40 cols used) */
#define FA_SMEM (2 * (AKB * KROW_U4 * 16) + 32 * LDVP * 4)

template <int MODE, bool ACCUM>
__global__ void __launch_bounds__(128) attn_fa(int branch) {
    extern __shared__ char smc[];
    uint4* Khi4 = (uint4*)smc;                       // AKB x 13 uint4
    uint4* Klo4 = Khi4 + AKB * KROW_U4;
    uint32_t* Vp = (uint32_t*)(Klo4 + AKB * KROW_U4); // 32 pair-rows x LDVP (cols 0..39 used)
    const uint32_t* KhiW = (const uint32_t*)Khi4;
    const uint32_t* KloW = (const uint32_t*)Klo4;

    const int Tk = (MODE == 1) ? KEEP : T_SEQ;
    int b = blockIdx.z, h = blockIdx.y;
    int qt0 = blockIdx.x * AQB;
    int tid = threadIdx.x;
    int w = tid >> 5, lane = tid & 31;
    int g = lane >> 2, tg = lane & 3;
    int r0 = w * 16;

    const __nv_bfloat16* KHI = (MODE == 1) ? g_kshi : (MODE == 2) ? g_kwhi : g_k1hi;
    const __nv_bfloat16* KLO = (MODE == 1) ? g_kslo : (MODE == 2) ? g_kwlo : g_k1lo;
    const float* V = (MODE == 1) ? g_vs : (MODE == 2) ? g_vw : g_v1;
    const __nv_bfloat16* KbaseH = KHI + (size_t)(b * H_NUM + h) * Tk * HD;
    const __nv_bfloat16* KbaseL = KLO + (size_t)(b * H_NUM + h) * Tk * HD;
    const float* Vbase = V + (size_t)(b * H_NUM + h) * Tk * VD;
    const float* Qbase = g_q + ((size_t)(b * H_NUM + h) * T_SEQ + qt0) * HD;
    const float qscale = 0.14724444f; // log2(e)/sqrt(96): S in log2 domain

    // ones/zeros pad columns of packed V (cols 32..39), written once
    for (int i = tid; i < 32 * 8; i += 128) {
        int pr = i >> 3, c = 32 + (i & 7);
        Vp[pr * LDVP + c] = (c == 32) ? 0x3C003C00u : 0u; // {1,1} fp16 : {0,0}
    }

    // Q in registers: bf16 hi/lo A-fragments (scale folded)
    uint32_t qhi[6][4], qlo[6][4];
    #pragma unroll
    for (int kc = 0; kc < 6; ++kc) {
        #pragma unroll
        for (int e = 0; e < 4; ++e) {
            int row = r0 + g + (e & 1) * 8;
            int col = kc * 16 + 2 * tg + (e & 2) * 4;
            float2 qv = *(const float2*)(Qbase + (size_t)row * HD + col);
            qv.x *= qscale; qv.y *= qscale;
            __nv_bfloat16 hx = __float2bfloat16(qv.x);
            __nv_bfloat16 hy = __float2bfloat16(qv.y);
            qhi[kc][e] = ((uint32_t)__bfloat16_as_ushort(hy) << 16) | __bfloat16_as_ushort(hx);
            __nv_bfloat16 lx = __float2bfloat16(qv.x - __bfloat162float(hx));
            __nv_bfloat16 ly = __float2bfloat16(qv.y - __bfloat162float(hy));
            qlo[kc][e] = ((uint32_t)__bfloat16_as_ushort(ly) << 16) | __bfloat16_as_ushort(lx);
        }
    }

    float oacc[5][4];
    #pragma unroll
    for (int nt = 0; nt < 5; ++nt)
        #pragma unroll
        for (int e = 0; e < 4; ++e) oacc[nt][e] = 0.f;

    int kend = (MODE == 1) ? Tk : (qt0 + AQB);
    int k0 = 0;
    if (MODE == 2) { int a0 = qt0 - (WIN - 1); k0 = (a0 > 0) ? (a0 & ~(AKB - 1)) : 0; }

    for (int kt = k0; kt < kend; kt += AKB) {
        __syncthreads();
        // K tiles: uint4 copies of precomputed bf16 hi/lo
        const uint4* KsrcH = (const uint4*)(KbaseH + (size_t)kt * HD);
        const uint4* KsrcL = (const uint4*)(KbaseL + (size_t)kt * HD);
        #pragma unroll
        for (int it = 0; it < 6; ++it) {
            int i = tid + it * 128;
            int r = i / 12, c = i % 12;
            Khi4[r * KROW_U4 + c] = KsrcH[i];
            Klo4[r * KROW_U4 + c] = KsrcL[i];
        }
        // V tile: fp32 -> fp16 pair-row packed layout (+ones col untouched)
        const float4* Vsrc = (const float4*)(Vbase + (size_t)kt * VD);
        #pragma unroll
        for (int it = 0; it < 2; ++it) {
            int pc = tid + it * 128;         // pair-chunk: 32 pair-rows x 8 float4-chunks
            int pr = pc >> 3, cc = pc & 7;
            float4 f0 = Vsrc[(2 * pr) * 8 + cc];
            float4 f1 = Vsrc[(2 * pr + 1) * 8 + cc];
            uint32_t* dst = Vp + pr * LDVP + cc * 4;
            __half2 p0 = __floats2half2_rn(f0.x, f1.x);
            __half2 p1 = __floats2half2_rn(f0.y, f1.y);
            __half2 p2 = __floats2half2_rn(f0.z, f1.z);
            __half2 p3 = __floats2half2_rn(f0.w, f1.w);
            dst[0] = *(uint32_t*)&p0; dst[1] = *(uint32_t*)&p1;
            dst[2] = *(uint32_t*)&p2; dst[3] = *(uint32_t*)&p3;
        }
        __syncthreads();

        // S = Q K^T (bf16 3-term), log2 domain
        float sacc[8][4];
        #pragma unroll
        for (int nt = 0; nt < 8; ++nt)
            #pragma unroll
            for (int e = 0; e < 4; ++e) sacc[nt][e] = 0.f;
        #pragma unroll
        for (int nt = 0; nt < 8; ++nt) {
            int key = nt * 8 + g;
            #pragma unroll
            for (int kc = 0; kc < 6; ++kc) {
                const uint32_t* kh = KhiW + key * KROW_U32 + kc * 8 + tg;
                const uint32_t* kl = KloW + key * KROW_U32 + kc * 8 + tg;
                uint32_t bh0 = kh[0], bh1 = kh[4];
                uint32_t bl0 = kl[0], bl1 = kl[4];
                mma16bf(sacc[nt], qhi[kc], bh0, bh1);
                mma16bf(sacc[nt], qhi[kc], bl0, bl1);
                mma16bf(sacc[nt], qlo[kc], bh0, bh1);
            }
        }

        // mask (diagonal / window tiles only)
        bool need_mask = (MODE == 2) || (MODE == 0 && kt + AKB > qt0);
        if (need_mask) {
            #pragma unroll
            for (int nt = 0; nt < 8; ++nt) {
                #pragma unroll
                for (int e = 0; e < 4; ++e) {
                    int key = kt + nt * 8 + 2 * tg + (e & 1);
                    int row = qt0 + r0 + g + ((e & 2) ? 8 : 0);
                    bool ok = key <= row;
                    if (MODE == 2) ok = ok && (row - key < WIN);
                    if (!ok) sacc[nt][e] = -1e30f;
                }
            }
        }

        // P = 2^S via fp16x2 MUFU; halves are directly the fp16 A-fragment regs
        uint32_t ph2[8][2];
        #pragma unroll
        for (int nt = 0; nt < 8; ++nt) {
            __half2 e0 = h2exp2(__floats2half2_rn(sacc[nt][0], sacc[nt][1]));
            __half2 e1 = h2exp2(__floats2half2_rn(sacc[nt][2], sacc[nt][3]));
            ph2[nt][0] = *(uint32_t*)&e0;
            ph2[nt][1] = *(uint32_t*)&e1;
        }

        // O += P V (fp16); n-tile 4 accumulates l via ones column
        #pragma unroll
        for (int kc2 = 0; kc2 < 4; ++kc2) {
            uint32_t pa[4] = { ph2[2 * kc2][0], ph2[2 * kc2][1],
                               ph2[2 * kc2 + 1][0], ph2[2 * kc2 + 1][1] };
            #pragma unroll
            for (int nt2 = 0; nt2 < 5; ++nt2) {
                uint32_t b0 = Vp[(kc2 * 8 + tg) * LDVP + nt2 * 8 + g];
                uint32_t b1 = Vp[(kc2 * 8 + tg + 4) * LDVP + nt2 * 8 + g];
                mma16h(oacc[nt2], pa, b0, b1);
            }
        }
    }

    // epilogue: l sits in oacc[4] col 32 (threads with tg==0); broadcast within group
    float l0 = __shfl_sync(0xffffffffu, oacc[4][0], lane & 28);
    float l1 = __shfl_sync(0xffffffffu, oacc[4][2], lane & 28);
    float gte = g_gate[b * 3 + branch];
    float inv0 = gte / l0, inv1 = gte / l1;
    #pragma unroll
    for (int nt = 0; nt < 4; ++nt) {
        #pragma unroll
        for (int e = 0; e < 4; ++e) {
            int row = qt0 + r0 + g + ((e & 2) ? 8 : 0);
            int col = nt * 8 + 2 * tg + (e & 1);
            float v = oacc[nt][e] * ((e & 2) ? inv1 : inv0);
            float* op = &g_O[((size_t)(b * T_SEQ + row) * H_NUM + h) * VD + col];
            if (ACCUM) v += *op;
            *op = v;
        }
    }
}

// ---------------- final projection ----------------
__global__ void proj_kernel(const float* __restrict__ Wproj, float* __restrict__ out) {
    const int RT = 16;
    int row0 = blockIdx.x * RT;
    int tid = threadIdx.x; // 256
    __shared__ float Os[RT][512];
    for (int i = tid; i < RT * 512; i += 256) Os[i >> 9][i & 511] = g_O[((size_t)row0 << 9) + i];
    __syncthreads();
    float acc[RT];
    #pragma unroll
    for (int r = 0; r < RT; ++r) acc[r] = 0.f;
    for (int c = 0; c < 512; ++c) {
        float w = Wproj[c * 256 + tid];
        #pragma unroll
        for (int r = 0; r < RT; ++r) acc[r] += Os[r][c] * w;
    }
    #pragma unroll
    for (int r = 0; r < RT; ++r) out[(size_t)(row0 + r) * 256 + tid] = acc[r];
}

// ---------------- launch ----------------
extern "C" void kernel_launch(void* const* d_in, const int* in_sizes, int n_in,
                              void* d_out, int out_size) {
    const float* x     = (const float*)d_in[0];
    const float* Wcq   = (const float*)d_in[1];
    const float* qnw   = (const float*)d_in[2];
    const float* Wqn   = (const float*)d_in[3];
    const float* Wqr   = (const float*)d_in[4];
    const float* Wckv  = (const float*)d_in[5];
    const float* kvnw  = (const float*)d_in[6];
    const float* Wkn   = (const float*)d_in[7];
    const float* Wv    = (const float*)d_in[8];
    const float* Wkr   = (const float*)d_in[9];
    const float* Wimp  = (const float*)d_in[10];
    const float* Wselk = (const float*)d_in[11];
    const float* Wselv = (const float*)d_in[12];
    const float* Wwink = (const float*)d_in[13];
    const float* Wwinv = (const float*)d_in[14];
    const float* Wgate = (const float*)d_in[15];
    const float* Wproj = (const float*)d_in[16];
    float* out = (float*)d_out;
    int B = in_sizes[0] / (T_SEQ * C_DIM);
    if (B < 1) B = 1; if (B > BMAX) B = BMAX;

    cudaFuncSetAttribute(attn_fa<0, false>, cudaFuncAttributeMaxDynamicSharedMemorySize, FA_SMEM);
    cudaFuncSetAttribute(attn_fa<1, true >, cudaFuncAttributeMaxDynamicSharedMemorySize, FA_SMEM);
    cudaFuncSetAttribute(attn_fa<2, true >, cudaFuncAttributeMaxDynamicSharedMemorySize, FA_SMEM);

    rope_tab_kernel<<<(T_SEQ * 32 + 255) / 256, 256>>>();
    row_feat_kernel<<<B * T_SEQ, 256>>>(x, Wcq, qnw, Wckv, kvnw, Wkr, Wimp);
    gate_kernel<<<1, 192>>>(x, Wgate, B);
    qkv_kernel<<<B * T_SEQ / 8, 256>>>(Wqn, Wqr, Wkn, Wv);
    topk_kernel<<<B, 1024>>>();
    kvproj_kernel<true><<<B * KEEP / 16, 256>>>(x, Wselk, Wselv);
    kvproj_kernel<false><<<B * T_SEQ / 16, 256>>>(x, Wwink, Wwinv);

    dim3 agrid(T_SEQ / AQB, H_NUM, B);
    attn_fa<0, false><<<agrid, 128, FA_SMEM>>>(0);
    attn_fa<1, true ><<<agrid, 128, FA_SMEM>>>(1);
    attn_fa<2, true ><<<agrid, 128, FA_SMEM>>>(2);

    proj_kernel<<<B * T_SEQ / 16, 256>>>(Wproj, out);
}

// round 7
// speedup vs baseline: 2.3431x; 1.6513x over previous
#include <cuda_runtime.h>
#include <cuda_bf16.h>
#include <cuda_fp16.h>
#include <math.h>
#include <stdint.h>

#define T_SEQ 2048
#define C_DIM 256
#define H_NUM 16
#define NOPE 32
#define ROPE 64
#define HD 96
#define VD 32
#define KEEP 512
#define WIN 128
#define BMAX 2
#define EPSF 1e-6f

// ---------------- device scratch ----------------
__device__ float g_costab[T_SEQ * 32];
__device__ float g_sintab[T_SEQ * 32];
__device__ float g_cq[BMAX * T_SEQ * 96];
__device__ float g_ckv[BMAX * T_SEQ * 32];
__device__ float g_kr[BMAX * T_SEQ * 64];
__device__ float g_imp[BMAX * T_SEQ];
__device__ int   g_idx[BMAX * KEEP];
__device__ float g_xpart[BMAX * 16 * C_DIM];
__device__ float g_gate[BMAX * 3];
__device__ float g_q [BMAX * H_NUM * T_SEQ * HD];
__device__ __nv_bfloat16 g_k1hi[BMAX * H_NUM * T_SEQ * HD];
__device__ __nv_bfloat16 g_k1lo[BMAX * H_NUM * T_SEQ * HD];
__device__ __nv_bfloat16 g_kshi[BMAX * H_NUM * KEEP * HD];
__device__ __nv_bfloat16 g_kslo[BMAX * H_NUM * KEEP * HD];
__device__ __nv_bfloat16 g_kwhi[BMAX * H_NUM * T_SEQ * HD];
__device__ __nv_bfloat16 g_kwlo[BMAX * H_NUM * T_SEQ * HD];
__device__ float g_v1[BMAX * H_NUM * T_SEQ * VD];
__device__ float g_vs[BMAX * H_NUM * KEEP * VD];
__device__ float g_vw[BMAX * H_NUM * T_SEQ * VD];
__device__ float g_O0[BMAX * T_SEQ * H_NUM * VD];
__device__ float g_O1[BMAX * T_SEQ * H_NUM * VD];
__device__ float g_O2[BMAX * T_SEQ * H_NUM * VD];

__device__ __forceinline__ void mma16bf(float* c, const uint32_t* a, uint32_t b0, uint32_t b1) {
    asm volatile("mma.sync.aligned.m16n8k16.row.col.f32.bf16.bf16.f32 "
        "{%0,%1,%2,%3}, {%4,%5,%6,%7}, {%8,%9}, {%0,%1,%2,%3};"
        : "+f"(c[0]), "+f"(c[1]), "+f"(c[2]), "+f"(c[3])
        : "r"(a[0]), "r"(a[1]), "r"(a[2]), "r"(a[3]), "r"(b0), "r"(b1));
}
__device__ __forceinline__ void mma16h(float* c, const uint32_t* a, uint32_t b0, uint32_t b1) {
    asm volatile("mma.sync.aligned.m16n8k16.row.col.f32.f16.f16.f32 "
        "{%0,%1,%2,%3}, {%4,%5,%6,%7}, {%8,%9}, {%0,%1,%2,%3};"
        : "+f"(c[0]), "+f"(c[1]), "+f"(c[2]), "+f"(c[3])
        : "r"(a[0]), "r"(a[1]), "r"(a[2]), "r"(a[3]), "r"(b0), "r"(b1));
}
__device__ __forceinline__ void split_store(float v, __nv_bfloat16* hi, __nv_bfloat16* lo) {
    __nv_bfloat16 h = __float2bfloat16(v);
    *hi = h;
    *lo = __float2bfloat16(v - __bfloat162float(h));
}

// ---------------- rope table ----------------
__global__ void rope_tab_kernel() {
    int id = blockIdx.x * 256 + threadIdx.x;
    if (id >= T_SEQ * 32) return;
    int t = id >> 5, i = id & 31;
    float f = (float)pow(10000.0, -(double)i / 32.0);
    float ang = (float)t * f;
    g_costab[id] = cosf(ang);
    g_sintab[id] = sinf(ang);
}

// ---------------- per-row features (2 syncs, warp-shfl reductions) ----------------
__global__ void row_feat_kernel(const float* __restrict__ x,
                                const float* __restrict__ Wcq, const float* __restrict__ qnw,
                                const float* __restrict__ Wckv, const float* __restrict__ kvnw,
                                const float* __restrict__ Wkr, const float* __restrict__ Wimp) {
    int row = blockIdx.x;
    int tid = threadIdx.x; // 256
    int lane = tid & 31, w = tid >> 5;
    int t = row % T_SEQ;
    __shared__ float xs[C_DIM];
    __shared__ float krbuf[64];
    __shared__ float red[4];
    xs[tid] = x[(size_t)row * C_DIM + tid];
    __syncthreads();
    float a = 0.f;
    if (tid < 96) {
        for (int c = 0; c < C_DIM; c += 4) {
            float4 xv = *(const float4*)&xs[c];
            a += xv.x * Wcq[c * 96 + tid] + xv.y * Wcq[(c + 1) * 96 + tid]
               + xv.z * Wcq[(c + 2) * 96 + tid] + xv.w * Wcq[(c + 3) * 96 + tid];
        }
    } else if (tid < 128) {
        int j = tid - 96;
        for (int c = 0; c < C_DIM; c += 4) {
            float4 xv = *(const float4*)&xs[c];
            a += xv.x * Wckv[c * 32 + j] + xv.y * Wckv[(c + 1) * 32 + j]
               + xv.z * Wckv[(c + 2) * 32 + j] + xv.w * Wckv[(c + 3) * 32 + j];
        }
    } else if (tid < 192) {
        int j = tid - 128;
        for (int c = 0; c < C_DIM; c += 4) {
            float4 xv = *(const float4*)&xs[c];
            a += xv.x * Wkr[c * 64 + j] + xv.y * Wkr[(c + 1) * 64 + j]
               + xv.z * Wkr[(c + 2) * 64 + j] + xv.w * Wkr[(c + 3) * 64 + j];
        }
        a *= (1.f / (float)H_NUM);
        krbuf[j] = a;
    } else if (tid == 192) {
        for (int c = 0; c < C_DIM; ++c) a += xs[c] * Wimp[c];
        g_imp[row] = a;
    }
    if (w < 4) {
        float sq = a * a;
        #pragma unroll
        for (int o = 16; o > 0; o >>= 1) sq += __shfl_xor_sync(0xffffffffu, sq, o);
        if (lane == 0) red[w] = sq;
    }
    __syncthreads();
    if (tid < 96) {
        float rms_cq = rsqrtf((red[0] + red[1] + red[2]) / 96.f + EPSF);
        g_cq[(size_t)row * 96 + tid] = a * rms_cq * qnw[tid];
    } else if (tid < 128) {
        float rms_kv = rsqrtf(red[3] / 32.f + EPSF);
        g_ckv[(size_t)row * 32 + (tid - 96)] = a * rms_kv * kvnw[tid - 96];
    } else if (tid < 160) {
        int i = tid - 128;
        float xr = krbuf[i], xi = krbuf[32 + i];
        float co = g_costab[t * 32 + i], si = g_sintab[t * 32 + i];
        g_kr[(size_t)row * 64 + i]      = xr * co - xi * si;
        g_kr[(size_t)row * 64 + 32 + i] = xr * si + xi * co;
    }
}

// ---------------- gate: parallel colmean partials + tiny reduce ----------------
__global__ void colmean_part_kernel(const float* __restrict__ x) {
    int blk = blockIdx.x;        // b*16 + chunk
    int b = blk >> 4, chunk = blk & 15;
    int c = threadIdx.x;
    const float* xp = x + ((size_t)b * T_SEQ + chunk * 128) * C_DIM + c;
    float s = 0.f;
    #pragma unroll 4
    for (int t = 0; t < 128; ++t) s += xp[(size_t)t * C_DIM];
    g_xpart[blk * C_DIM + c] = s;
}

__global__ void gate_kernel(const float* __restrict__ Wgate, int B) {
    __shared__ float lg[6];
    int tid = threadIdx.x;
    int w = tid >> 5, lane = tid & 31;
    if (w < B * 3) {
        int b = w / 3, j = w % 3;
        float s = 0.f;
        for (int c = lane; c < C_DIM; c += 32) {
            float m = 0.f;
            #pragma unroll
            for (int p = 0; p < 16; ++p) m += g_xpart[(b * 16 + p) * C_DIM + c];
            s += (m / (float)T_SEQ) * Wgate[c * 3 + j];
        }
        #pragma unroll
        for (int o = 16; o > 0; o >>= 1) s += __shfl_xor_sync(0xffffffffu, s, o);
        if (lane == 0) lg[w] = s;
    }
    __syncthreads();
    if (tid < B) {
        float a = lg[tid * 3], b2 = lg[tid * 3 + 1], c2 = lg[tid * 3 + 2];
        float mx = fmaxf(a, fmaxf(b2, c2));
        float ea = expf(a - mx), eb = expf(b2 - mx), ec = expf(c2 - mx);
        float s = ea + eb + ec;
        g_gate[tid * 3 + 0] = ea / s;
        g_gate[tid * 3 + 1] = eb / s;
        g_gate[tid * 3 + 2] = ec / s;
    }
}

// ---------------- q / k1 / v1 projection (float4 smem operands) ----------------
__global__ void qkv_kernel(const float* __restrict__ Wqn, const float* __restrict__ Wqr,
                           const float* __restrict__ Wkn, const float* __restrict__ Wv) {
    const int RT = 8;
    int row0 = blockIdx.x * RT;
    int tid = threadIdx.x; // 256
    __shared__ float cqs[RT][96];
    __shared__ float ckvs[RT][32];
    __shared__ float krs[RT][64];
    for (int i = tid; i < RT * 96; i += 256) cqs[i / 96][i % 96] = g_cq[(size_t)(row0 + i / 96) * 96 + (i % 96)];
    for (int i = tid; i < RT * 32; i += 256) ckvs[i / 32][i % 32] = g_ckv[(size_t)(row0 + i / 32) * 32 + (i % 32)];
    for (int i = tid; i < RT * 64; i += 256) krs[i / 64][i % 64] = g_kr[(size_t)(row0 + i / 64) * 64 + (i % 64)];
    __syncthreads();
    for (int o = tid; o < 512; o += 256) {
        int h = o >> 5, d = o & 31;
        float acc[RT];
        #pragma unroll
        for (int r = 0; r < RT; ++r) acc[r] = 0.f;
        for (int c = 0; c < 96; c += 4) {
            float w0 = Wqn[c * 512 + o], w1 = Wqn[(c + 1) * 512 + o];
            float w2 = Wqn[(c + 2) * 512 + o], w3 = Wqn[(c + 3) * 512 + o];
            #pragma unroll
            for (int r = 0; r < RT; ++r) {
                float4 q = *(const float4*)&cqs[r][c];
                acc[r] += q.x * w0 + q.y * w1 + q.z * w2 + q.w * w3;
            }
        }
        #pragma unroll
        for (int r = 0; r < RT; ++r) {
            int row = row0 + r; int b = row / T_SEQ, t = row % T_SEQ;
            g_q[((size_t)(b * H_NUM + h) * T_SEQ + t) * HD + d] = acc[r];
        }
    }
    for (int p = tid; p < 512; p += 256) {
        int h = p >> 5, i = p & 31;
        float ar[RT], ai[RT];
        #pragma unroll
        for (int r = 0; r < RT; ++r) { ar[r] = 0.f; ai[r] = 0.f; }
        for (int c = 0; c < 96; c += 2) {
            float wr0 = Wqr[c * 1024 + h * 64 + i];
            float wi0 = Wqr[c * 1024 + h * 64 + 32 + i];
            float wr1 = Wqr[(c + 1) * 1024 + h * 64 + i];
            float wi1 = Wqr[(c + 1) * 1024 + h * 64 + 32 + i];
            #pragma unroll
            for (int r = 0; r < RT; ++r) {
                float2 q = *(const float2*)&cqs[r][c];
                ar[r] += q.x * wr0 + q.y * wr1;
                ai[r] += q.x * wi0 + q.y * wi1;
            }
        }
        #pragma unroll
        for (int r = 0; r < RT; ++r) {
            int row = row0 + r; int b = row / T_SEQ, t = row % T_SEQ;
            float co = g_costab[t * 32 + i], si = g_sintab[t * 32 + i];
            size_t base = ((size_t)(b * H_NUM + h) * T_SEQ + t) * HD;
            g_q[base + 32 + i] = ar[r] * co - ai[r] * si;
            g_q[base + 64 + i] = ar[r] * si + ai[r] * co;
        }
    }
    for (int o = tid; o < 512; o += 256) {
        int h = o >> 5, d = o & 31;
        float acc[RT], accv[RT];
        #pragma unroll
        for (int r = 0; r < RT; ++r) { acc[r] = 0.f; accv[r] = 0.f; }
        for (int c = 0; c < 32; c += 4) {
            float k0 = Wkn[c * 512 + o], k1 = Wkn[(c + 1) * 512 + o];
            float k2 = Wkn[(c + 2) * 512 + o], k3 = Wkn[(c + 3) * 512 + o];
            float v0 = Wv[c * 512 + o], v1 = Wv[(c + 1) * 512 + o];
            float v2 = Wv[(c + 2) * 512 + o], v3 = Wv[(c + 3) * 512 + o];
            #pragma unroll
            for (int r = 0; r < RT; ++r) {
                float4 q = *(const float4*)&ckvs[r][c];
                acc[r]  += q.x * k0 + q.y * k1 + q.z * k2 + q.w * k3;
                accv[r] += q.x * v0 + q.y * v1 + q.z * v2 + q.w * v3;
            }
        }
        #pragma unroll
        for (int r = 0; r < RT; ++r) {
            int row = row0 + r; int b = row / T_SEQ, t = row % T_SEQ;
            size_t o2 = ((size_t)(b * H_NUM + h) * T_SEQ + t) * HD + d;
            split_store(acc[r], &g_k1hi[o2], &g_k1lo[o2]);
            g_v1[((size_t)(b * H_NUM + h) * T_SEQ + t) * VD + d] = accv[r];
        }
    }
    for (int i = tid; i < RT * H_NUM * 64; i += 256) {
        int r = i / (H_NUM * 64); int rem = i % (H_NUM * 64); int h = rem / 64; int d = rem % 64;
        int row = row0 + r; int b = row / T_SEQ, t = row % T_SEQ;
        size_t o2 = ((size_t)(b * H_NUM + h) * T_SEQ + t) * HD + 32 + d;
        split_store(krs[r][d], &g_k1hi[o2], &g_k1lo[o2]);
    }
}

// ---------------- top-k ----------------
__global__ void topk_kernel() {
    __shared__ float v[T_SEQ];
    __shared__ int   ix[T_SEQ];
    int b = blockIdx.x, tid = threadIdx.x; // 1024
    for (int i = tid; i < T_SEQ; i += 1024) { v[i] = g_imp[b * T_SEQ + i]; ix[i] = i; }
    __syncthreads();
    for (int k = 2; k <= T_SEQ; k <<= 1)
        for (int j = k >> 1; j > 0; j >>= 1) {
            for (int i = tid; i < T_SEQ; i += 1024) {
                int p = i ^ j;
                if (p > i) {
                    bool up = ((i & k) == 0);
                    bool sw = up ? (v[i] < v[p]) : (v[i] > v[p]);
                    if (sw) {
                        float tv = v[i]; v[i] = v[p]; v[p] = tv;
                        int ti = ix[i]; ix[i] = ix[p]; ix[p] = ti;
                    }
                }
            }
            __syncthreads();
        }
    for (int k = 2; k <= KEEP; k <<= 1)
        for (int j = k >> 1; j > 0; j >>= 1) {
            if (tid < KEEP) {
                int i = tid, p = i ^ j;
                if (p > i) {
                    bool up = ((i & k) == 0);
                    bool sw = up ? (ix[i] > ix[p]) : (ix[i] < ix[p]);
                    if (sw) { int ti = ix[i]; ix[i] = ix[p]; ix[p] = ti; }
                }
            }
            __syncthreads();
        }
    for (int i = tid; i < KEEP; i += 1024) g_idx[b * KEEP + i] = ix[i];
}

// ---------------- sel / window K,V projection (float4 smem operands) ----------------
template <bool SEL>
__global__ void kvproj_kernel(const float* __restrict__ x,
                              const float* __restrict__ Wk, const float* __restrict__ Wv) {
    const int RT = 16;
    const int Tk = SEL ? KEEP : T_SEQ;
    int row0 = blockIdx.x * RT;
    int tid = threadIdx.x; // 256
    __shared__ float xs[RT][C_DIM];
    for (int r = 0; r < RT; ++r) {
        int row = row0 + r; int b = row / Tk; int s = row % Tk;
        int src = SEL ? (b * T_SEQ + g_idx[b * KEEP + s]) : (b * T_SEQ + s);
        xs[r][tid] = x[(size_t)src * C_DIM + tid];
    }
    __syncthreads();
    __nv_bfloat16* Khi = SEL ? g_kshi : g_kwhi;
    __nv_bfloat16* Klo = SEL ? g_kslo : g_kwlo;
    float* Vo = SEL ? g_vs : g_vw;
    for (int o = tid; o < 512; o += 256) {
        int h = o >> 5, d = o & 31; int col = h * HD + d;
        float acc[RT];
        #pragma unroll
        for (int r = 0; r < RT; ++r) acc[r] = 0.f;
        for (int c = 0; c < C_DIM; c += 4) {
            float w0 = Wk[c * 1536 + col], w1 = Wk[(c + 1) * 1536 + col];
            float w2 = Wk[(c + 2) * 1536 + col], w3 = Wk[(c + 3) * 1536 + col];
            #pragma unroll
            for (int r = 0; r < RT; ++r) {
                float4 q = *(const float4*)&xs[r][c];
                acc[r] += q.x * w0 + q.y * w1 + q.z * w2 + q.w * w3;
            }
        }
        #pragma unroll
        for (int r = 0; r < RT; ++r) {
            int row = row0 + r; int b = row / Tk; int s = row % Tk;
            size_t o2 = ((size_t)(b * H_NUM + h) * Tk + s) * HD + d;
            split_store(acc[r], &Khi[o2], &Klo[o2]);
        }
    }
    for (int p = tid; p < 512; p += 256) {
        int h = p >> 5, i = p & 31;
        float ar[RT], ai[RT];
        #pragma unroll
        for (int r = 0; r < RT; ++r) { ar[r] = 0.f; ai[r] = 0.f; }
        for (int c = 0; c < C_DIM; c += 2) {
            float wr0 = Wk[c * 1536 + h * HD + 32 + i];
            float wi0 = Wk[c * 1536 + h * HD + 64 + i];
            float wr1 = Wk[(c + 1) * 1536 + h * HD + 32 + i];
            float wi1 = Wk[(c + 1) * 1536 + h * HD + 64 + i];
            #pragma unroll
            for (int r = 0; r < RT; ++r) {
                float2 q = *(const float2*)&xs[r][c];
                ar[r] += q.x * wr0 + q.y * wr1;
                ai[r] += q.x * wi0 + q.y * wi1;
            }
        }
        #pragma unroll
        for (int r = 0; r < RT; ++r) {
            int row = row0 + r; int b = row / Tk; int s = row % Tk;
            float co = g_costab[s * 32 + i], si = g_sintab[s * 32 + i];
            size_t base = ((size_t)(b * H_NUM + h) * Tk + s) * HD;
            split_store(ar[r] * co - ai[r] * si, &Khi[base + 32 + i], &Klo[base + 32 + i]);
            split_store(ar[r] * si + ai[r] * co, &Khi[base + 64 + i], &Klo[base + 64 + i]);
        }
    }
    for (int o = tid; o < 512; o += 256) {
        int h = o >> 5, d = o & 31;
        float acc[RT];
        #pragma unroll
        for (int r = 0; r < RT; ++r) acc[r] = 0.f;
        for (int c = 0; c < C_DIM; c += 4) {
            float w0 = Wv[c * 512 + o], w1 = Wv[(c + 1) * 512 + o];
            float w2 = Wv[(c + 2) * 512 + o], w3 = Wv[(c + 3) * 512 + o];
            #pragma unroll
            for (int r = 0; r < RT; ++r) {
                float4 q = *(const float4*)&xs[r][c];
                acc[r] += q.x * w0 + q.y * w1 + q.z * w2 + q.w * w3;
            }
        }
        #pragma unroll
        for (int r = 0; r < RT; ++r) {
            int row = row0 + r; int b = row / Tk; int s = row % Tk;
            Vo[((size_t)(b * H_NUM + h) * Tk + s) * VD + d] = acc[r];
        }
    }
}

// ---------------- fused flash attention: all 3 branches in ONE launch ----------------
// grid.x = 96: mode = blockIdx.x/32, q-tile = blockIdx.x%32.
#define AQB 64
#define AKB 64
#define KROW_U32 52
#define KROW_U4  13
#define LDVP 42
#define FA_SMEM (2 * (AKB * KROW_U4 * 16) + 32 * LDVP * 4)

__global__ void __launch_bounds__(128) attn_all() {
    extern __shared__ char smc[];
    uint4* Khi4 = (uint4*)smc;
    uint4* Klo4 = Khi4 + AKB * KROW_U4;
    uint32_t* Vp = (uint32_t*)(Klo4 + AKB * KROW_U4);
    const uint32_t* KhiW = (const uint32_t*)Khi4;
    const uint32_t* KloW = (const uint32_t*)Klo4;

    int mode = blockIdx.x >> 5;
    int qt0 = (blockIdx.x & 31) * AQB;
    const int Tk = (mode == 1) ? KEEP : T_SEQ;
    int b = blockIdx.z, h = blockIdx.y;
    int tid = threadIdx.x;
    int w = tid >> 5, lane = tid & 31;
    int g = lane >> 2, tg = lane & 3;
    int r0 = w * 16;

    const __nv_bfloat16* KHI = (mode == 1) ? g_kshi : (mode == 2) ? g_kwhi : g_k1hi;
    const __nv_bfloat16* KLO = (mode == 1) ? g_kslo : (mode == 2) ? g_kwlo : g_k1lo;
    const float* V = (mode == 1) ? g_vs : (mode == 2) ? g_vw : g_v1;
    float* Oout = (mode == 1) ? g_O1 : (mode == 2) ? g_O2 : g_O0;
    const __nv_bfloat16* KbaseH = KHI + (size_t)(b * H_NUM + h) * Tk * HD;
    const __nv_bfloat16* KbaseL = KLO + (size_t)(b * H_NUM + h) * Tk * HD;
    const float* Vbase = V + (size_t)(b * H_NUM + h) * Tk * VD;
    const float* Qbase = g_q + ((size_t)(b * H_NUM + h) * T_SEQ + qt0) * HD;
    const float qscale = 0.14724444f; // log2(e)/sqrt(96)

    for (int i = tid; i < 32 * 8; i += 128) {
        int pr = i >> 3, c = 32 + (i & 7);
        Vp[pr * LDVP + c] = (c == 32) ? 0x3C003C00u : 0u;
    }

    uint32_t qhi[6][4], qlo[6][4];
    #pragma unroll
    for (int kc = 0; kc < 6; ++kc) {
        #pragma unroll
        for (int e = 0; e < 4; ++e) {
            int row = r0 + g + (e & 1) * 8;
            int col = kc * 16 + 2 * tg + (e & 2) * 4;
            float2 qv = *(const float2*)(Qbase + (size_t)row * HD + col);
            qv.x *= qscale; qv.y *= qscale;
            __nv_bfloat16 hx = __float2bfloat16(qv.x);
            __nv_bfloat16 hy = __float2bfloat16(qv.y);
            qhi[kc][e] = ((uint32_t)__bfloat16_as_ushort(hy) << 16) | __bfloat16_as_ushort(hx);
            __nv_bfloat16 lx = __float2bfloat16(qv.x - __bfloat162float(hx));
            __nv_bfloat16 ly = __float2bfloat16(qv.y - __bfloat162float(hy));
            qlo[kc][e] = ((uint32_t)__bfloat16_as_ushort(ly) << 16) | __bfloat16_as_ushort(lx);
        }
    }

    float oacc[5][4];
    #pragma unroll
    for (int nt = 0; nt < 5; ++nt)
        #pragma unroll
        for (int e = 0; e < 4; ++e) oacc[nt][e] = 0.f;

    int kend = (mode == 1) ? KEEP : (qt0 + AQB);
    int k0 = 0;
    if (mode == 2) { int a0 = qt0 - (WIN - 1); k0 = (a0 > 0) ? (a0 & ~(AKB - 1)) : 0; }

    for (int kt = k0; kt < kend; kt += AKB) {
        __syncthreads();
        const uint4* KsrcH = (const uint4*)(KbaseH + (size_t)kt * HD);
        const uint4* KsrcL = (const uint4*)(KbaseL + (size_t)kt * HD);
        #pragma unroll
        for (int it = 0; it < 6; ++it) {
            int i = tid + it * 128;
            int r = i / 12, c = i % 12;
            Khi4[r * KROW_U4 + c] = KsrcH[i];
            Klo4[r * KROW_U4 + c] = KsrcL[i];
        }
        const float4* Vsrc = (const float4*)(Vbase + (size_t)kt * VD);
        #pragma unroll
        for (int it = 0; it < 2; ++it) {
            int pc = tid + it * 128;
            int pr = pc >> 3, cc = pc & 7;
            float4 f0 = Vsrc[(2 * pr) * 8 + cc];
            float4 f1 = Vsrc[(2 * pr + 1) * 8 + cc];
            uint32_t* dst = Vp + pr * LDVP + cc * 4;
            __half2 p0 = __floats2half2_rn(f0.x, f1.x);
            __half2 p1 = __floats2half2_rn(f0.y, f1.y);
            __half2 p2 = __floats2half2_rn(f0.z, f1.z);
            __half2 p3 = __floats2half2_rn(f0.w, f1.w);
            dst[0] = *(uint32_t*)&p0; dst[1] = *(uint32_t*)&p1;
            dst[2] = *(uint32_t*)&p2; dst[3] = *(uint32_t*)&p3;
        }
        __syncthreads();

        float sacc[8][4];
        #pragma unroll
        for (int nt = 0; nt < 8; ++nt)
            #pragma unroll
            for (int e = 0; e < 4; ++e) sacc[nt][e] = 0.f;
        #pragma unroll
        for (int nt = 0; nt < 8; ++nt) {
            int key = nt * 8 + g;
            #pragma unroll
            for (int kc = 0; kc < 6; ++kc) {
                const uint32_t* kh = KhiW + key * KROW_U32 + kc * 8 + tg;
                const uint32_t* kl = KloW + key * KROW_U32 + kc * 8 + tg;
                uint32_t bh0 = kh[0], bh1 = kh[4];
                uint32_t bl0 = kl[0], bl1 = kl[4];
                mma16bf(sacc[nt], qhi[kc], bh0, bh1);
                mma16bf(sacc[nt], qhi[kc], bl0, bl1);
                mma16bf(sacc[nt], qlo[kc], bh0, bh1);
            }
        }

        bool need_mask = (mode == 2) || (mode == 0 && kt + AKB > qt0);
        if (need_mask) {
            #pragma unroll
            for (int nt = 0; nt < 8; ++nt) {
                #pragma unroll
                for (int e = 0; e < 4; ++e) {
                    int key = kt + nt * 8 + 2 * tg + (e & 1);
                    int row = qt0 + r0 + g + ((e & 2) ? 8 : 0);
                    bool ok = key <= row;
                    if (mode == 2) ok = ok && (row - key < WIN);
                    if (!ok) sacc[nt][e] = -1e30f;
                }
            }
        }

        uint32_t ph2[8][2];
        #pragma unroll
        for (int nt = 0; nt < 8; ++nt) {
            __half2 e0 = h2exp2(__floats2half2_rn(sacc[nt][0], sacc[nt][1]));
            __half2 e1 = h2exp2(__floats2half2_rn(sacc[nt][2], sacc[nt][3]));
            ph2[nt][0] = *(uint32_t*)&e0;
            ph2[nt][1] = *(uint32_t*)&e1;
        }

        #pragma unroll
        for (int kc2 = 0; kc2 < 4; ++kc2) {
            uint32_t pa[4] = { ph2[2 * kc2][0], ph2[2 * kc2][1],
                               ph2[2 * kc2 + 1][0], ph2[2 * kc2 + 1][1] };
            #pragma unroll
            for (int nt2 = 0; nt2 < 5; ++nt2) {
                uint32_t b0 = Vp[(kc2 * 8 + tg) * LDVP + nt2 * 8 + g];
                uint32_t b1 = Vp[(kc2 * 8 + tg + 4) * LDVP + nt2 * 8 + g];
                mma16h(oacc[nt2], pa, b0, b1);
            }
        }
    }

    float l0 = __shfl_sync(0xffffffffu, oacc[4][0], lane & 28);
    float l1 = __shfl_sync(0xffffffffu, oacc[4][2], lane & 28);
    float gte = g_gate[b * 3 + mode];
    float inv0 = gte / l0, inv1 = gte / l1;
    #pragma unroll
    for (int nt = 0; nt < 4; ++nt) {
        #pragma unroll
        for (int e = 0; e < 4; ++e) {
            int row = qt0 + r0 + g + ((e & 2) ? 8 : 0);
            int col = nt * 8 + 2 * tg + (e & 1);
            Oout[((size_t)(b * T_SEQ + row) * H_NUM + h) * VD + col] =
                oacc[nt][e] * ((e & 2) ? inv1 : inv0);
        }
    }
}

// ---------------- final projection (sums 3 branch buffers) ----------------
__global__ void proj_kernel(const float* __restrict__ Wproj, float* __restrict__ out) {
    const int RT = 16;
    int row0 = blockIdx.x * RT;
    int tid = threadIdx.x; // 256
    __shared__ float Os[RT][512];
    const float4* O0 = (const float4*)(g_O0 + ((size_t)row0 << 9));
    const float4* O1 = (const float4*)(g_O1 + ((size_t)row0 << 9));
    const float4* O2 = (const float4*)(g_O2 + ((size_t)row0 << 9));
    for (int i = tid; i < RT * 128; i += 256) {
        float4 a = O0[i], b = O1[i], c = O2[i];
        a.x += b.x + c.x; a.y += b.y + c.y; a.z += b.z + c.z; a.w += b.w + c.w;
        ((float4*)Os)[i] = a;
    }
    __syncthreads();
    float acc[RT];
    #pragma unroll
    for (int r = 0; r < RT; ++r) acc[r] = 0.f;
    for (int c = 0; c < 512; c += 4) {
        float w0 = Wproj[c * 256 + tid], w1 = Wproj[(c + 1) * 256 + tid];
        float w2 = Wproj[(c + 2) * 256 + tid], w3 = Wproj[(c + 3) * 256 + tid];
        #pragma unroll
        for (int r = 0; r < RT; ++r) {
            float4 o = *(const float4*)&Os[r][c];
            acc[r] += o.x * w0 + o.y * w1 + o.z * w2 + o.w * w3;
        }
    }
    #pragma unroll
    for (int r = 0; r < RT; ++r) out[(size_t)(row0 + r) * 256 + tid] = acc[r];
}

// ---------------- launch (single stream; no allocations, no streams/events) ----------------
extern "C" void kernel_launch(void* const* d_in, const int* in_sizes, int n_in,
                              void* d_out, int out_size) {
    const float* x     = (const float*)d_in[0];
    const float* Wcq   = (const float*)d_in[1];
    const float* qnw   = (const float*)d_in[2];
    const float* Wqn   = (const float*)d_in[3];
    const float* Wqr   = (const float*)d_in[4];
    const float* Wckv  = (const float*)d_in[5];
    const float* kvnw  = (const float*)d_in[6];
    const float* Wkn   = (const float*)d_in[7];
    const float* Wv    = (const float*)d_in[8];
    const float* Wkr   = (const float*)d_in[9];
    const float* Wimp  = (const float*)d_in[10];
    const float* Wselk = (const float*)d_in[11];
    const float* Wselv = (const float*)d_in[12];
    const float* Wwink = (const float*)d_in[13];
    const float* Wwinv = (const float*)d_in[14];
    const float* Wgate = (const float*)d_in[15];
    const float* Wproj = (const float*)d_in[16];
    float* out = (float*)d_out;
    int B = in_sizes[0] / (T_SEQ * C_DIM);
    if (B < 1) B = 1; if (B > BMAX) B = BMAX;

    cudaFuncSetAttribute(attn_all, cudaFuncAttributeMaxDynamicSharedMemorySize, FA_SMEM);

    rope_tab_kernel<<<(T_SEQ * 32 + 255) / 256, 256>>>();
    row_feat_kernel<<<B * T_SEQ, 256>>>(x, Wcq, qnw, Wckv, kvnw, Wkr, Wimp);
    colmean_part_kernel<<<B * 16, 256>>>(x);
    gate_kernel<<<1, 192>>>(Wgate, B);
    qkv_kernel<<<B * T_SEQ / 8, 256>>>(Wqn, Wqr, Wkn, Wv);
    topk_kernel<<<B, 1024>>>();
    kvproj_kernel<true><<<B * KEEP / 16, 256>>>(x, Wselk, Wselv);
    kvproj_kernel<false><<<B * T_SEQ / 16, 256>>>(x, Wwink, Wwinv);

    dim3 agrid(96, H_NUM, B);
    attn_all<<<agrid, 128, FA_SMEM>>>();

    proj_kernel<<<B * T_SEQ / 16, 256>>>(Wproj, out);
}

// round 8
// speedup vs baseline: 2.8151x; 1.2014x over previous
#include <cuda_runtime.h>
#include <cuda_bf16.h>
#include <cuda_fp16.h>
#include <math.h>
#include <stdint.h>

#define T_SEQ 2048
#define C_DIM 256
#define H_NUM 16
#define NOPE 32
#define ROPE 64
#define HD 96
#define VD 32
#define KEEP 512
#define WIN 128
#define BMAX 2
#define EPSF 1e-6f

// ---------------- device scratch ----------------
__device__ float g_costab[T_SEQ * 32];
__device__ float g_sintab[T_SEQ * 32];
__device__ float g_cq[BMAX * T_SEQ * 96];
__device__ float g_ckv[BMAX * T_SEQ * 32];
__device__ float g_kr[BMAX * T_SEQ * 64];
__device__ float g_imp[BMAX * T_SEQ];
__device__ int   g_idx[BMAX * KEEP];
__device__ float g_xpart[BMAX * 16 * C_DIM];
__device__ float g_gate[BMAX * 3];
__device__ float g_q [BMAX * H_NUM * T_SEQ * HD];
__device__ __nv_bfloat16 g_k1hi[BMAX * H_NUM * T_SEQ * HD];
__device__ __nv_bfloat16 g_k1lo[BMAX * H_NUM * T_SEQ * HD];
__device__ __nv_bfloat16 g_kshi[BMAX * H_NUM * KEEP * HD];
__device__ __nv_bfloat16 g_kslo[BMAX * H_NUM * KEEP * HD];
__device__ __nv_bfloat16 g_kwhi[BMAX * H_NUM * T_SEQ * HD];
__device__ __nv_bfloat16 g_kwlo[BMAX * H_NUM * T_SEQ * HD];
__device__ float g_v1[BMAX * H_NUM * T_SEQ * VD];
__device__ float g_vs[BMAX * H_NUM * KEEP * VD];
__device__ float g_vw[BMAX * H_NUM * T_SEQ * VD];
__device__ float g_O0[BMAX * T_SEQ * H_NUM * VD];
__device__ float g_O1[BMAX * T_SEQ * H_NUM * VD];
__device__ float g_O2[BMAX * T_SEQ * H_NUM * VD];

__device__ __forceinline__ void mma16bf(float* c, const uint32_t* a, uint32_t b0, uint32_t b1) {
    asm volatile("mma.sync.aligned.m16n8k16.row.col.f32.bf16.bf16.f32 "
        "{%0,%1,%2,%3}, {%4,%5,%6,%7}, {%8,%9}, {%0,%1,%2,%3};"
        : "+f"(c[0]), "+f"(c[1]), "+f"(c[2]), "+f"(c[3])
        : "r"(a[0]), "r"(a[1]), "r"(a[2]), "r"(a[3]), "r"(b0), "r"(b1));
}
__device__ __forceinline__ void mma16h(float* c, const uint32_t* a, uint32_t b0, uint32_t b1) {
    asm volatile("mma.sync.aligned.m16n8k16.row.col.f32.f16.f16.f32 "
        "{%0,%1,%2,%3}, {%4,%5,%6,%7}, {%8,%9}, {%0,%1,%2,%3};"
        : "+f"(c[0]), "+f"(c[1]), "+f"(c[2]), "+f"(c[3])
        : "r"(a[0]), "r"(a[1]), "r"(a[2]), "r"(a[3]), "r"(b0), "r"(b1));
}
__device__ __forceinline__ void ldsm4(uint32_t& r0, uint32_t& r1, uint32_t& r2, uint32_t& r3,
                                      uint32_t addr) {
    asm volatile("ldmatrix.sync.aligned.m8n8.x4.shared.b16 {%0,%1,%2,%3}, [%4];"
        : "=r"(r0), "=r"(r1), "=r"(r2), "=r"(r3) : "r"(addr));
}
__device__ __forceinline__ void split_store(float v, __nv_bfloat16* hi, __nv_bfloat16* lo) {
    __nv_bfloat16 h = __float2bfloat16(v);
    *hi = h;
    *lo = __float2bfloat16(v - __bfloat162float(h));
}

// ---------------- rope table ----------------
__global__ void rope_tab_kernel() {
    int id = blockIdx.x * 256 + threadIdx.x;
    if (id >= T_SEQ * 32) return;
    int t = id >> 5, i = id & 31;
    float f = (float)pow(10000.0, -(double)i / 32.0);
    float ang = (float)t * f;
    g_costab[id] = cosf(ang);
    g_sintab[id] = sinf(ang);
}

// ---------------- per-row features ----------------
__global__ void row_feat_kernel(const float* __restrict__ x,
                                const float* __restrict__ Wcq, const float* __restrict__ qnw,
                                const float* __restrict__ Wckv, const float* __restrict__ kvnw,
                                const float* __restrict__ Wkr, const float* __restrict__ Wimp) {
    int row = blockIdx.x;
    int tid = threadIdx.x; // 256
    int lane = tid & 31, w = tid >> 5;
    int t = row % T_SEQ;
    __shared__ float xs[C_DIM];
    __shared__ float krbuf[64];
    __shared__ float red[4];
    xs[tid] = x[(size_t)row * C_DIM + tid];
    __syncthreads();
    float a = 0.f;
    if (tid < 96) {
        for (int c = 0; c < C_DIM; c += 4) {
            float4 xv = *(const float4*)&xs[c];
            a += xv.x * Wcq[c * 96 + tid] + xv.y * Wcq[(c + 1) * 96 + tid]
               + xv.z * Wcq[(c + 2) * 96 + tid] + xv.w * Wcq[(c + 3) * 96 + tid];
        }
    } else if (tid < 128) {
        int j = tid - 96;
        for (int c = 0; c < C_DIM; c += 4) {
            float4 xv = *(const float4*)&xs[c];
            a += xv.x * Wckv[c * 32 + j] + xv.y * Wckv[(c + 1) * 32 + j]
               + xv.z * Wckv[(c + 2) * 32 + j] + xv.w * Wckv[(c + 3) * 32 + j];
        }
    } else if (tid < 192) {
        int j = tid - 128;
        for (int c = 0; c < C_DIM; c += 4) {
            float4 xv = *(const float4*)&xs[c];
            a += xv.x * Wkr[c * 64 + j] + xv.y * Wkr[(c + 1) * 64 + j]
               + xv.z * Wkr[(c + 2) * 64 + j] + xv.w * Wkr[(c + 3) * 64 + j];
        }
        a *= (1.f / (float)H_NUM);
        krbuf[j] = a;
    } else if (tid == 192) {
        for (int c = 0; c < C_DIM; ++c) a += xs[c] * Wimp[c];
        g_imp[row] = a;
    }
    if (w < 4) {
        float sq = a * a;
        #pragma unroll
        for (int o = 16; o > 0; o >>= 1) sq += __shfl_xor_sync(0xffffffffu, sq, o);
        if (lane == 0) red[w] = sq;
    }
    __syncthreads();
    if (tid < 96) {
        float rms_cq = rsqrtf((red[0] + red[1] + red[2]) / 96.f + EPSF);
        g_cq[(size_t)row * 96 + tid] = a * rms_cq * qnw[tid];
    } else if (tid < 128) {
        float rms_kv = rsqrtf(red[3] / 32.f + EPSF);
        g_ckv[(size_t)row * 32 + (tid - 96)] = a * rms_kv * kvnw[tid - 96];
    } else if (tid < 160) {
        int i = tid - 128;
        float xr = krbuf[i], xi = krbuf[32 + i];
        float co = g_costab[t * 32 + i], si = g_sintab[t * 32 + i];
        g_kr[(size_t)row * 64 + i]      = xr * co - xi * si;
        g_kr[(size_t)row * 64 + 32 + i] = xr * si + xi * co;
    }
}

// ---------------- gate: parallel colmean partials + tiny reduce ----------------
__global__ void colmean_part_kernel(const float* __restrict__ x) {
    int blk = blockIdx.x;
    int b = blk >> 4, chunk = blk & 15;
    int c = threadIdx.x;
    const float* xp = x + ((size_t)b * T_SEQ + chunk * 128) * C_DIM + c;
    float s = 0.f;
    #pragma unroll 4
    for (int t = 0; t < 128; ++t) s += xp[(size_t)t * C_DIM];
    g_xpart[blk * C_DIM + c] = s;
}

__global__ void gate_kernel(const float* __restrict__ Wgate, int B) {
    __shared__ float lg[6];
    int tid = threadIdx.x;
    int w = tid >> 5, lane = tid & 31;
    if (w < B * 3) {
        int b = w / 3, j = w % 3;
        float s = 0.f;
        for (int c = lane; c < C_DIM; c += 32) {
            float m = 0.f;
            #pragma unroll
            for (int p = 0; p < 16; ++p) m += g_xpart[(b * 16 + p) * C_DIM + c];
            s += (m / (float)T_SEQ) * Wgate[c * 3 + j];
        }
        #pragma unroll
        for (int o = 16; o > 0; o >>= 1) s += __shfl_xor_sync(0xffffffffu, s, o);
        if (lane == 0) lg[w] = s;
    }
    __syncthreads();
    if (tid < B) {
        float a = lg[tid * 3], b2 = lg[tid * 3 + 1], c2 = lg[tid * 3 + 2];
        float mx = fmaxf(a, fmaxf(b2, c2));
        float ea = expf(a - mx), eb = expf(b2 - mx), ec = expf(c2 - mx);
        float s = ea + eb + ec;
        g_gate[tid * 3 + 0] = ea / s;
        g_gate[tid * 3 + 1] = eb / s;
        g_gate[tid * 3 + 2] = ec / s;
    }
}

// ---------------- q / k1 / v1 projection (x-reuse: 2 cols per thread per pass) ----------------
__global__ void qkv_kernel(const float* __restrict__ Wqn, const float* __restrict__ Wqr,
                           const float* __restrict__ Wkn, const float* __restrict__ Wv) {
    const int RT = 8;
    int row0 = blockIdx.x * RT;
    int tid = threadIdx.x; // 256
    __shared__ float cqs[RT][96];
    __shared__ float ckvs[RT][32];
    __shared__ float krs[RT][64];
    for (int i = tid; i < RT * 96; i += 256) cqs[i / 96][i % 96] = g_cq[(size_t)(row0 + i / 96) * 96 + (i % 96)];
    for (int i = tid; i < RT * 32; i += 256) ckvs[i / 32][i % 32] = g_ckv[(size_t)(row0 + i / 32) * 32 + (i % 32)];
    for (int i = tid; i < RT * 64; i += 256) krs[i / 64][i % 64] = g_kr[(size_t)(row0 + i / 64) * 64 + (i % 64)];
    __syncthreads();
    // q nope: cols tid and tid+256 in one k-loop (x loaded once)
    {
        int o0 = tid, o1 = tid + 256;
        float acc0[RT], acc1[RT];
        #pragma unroll
        for (int r = 0; r < RT; ++r) { acc0[r] = 0.f; acc1[r] = 0.f; }
        for (int c = 0; c < 96; c += 4) {
            float a0 = Wqn[c * 512 + o0], a1 = Wqn[(c + 1) * 512 + o0];
            float a2 = Wqn[(c + 2) * 512 + o0], a3 = Wqn[(c + 3) * 512 + o0];
            float b0 = Wqn[c * 512 + o1], b1 = Wqn[(c + 1) * 512 + o1];
            float b2 = Wqn[(c + 2) * 512 + o1], b3 = Wqn[(c + 3) * 512 + o1];
            #pragma unroll
            for (int r = 0; r < RT; ++r) {
                float4 q = *(const float4*)&cqs[r][c];
                acc0[r] += q.x * a0 + q.y * a1 + q.z * a2 + q.w * a3;
                acc1[r] += q.x * b0 + q.y * b1 + q.z * b2 + q.w * b3;
            }
        }
        #pragma unroll
        for (int r = 0; r < RT; ++r) {
            int row = row0 + r; int b = row / T_SEQ, t = row % T_SEQ;
            size_t base = (size_t)b * H_NUM * T_SEQ * HD + (size_t)t * HD;
            g_q[base + (size_t)(o0 >> 5) * T_SEQ * HD + (o0 & 31)] = acc0[r];
            g_q[base + (size_t)(o1 >> 5) * T_SEQ * HD + (o1 & 31)] = acc1[r];
        }
    }
    // q rope pairs
    for (int p = tid; p < 512; p += 256) {
        int h = p >> 5, i = p & 31;
        float ar[RT], ai[RT];
        #pragma unroll
        for (int r = 0; r < RT; ++r) { ar[r] = 0.f; ai[r] = 0.f; }
        for (int c = 0; c < 96; c += 2) {
            float wr0 = Wqr[c * 1024 + h * 64 + i];
            float wi0 = Wqr[c * 1024 + h * 64 + 32 + i];
            float wr1 = Wqr[(c + 1) * 1024 + h * 64 + i];
            float wi1 = Wqr[(c + 1) * 1024 + h * 64 + 32 + i];
            #pragma unroll
            for (int r = 0; r < RT; ++r) {
                float2 q = *(const float2*)&cqs[r][c];
                ar[r] += q.x * wr0 + q.y * wr1;
                ai[r] += q.x * wi0 + q.y * wi1;
            }
        }
        #pragma unroll
        for (int r = 0; r < RT; ++r) {
            int row = row0 + r; int b = row / T_SEQ, t = row % T_SEQ;
            float co = g_costab[t * 32 + i], si = g_sintab[t * 32 + i];
            size_t base = ((size_t)(b * H_NUM + h) * T_SEQ + t) * HD;
            g_q[base + 32 + i] = ar[r] * co - ai[r] * si;
            g_q[base + 64 + i] = ar[r] * si + ai[r] * co;
        }
    }
    // k nope + v (shared x, 2 outputs already)
    for (int o = tid; o < 512; o += 256) {
        int h = o >> 5, d = o & 31;
        float acc[RT], accv[RT];
        #pragma unroll
        for (int r = 0; r < RT; ++r) { acc[r] = 0.f; accv[r] = 0.f; }
        for (int c = 0; c < 32; c += 4) {
            float k0 = Wkn[c * 512 + o], k1 = Wkn[(c + 1) * 512 + o];
            float k2 = Wkn[(c + 2) * 512 + o], k3 = Wkn[(c + 3) * 512 + o];
            float v0 = Wv[c * 512 + o], v1 = Wv[(c + 1) * 512 + o];
            float v2 = Wv[(c + 2) * 512 + o], v3 = Wv[(c + 3) * 512 + o];
            #pragma unroll
            for (int r = 0; r < RT; ++r) {
                float4 q = *(const float4*)&ckvs[r][c];
                acc[r]  += q.x * k0 + q.y * k1 + q.z * k2 + q.w * k3;
                accv[r] += q.x * v0 + q.y * v1 + q.z * v2 + q.w * v3;
            }
        }
        #pragma unroll
        for (int r = 0; r < RT; ++r) {
            int row = row0 + r; int b = row / T_SEQ, t = row % T_SEQ;
            size_t o2 = ((size_t)(b * H_NUM + h) * T_SEQ + t) * HD + d;
            split_store(acc[r], &g_k1hi[o2], &g_k1lo[o2]);
            g_v1[((size_t)(b * H_NUM + h) * T_SEQ + t) * VD + d] = accv[r];
        }
    }
    for (int i = tid; i < RT * H_NUM * 64; i += 256) {
        int r = i / (H_NUM * 64); int rem = i % (H_NUM * 64); int h = rem / 64; int d = rem % 64;
        int row = row0 + r; int b = row / T_SEQ, t = row % T_SEQ;
        size_t o2 = ((size_t)(b * H_NUM + h) * T_SEQ + t) * HD + 32 + d;
        split_store(krs[r][d], &g_k1hi[o2], &g_k1lo[o2]);
    }
}

// ---------------- top-k ----------------
__global__ void topk_kernel() {
    __shared__ float v[T_SEQ];
    __shared__ int   ix[T_SEQ];
    int b = blockIdx.x, tid = threadIdx.x; // 1024
    for (int i = tid; i < T_SEQ; i += 1024) { v[i] = g_imp[b * T_SEQ + i]; ix[i] = i; }
    __syncthreads();
    for (int k = 2; k <= T_SEQ; k <<= 1)
        for (int j = k >> 1; j > 0; j >>= 1) {
            for (int i = tid; i < T_SEQ; i += 1024) {
                int p = i ^ j;
                if (p > i) {
                    bool up = ((i & k) == 0);
                    bool sw = up ? (v[i] < v[p]) : (v[i] > v[p]);
                    if (sw) {
                        float tv = v[i]; v[i] = v[p]; v[p] = tv;
                        int ti = ix[i]; ix[i] = ix[p]; ix[p] = ti;
                    }
                }
            }
            __syncthreads();
        }
    for (int k = 2; k <= KEEP; k <<= 1)
        for (int j = k >> 1; j > 0; j >>= 1) {
            if (tid < KEEP) {
                int i = tid, p = i ^ j;
                if (p > i) {
                    bool up = ((i & k) == 0);
                    bool sw = up ? (ix[i] > ix[p]) : (ix[i] < ix[p]);
                    if (sw) { int ti = ix[i]; ix[i] = ix[p]; ix[p] = ti; }
                }
            }
            __syncthreads();
        }
    for (int i = tid; i < KEEP; i += 1024) g_idx[b * KEEP + i] = ix[i];
}

// ---------------- sel / window K,V projection (x-reuse: 2 cols per thread per pass) ----------------
template <bool SEL>
__global__ void kvproj_kernel(const float* __restrict__ x,
                              const float* __restrict__ Wk, const float* __restrict__ Wv) {
    const int RT = 16;
    const int Tk = SEL ? KEEP : T_SEQ;
    int row0 = blockIdx.x * RT;
    int tid = threadIdx.x; // 256
    __shared__ float xs[RT][C_DIM];
    for (int r = 0; r < RT; ++r) {
        int row = row0 + r; int b = row / Tk; int s = row % Tk;
        int src = SEL ? (b * T_SEQ + g_idx[b * KEEP + s]) : (b * T_SEQ + s);
        xs[r][tid] = x[(size_t)src * C_DIM + tid];
    }
    __syncthreads();
    __nv_bfloat16* Khi = SEL ? g_kshi : g_kwhi;
    __nv_bfloat16* Klo = SEL ? g_kslo : g_kwlo;
    float* Vo = SEL ? g_vs : g_vw;
    // K nope: cols tid, tid+256 fused
    {
        int o0 = tid, o1 = tid + 256;
        int col0 = (o0 >> 5) * HD + (o0 & 31);
        int col1 = (o1 >> 5) * HD + (o1 & 31);
        float acc0[RT], acc1[RT];
        #pragma unroll
        for (int r = 0; r < RT; ++r) { acc0[r] = 0.f; acc1[r] = 0.f; }
        for (int c = 0; c < C_DIM; c += 4) {
            float a0 = Wk[c * 1536 + col0], a1 = Wk[(c + 1) * 1536 + col0];
            float a2 = Wk[(c + 2) * 1536 + col0], a3 = Wk[(c + 3) * 1536 + col0];
            float b0 = Wk[c * 1536 + col1], b1 = Wk[(c + 1) * 1536 + col1];
            float b2 = Wk[(c + 2) * 1536 + col1], b3 = Wk[(c + 3) * 1536 + col1];
            #pragma unroll
            for (int r = 0; r < RT; ++r) {
                float4 q = *(const float4*)&xs[r][c];
                acc0[r] += q.x * a0 + q.y * a1 + q.z * a2 + q.w * a3;
                acc1[r] += q.x * b0 + q.y * b1 + q.z * b2 + q.w * b3;
            }
        }
        #pragma unroll
        for (int r = 0; r < RT; ++r) {
            int row = row0 + r; int b = row / Tk; int s = row % Tk;
            size_t hb = (size_t)b * H_NUM * Tk * HD + (size_t)s * HD;
            size_t p0 = hb + (size_t)(o0 >> 5) * Tk * HD + (o0 & 31);
            size_t p1 = hb + (size_t)(o1 >> 5) * Tk * HD + (o1 & 31);
            split_store(acc0[r], &Khi[p0], &Klo[p0]);
            split_store(acc1[r], &Khi[p1], &Klo[p1]);
        }
    }
    // K rope pairs
    for (int p = tid; p < 512; p += 256) {
        int h = p >> 5, i = p & 31;
        float ar[RT], ai[RT];
        #pragma unroll
        for (int r = 0; r < RT; ++r) { ar[r] = 0.f; ai[r] = 0.f; }
        for (int c = 0; c < C_DIM; c += 2) {
            float wr0 = Wk[c * 1536 + h * HD + 32 + i];
            float wi0 = Wk[c * 1536 + h * HD + 64 + i];
            float wr1 = Wk[(c + 1) * 1536 + h * HD + 32 + i];
            float wi1 = Wk[(c + 1) * 1536 + h * HD + 64 + i];
            #pragma unroll
            for (int r = 0; r < RT; ++r) {
                float2 q = *(const float2*)&xs[r][c];
                ar[r] += q.x * wr0 + q.y * wr1;
                ai[r] += q.x * wi0 + q.y * wi1;
            }
        }
        #pragma unroll
        for (int r = 0; r < RT; ++r) {
            int row = row0 + r; int b = row / Tk; int s = row % Tk;
            float co = g_costab[s * 32 + i], si = g_sintab[s * 32 + i];
            size_t base = ((size_t)(b * H_NUM + h) * Tk + s) * HD;
            split_store(ar[r] * co - ai[r] * si, &Khi[base + 32 + i], &Klo[base + 32 + i]);
            split_store(ar[r] * si + ai[r] * co, &Khi[base + 64 + i], &Klo[base + 64 + i]);
        }
    }
    // V: cols tid, tid+256 fused
    {
        int o0 = tid, o1 = tid + 256;
        float acc0[RT], acc1[RT];
        #pragma unroll
        for (int r = 0; r < RT; ++r) { acc0[r] = 0.f; acc1[r] = 0.f; }
        for (int c = 0; c < C_DIM; c += 4) {
            float a0 = Wv[c * 512 + o0], a1 = Wv[(c + 1) * 512 + o0];
            float a2 = Wv[(c + 2) * 512 + o0], a3 = Wv[(c + 3) * 512 + o0];
            float b0 = Wv[c * 512 + o1], b1 = Wv[(c + 1) * 512 + o1];
            float b2 = Wv[(c + 2) * 512 + o1], b3 = Wv[(c + 3) * 512 + o1];
            #pragma unroll
            for (int r = 0; r < RT; ++r) {
                float4 q = *(const float4*)&xs[r][c];
                acc0[r] += q.x * a0 + q.y * a1 + q.z * a2 + q.w * a3;
                acc1[r] += q.x * b0 + q.y * b1 + q.z * b2 + q.w * b3;
            }
        }
        #pragma unroll
        for (int r = 0; r < RT; ++r) {
            int row = row0 + r; int b = row / Tk; int s = row % Tk;
            size_t vb = (size_t)b * H_NUM * Tk * VD + (size_t)s * VD;
            Vo[vb + (size_t)(o0 >> 5) * Tk * VD + (o0 & 31)] = acc0[r];
            Vo[vb + (size_t)(o1 >> 5) * Tk * VD + (o1 & 31)] = acc1[r];
        }
    }
}

// ---------------- fused flash attention (ldmatrix K-fragment loads) ----------------
#define AQB 64
#define AKB 64
#define KROW_U32 52
#define KROW_U4  13
#define KROW_B   208
#define LDVP 42
#define FA_SMEM (2 * (AKB * KROW_U4 * 16) + 32 * LDVP * 4)

__global__ void __launch_bounds__(128) attn_all() {
    extern __shared__ char smc[];
    uint4* Khi4 = (uint4*)smc;
    uint4* Klo4 = Khi4 + AKB * KROW_U4;
    uint32_t* Vp = (uint32_t*)(Klo4 + AKB * KROW_U4);

    int mode = blockIdx.x >> 5;
    int qt0 = (blockIdx.x & 31) * AQB;
    const int Tk = (mode == 1) ? KEEP : T_SEQ;
    int b = blockIdx.z, h = blockIdx.y;
    int tid = threadIdx.x;
    int w = tid >> 5, lane = tid & 31;
    int g = lane >> 2, tg = lane & 3;
    int r0 = w * 16;

    const __nv_bfloat16* KHI = (mode == 1) ? g_kshi : (mode == 2) ? g_kwhi : g_k1hi;
    const __nv_bfloat16* KLO = (mode == 1) ? g_kslo : (mode == 2) ? g_kwlo : g_k1lo;
    const float* V = (mode == 1) ? g_vs : (mode == 2) ? g_vw : g_v1;
    float* Oout = (mode == 1) ? g_O1 : (mode == 2) ? g_O2 : g_O0;
    const __nv_bfloat16* KbaseH = KHI + (size_t)(b * H_NUM + h) * Tk * HD;
    const __nv_bfloat16* KbaseL = KLO + (size_t)(b * H_NUM + h) * Tk * HD;
    const float* Vbase = V + (size_t)(b * H_NUM + h) * Tk * VD;
    const float* Qbase = g_q + ((size_t)(b * H_NUM + h) * T_SEQ + qt0) * HD;
    const float qscale = 0.14724444f; // log2(e)/sqrt(96)

    // ldmatrix per-lane base addresses (row = lane&7, matrix = lane>>3)
    uint32_t lmoff = (uint32_t)(lane & 7) * KROW_B + (uint32_t)(lane >> 3) * 16;
    uint32_t baseH = (uint32_t)__cvta_generic_to_shared(Khi4) + lmoff;
    uint32_t baseL = (uint32_t)__cvta_generic_to_shared(Klo4) + lmoff;

    for (int i = tid; i < 32 * 8; i += 128) {
        int pr = i >> 3, c = 32 + (i & 7);
        Vp[pr * LDVP + c] = (c == 32) ? 0x3C003C00u : 0u;
    }

    uint32_t qhi[6][4], qlo[6][4];
    #pragma unroll
    for (int kc = 0; kc < 6; ++kc) {
        #pragma unroll
        for (int e = 0; e < 4; ++e) {
            int row = r0 + g + (e & 1) * 8;
            int col = kc * 16 + 2 * tg + (e & 2) * 4;
            float2 qv = *(const float2*)(Qbase + (size_t)row * HD + col);
            qv.x *= qscale; qv.y *= qscale;
            __nv_bfloat16 hx = __float2bfloat16(qv.x);
            __nv_bfloat16 hy = __float2bfloat16(qv.y);
            qhi[kc][e] = ((uint32_t)__bfloat16_as_ushort(hy) << 16) | __bfloat16_as_ushort(hx);
            __nv_bfloat16 lx = __float2bfloat16(qv.x - __bfloat162float(hx));
            __nv_bfloat16 ly = __float2bfloat16(qv.y - __bfloat162float(hy));
            qlo[kc][e] = ((uint32_t)__bfloat16_as_ushort(ly) << 16) | __bfloat16_as_ushort(lx);
        }
    }

    float oacc[5][4];
    #pragma unroll
    for (int nt = 0; nt < 5; ++nt)
        #pragma unroll
        for (int e = 0; e < 4; ++e) oacc[nt][e] = 0.f;

    int kend = (mode == 1) ? KEEP : (qt0 + AQB);
    int k0 = 0;
    if (mode == 2) { int a0 = qt0 - (WIN - 1); k0 = (a0 > 0) ? (a0 & ~(AKB - 1)) : 0; }

    for (int kt = k0; kt < kend; kt += AKB) {
        __syncthreads();
        const uint4* KsrcH = (const uint4*)(KbaseH + (size_t)kt * HD);
        const uint4* KsrcL = (const uint4*)(KbaseL + (size_t)kt * HD);
        #pragma unroll
        for (int it = 0; it < 6; ++it) {
            int i = tid + it * 128;
            int r = i / 12, c = i % 12;
            Khi4[r * KROW_U4 + c] = KsrcH[i];
            Klo4[r * KROW_U4 + c] = KsrcL[i];
        }
        const float4* Vsrc = (const float4*)(Vbase + (size_t)kt * VD);
        #pragma unroll
        for (int it = 0; it < 2; ++it) {
            int pc = tid + it * 128;
            int pr = pc >> 3, cc = pc & 7;
            float4 f0 = Vsrc[(2 * pr) * 8 + cc];
            float4 f1 = Vsrc[(2 * pr + 1) * 8 + cc];
            uint32_t* dst = Vp + pr * LDVP + cc * 4;
            __half2 p0 = __floats2half2_rn(f0.x, f1.x);
            __half2 p1 = __floats2half2_rn(f0.y, f1.y);
            __half2 p2 = __floats2half2_rn(f0.z, f1.z);
            __half2 p3 = __floats2half2_rn(f0.w, f1.w);
            dst[0] = *(uint32_t*)&p0; dst[1] = *(uint32_t*)&p1;
            dst[2] = *(uint32_t*)&p2; dst[3] = *(uint32_t*)&p3;
        }
        __syncthreads();

        // S = Q K^T (bf16 3-term) with ldmatrix.x4 operand loads
        float sacc[8][4];
        #pragma unroll
        for (int nt = 0; nt < 8; ++nt)
            #pragma unroll
            for (int e = 0; e < 4; ++e) sacc[nt][e] = 0.f;
        #pragma unroll
        for (int nt = 0; nt < 8; ++nt) {
            uint32_t aH = baseH + (uint32_t)nt * (8 * KROW_B);
            uint32_t aL = baseL + (uint32_t)nt * (8 * KROW_B);
            #pragma unroll
            for (int kp = 0; kp < 3; ++kp) {
                uint32_t h0, h1, h2, h3, l0, l1, l2, l3;
                ldsm4(h0, h1, h2, h3, aH + kp * 64);
                ldsm4(l0, l1, l2, l3, aL + kp * 64);
                int kc = 2 * kp;
                mma16bf(sacc[nt], qhi[kc], h0, h1);
                mma16bf(sacc[nt], qhi[kc], l0, l1);
                mma16bf(sacc[nt], qlo[kc], h0, h1);
                mma16bf(sacc[nt], qhi[kc + 1], h2, h3);
                mma16bf(sacc[nt], qhi[kc + 1], l2, l3);
                mma16bf(sacc[nt], qlo[kc + 1], h2, h3);
            }
        }

        bool need_mask = (mode == 2) || (mode == 0 && kt + AKB > qt0);
        if (need_mask) {
            #pragma unroll
            for (int nt = 0; nt < 8; ++nt) {
                #pragma unroll
                for (int e = 0; e < 4; ++e) {
                    int key = kt + nt * 8 + 2 * tg + (e & 1);
                    int row = qt0 + r0 + g + ((e & 2) ? 8 : 0);
                    bool ok = key <= row;
                    if (mode == 2) ok = ok && (row - key < WIN);
                    if (!ok) sacc[nt][e] = -1e30f;
                }
            }
        }

        uint32_t ph2[8][2];
        #pragma unroll
        for (int nt = 0; nt < 8; ++nt) {
            __half2 e0 = h2exp2(__floats2half2_rn(sacc[nt][0], sacc[nt][1]));
            __half2 e1 = h2exp2(__floats2half2_rn(sacc[nt][2], sacc[nt][3]));
            ph2[nt][0] = *(uint32_t*)&e0;
            ph2[nt][1] = *(uint32_t*)&e1;
        }

        #pragma unroll
        for (int kc2 = 0; kc2 < 4; ++kc2) {
            uint32_t pa[4] = { ph2[2 * kc2][0], ph2[2 * kc2][1],
                               ph2[2 * kc2 + 1][0], ph2[2 * kc2 + 1][1] };
            #pragma unroll
            for (int nt2 = 0; nt2 < 5; ++nt2) {
                uint32_t b0 = Vp[(kc2 * 8 + tg) * LDVP + nt2 * 8 + g];
                uint32_t b1 = Vp[(kc2 * 8 + tg + 4) * LDVP + nt2 * 8 + g];
                mma16h(oacc[nt2], pa, b0, b1);
            }
        }
    }

    float l0 = __shfl_sync(0xffffffffu, oacc[4][0], lane & 28);
    float l1 = __shfl_sync(0xffffffffu, oacc[4][2], lane & 28);
    float gte = g_gate[b * 3 + mode];
    float inv0 = gte / l0, inv1 = gte / l1;
    #pragma unroll
    for (int nt = 0; nt < 4; ++nt) {
        #pragma unroll
        for (int e = 0; e < 4; ++e) {
            int row = qt0 + r0 + g + ((e & 2) ? 8 : 0);
            int col = nt * 8 + 2 * tg + (e & 1);
            Oout[((size_t)(b * T_SEQ + row) * H_NUM + h) * VD + col] =
                oacc[nt][e] * ((e & 2) ? inv1 : inv0);
        }
    }
}

// ---------------- final projection (sums 3 branch buffers) ----------------
__global__ void proj_kernel(const float* __restrict__ Wproj, float* __restrict__ out) {
    const int RT = 16;
    int row0 = blockIdx.x * RT;
    int tid = threadIdx.x; // 256
    __shared__ float Os[RT][512];
    const float4* O0 = (const float4*)(g_O0 + ((size_t)row0 << 9));
    const float4* O1 = (const float4*)(g_O1 + ((size_t)row0 << 9));
    const float4* O2 = (const float4*)(g_O2 + ((size_t)row0 << 9));
    for (int i = tid; i < RT * 128; i += 256) {
        float4 a = O0[i], b = O1[i], c = O2[i];
        a.x += b.x + c.x; a.y += b.y + c.y; a.z += b.z + c.z; a.w += b.w + c.w;
        ((float4*)Os)[i] = a;
    }
    __syncthreads();
    float acc[RT];
    #pragma unroll
    for (int r = 0; r < RT; ++r) acc[r] = 0.f;
    for (int c = 0; c < 512; c += 4) {
        float w0 = Wproj[c * 256 + tid], w1 = Wproj[(c + 1) * 256 + tid];
        float w2 = Wproj[(c + 2) * 256 + tid], w3 = Wproj[(c + 3) * 256 + tid];
        #pragma unroll
        for (int r = 0; r < RT; ++r) {
            float4 o = *(const float4*)&Os[r][c];
            acc[r] += o.x * w0 + o.y * w1 + o.z * w2 + o.w * w3;
        }
    }
    #pragma unroll
    for (int r = 0; r < RT; ++r) out[(size_t)(row0 + r) * 256 + tid] = acc[r];
}

// ---------------- launch ----------------
extern "C" void kernel_launch(void* const* d_in, const int* in_sizes, int n_in,
                              void* d_out, int out_size) {
    const float* x     = (const float*)d_in[0];
    const float* Wcq   = (const float*)d_in[1];
    const float* qnw   = (const float*)d_in[2];
    const float* Wqn   = (const float*)d_in[3];
    const float* Wqr   = (const float*)d_in[4];
    const float* Wckv  = (const float*)d_in[5];
    const float* kvnw  = (const float*)d_in[6];
    const float* Wkn   = (const float*)d_in[7];
    const float* Wv    = (const float*)d_in[8];
    const float* Wkr   = (const float*)d_in[9];
    const float* Wimp  = (const float*)d_in[10];
    const float* Wselk = (const float*)d_in[11];
    const float* Wselv = (const float*)d_in[12];
    const float* Wwink = (const float*)d_in[13];
    const float* Wwinv = (const float*)d_in[14];
    const float* Wgate = (const float*)d_in[15];
    const float* Wproj = (const float*)d_in[16];
    float* out = (float*)d_out;
    int B = in_sizes[0] / (T_SEQ * C_DIM);
    if (B < 1) B = 1; if (B > BMAX) B = BMAX;

    cudaFuncSetAttribute(attn_all, cudaFuncAttributeMaxDynamicSharedMemorySize, FA_SMEM);

    rope_tab_kernel<<<(T_SEQ * 32 + 255) / 256, 256>>>();
    row_feat_kernel<<<B * T_SEQ, 256>>>(x, Wcq, qnw, Wckv, kvnw, Wkr, Wimp);
    colmean_part_kernel<<<B * 16, 256>>>(x);
    gate_kernel<<<1, 192>>>(Wgate, B);
    qkv_kernel<<<B * T_SEQ / 8, 256>>>(Wqn, Wqr, Wkn, Wv);
    topk_kernel<<<B, 1024>>>();
    kvproj_kernel<true><<<B * KEEP / 16, 256>>>(x, Wselk, Wselv);
    kvproj_kernel<false><<<B * T_SEQ / 16, 256>>>(x, Wwink, Wwinv);

    dim3 agrid(96, H_NUM, B);
    attn_all<<<agrid, 128, FA_SMEM>>>();

    proj_kernel<<<B * T_SEQ / 16, 256>>>(Wproj, out);
}